// round 1
// baseline (speedup 1.0000x reference)
#include <cuda_runtime.h>
#include <cuda_bf16.h>
#include <math.h>

#define BB 4
#define NN 12544
#define NBHD 48
#define DIM 256
#define OUTD 512
#define INNER 4
#define TABLE 4096
#define KEEP 3136
#define RESV 784
#define SAMP 2352
#define NPAD 16384
#define KDIM 1024   // INNER*DIM
#define LNEPS 1e-5f

// ---------------- device scratch (static, no allocation) ----------------
__device__ float               g_wt[TABLE * INNER];
__device__ unsigned long long  g_keys[BB * NPAD];
__device__ int                 g_idx[BB * KEEP];
__device__ float               g_X[(size_t)BB * KEEP * KDIM];   // ~51.4 MB

// ---------------- weight_net table: gelu(LN(pre_table @ w1 + b1)) ----------------
__global__ void wt_kernel(const float* __restrict__ pre, const float* __restrict__ w1,
                          const float* __restrict__ b1, const float* __restrict__ g,
                          const float* __restrict__ bb) {
    int r = blockIdx.x * blockDim.x + threadIdx.x;
    if (r >= TABLE) return;
    float p[5];
#pragma unroll
    for (int k = 0; k < 5; k++) p[k] = pre[r * 5 + k];
    float h[4];
#pragma unroll
    for (int m = 0; m < 4; m++) {
        float s = b1[m];
#pragma unroll
        for (int k = 0; k < 5; k++) s += p[k] * w1[k * 4 + m];
        h[m] = s;
    }
    float mean = 0.25f * (h[0] + h[1] + h[2] + h[3]);
    float v = 0.f;
#pragma unroll
    for (int m = 0; m < 4; m++) { float d = h[m] - mean; v += d * d; }
    v *= 0.25f;
    float rstd = rsqrtf(v + LNEPS);
#pragma unroll
    for (int m = 0; m < 4; m++) {
        float x = (h[m] - mean) * rstd * g[m] + bb[m];
        // exact gelu
        float y = 0.5f * x * (1.f + erff(x * 0.70710678118654752440f));
        g_wt[r * 4 + m] = y;
    }
}

// ---------------- build sort keys ----------------
__global__ void prob_kernel(const float* __restrict__ pos, const float* __restrict__ lp) {
    int gidx = blockIdx.x * blockDim.x + threadIdx.x;
    if (gidx >= BB * NPAD) return;
    int b = gidx / NPAD;
    int i = gidx - b * NPAD;
    unsigned long long key;
    if (i < NN) {
        int px = (int)pos[((size_t)b * NN + i) * 2 + 0];
        int py = (int)pos[((size_t)b * NN + i) * 2 + 1];
        float fp = (((px & 1) == 0) && ((py & 1) == 0)) ? 1.f : 0.f;
        fp += lp[(size_t)b * NN + i] * 4.f;
        if (((px & 3) == 0) && ((py & 3) == 0)) fp -= 100.f;
        unsigned u = __float_as_uint(fp);
        u = (u & 0x80000000u) ? ~u : (u ^ 0x80000000u);   // ascending-order encoding
        unsigned inv = ~u;                                 // descending primary
        key = (((unsigned long long)inv) << 32) | (unsigned)i;  // ascending index tiebreak
    } else {
        key = 0xFFFFFFFFFFFFFFFFull;                       // pad -> end
    }
    g_keys[gidx] = key;
}

// ---------------- bitonic sort per batch (ascending key64, in gmem) ----------------
__global__ void sort_kernel() {
    unsigned long long* a = g_keys + (size_t)blockIdx.x * NPAD;
    int tid = threadIdx.x;
    for (int k = 2; k <= NPAD; k <<= 1) {
        for (int j = k >> 1; j > 0; j >>= 1) {
            for (int i = tid; i < NPAD; i += blockDim.x) {
                int ixj = i ^ j;
                if (ixj > i) {
                    unsigned long long x = a[i], y = a[ixj];
                    bool up = ((i & k) == 0);
                    if (up ? (x > y) : (x < y)) { a[i] = y; a[ixj] = x; }
                }
            }
            __syncthreads();
        }
    }
}

// ---------------- gather kept indices: top-2352 sorted + closed-form reserve ----------------
__global__ void idx_kernel() {
    int b = blockIdx.x;
    for (int t = threadIdx.x; t < KEEP; t += blockDim.x) {
        int v;
        if (t < SAMP) {
            v = (int)(g_keys[(size_t)b * NPAD + t] & 0xFFFFFFFFull);
        } else {
            int r = t - SAMP;
            v = ((r / 28) * 4) * 112 + (r % 28) * 4;   // ascending reserve grid (pos%4==0)
        }
        g_idx[b * KEEP + t] = v;
    }
}

// ---------------- per-token: weighted neighbor sum + LN -> X; also pos_k ----------------
__global__ void token_kernel(const float* __restrict__ pos, const float* __restrict__ feat,
                             const int* __restrict__ member, const float* __restrict__ cmask,
                             const float* __restrict__ lp, const int* __restrict__ pe,
                             const float* __restrict__ ng, const float* __restrict__ nb,
                             float* __restrict__ out_pos) {
    int t = blockIdx.x;                 // 0 .. BB*KEEP-1
    int b = t / KEEP;
    int tid = threadIdx.x;              // 256 threads = channel id

    __shared__ int   s_mem[NBHD];
    __shared__ float s_w[NBHD * 4];
    __shared__ float red[8];
    __shared__ int   s_src;

    if (tid == 0) s_src = g_idx[t];
    __syncthreads();
    int src = s_src;

    if (tid < 2) out_pos[(size_t)t * 2 + tid] = pos[((size_t)b * NN + src) * 2 + tid];

    if (tid < NBHD) {
        size_t eoff = ((size_t)b * NN + src) * NBHD + tid;
        int mm = member[eoff];
        int pp = pe[eoff];
        float sc = lp[(size_t)b * NN + mm] * cmask[eoff];
        s_mem[tid] = mm;
#pragma unroll
        for (int m = 0; m < 4; m++) s_w[tid * 4 + m] = g_wt[pp * 4 + m] * sc;
    }
    __syncthreads();

    const float* fb = feat + (size_t)b * NN * DIM;
    float a0 = 0.f, a1 = 0.f, a2 = 0.f, a3 = 0.f;
    int c = tid;
#pragma unroll 4
    for (int j = 0; j < NBHD; j++) {
        float f = fb[(size_t)s_mem[j] * DIM + c];
        a0 += s_w[j * 4 + 0] * f;
        a1 += s_w[j * 4 + 1] * f;
        a2 += s_w[j * 4 + 2] * f;
        a3 += s_w[j * 4 + 3] * f;
    }

    // LayerNorm over 1024 (values: flat index m*256 + c)
    float s = a0 + a1 + a2 + a3;
#pragma unroll
    for (int o = 16; o > 0; o >>= 1) s += __shfl_down_sync(0xffffffffu, s, o);
    if ((tid & 31) == 0) red[tid >> 5] = s;
    __syncthreads();
    float tot = red[0] + red[1] + red[2] + red[3] + red[4] + red[5] + red[6] + red[7];
    float mean = tot * (1.f / 1024.f);
    __syncthreads();

    float d0 = a0 - mean, d1 = a1 - mean, d2 = a2 - mean, d3 = a3 - mean;
    float vs = d0 * d0 + d1 * d1 + d2 * d2 + d3 * d3;
#pragma unroll
    for (int o = 16; o > 0; o >>= 1) vs += __shfl_down_sync(0xffffffffu, vs, o);
    if ((tid & 31) == 0) red[tid >> 5] = vs;
    __syncthreads();
    float vtot = red[0] + red[1] + red[2] + red[3] + red[4] + red[5] + red[6] + red[7];
    float rstd = rsqrtf(vtot * (1.f / 1024.f) + LNEPS);

    float* X = g_X + (size_t)t * KDIM;
    X[0 * 256 + c] = d0 * rstd * ng[0 * 256 + c] + nb[0 * 256 + c];
    X[1 * 256 + c] = d1 * rstd * ng[1 * 256 + c] + nb[1 * 256 + c];
    X[2 * 256 + c] = d2 * rstd * ng[2 * 256 + c] + nb[2 * 256 + c];
    X[3 * 256 + c] = d3 * rstd * ng[3 * 256 + c] + nb[3 * 256 + c];
}

// ---------------- GEMM: (BB*KEEP x 1024) @ (1024 x 512) + bias ----------------
#define BM 128
#define BN 64
#define BK 16

__global__ __launch_bounds__(256) void gemm_kernel(const float* __restrict__ Wl,
                                                   const float* __restrict__ bias,
                                                   float* __restrict__ out) {
    __shared__ float As[BK * BM];   // [k][m]
    __shared__ float Bs[BK * BN];   // [k][n]
    int tid = threadIdx.x;
    int m0 = blockIdx.x * BM;
    int n0 = blockIdx.y * BN;
    int ty = tid >> 4;           // 0..15
    int tx = tid & 15;           // 0..15

    float acc[8][4];
#pragma unroll
    for (int i = 0; i < 8; i++)
#pragma unroll
        for (int j = 0; j < 4; j++) acc[i][j] = 0.f;

    int ar = tid >> 2;           // 0..63
    int ac = (tid & 3) * 4;      // 0,4,8,12

    for (int k0 = 0; k0 < KDIM; k0 += BK) {
#pragma unroll
        for (int it = 0; it < 2; it++) {
            float4 v = *(const float4*)(g_X + (size_t)(m0 + ar + 64 * it) * KDIM + k0 + ac);
            As[(ac + 0) * BM + ar + 64 * it] = v.x;
            As[(ac + 1) * BM + ar + 64 * it] = v.y;
            As[(ac + 2) * BM + ar + 64 * it] = v.z;
            As[(ac + 3) * BM + ar + 64 * it] = v.w;
        }
        {
            float4 v = *(const float4*)(Wl + (size_t)(k0 + ty) * OUTD + n0 + tx * 4);
            *(float4*)(Bs + ty * BN + tx * 4) = v;
        }
        __syncthreads();
#pragma unroll
        for (int k = 0; k < BK; k++) {
            float4 av0 = *(const float4*)(As + k * BM + ty * 8);
            float4 av1 = *(const float4*)(As + k * BM + ty * 8 + 4);
            float4 bv  = *(const float4*)(Bs + k * BN + tx * 4);
            float a[8] = {av0.x, av0.y, av0.z, av0.w, av1.x, av1.y, av1.z, av1.w};
            float bf[4] = {bv.x, bv.y, bv.z, bv.w};
#pragma unroll
            for (int i = 0; i < 8; i++)
#pragma unroll
                for (int j = 0; j < 4; j++) acc[i][j] += a[i] * bf[j];
        }
        __syncthreads();
    }

    float4 bl = *(const float4*)(bias + n0 + tx * 4);
#pragma unroll
    for (int i = 0; i < 8; i++) {
        float4 r;
        r.x = acc[i][0] + bl.x;
        r.y = acc[i][1] + bl.y;
        r.z = acc[i][2] + bl.z;
        r.w = acc[i][3] + bl.w;
        *(float4*)(out + (size_t)(m0 + ty * 8 + i) * OUTD + n0 + tx * 4) = r;
    }
}

// ---------------- launch ----------------
extern "C" void kernel_launch(void* const* d_in, const int* in_sizes, int n_in,
                              void* d_out, int out_size) {
    const float* pos    = (const float*)d_in[0];
    const float* feat   = (const float*)d_in[1];
    const int*   member = (const int*)d_in[2];
    const float* cmask  = (const float*)d_in[3];
    const float* lp     = (const float*)d_in[4];

    // pe_idx: skip optional scalar 'stride'
    int pi = 5;
    if (pi < n_in && in_sizes[pi] == 1) pi++;
    const int* pe = (const int*)d_in[pi];

    // locate pre_table by element count (4096*5), robust to optional 'reserve_num' scalar
    int pt = pi + 1;
    while (pt < n_in && in_sizes[pt] != TABLE * 5) pt++;
    const float* pre    = (const float*)d_in[pt];
    const float* w1     = (const float*)d_in[pt + 1];
    const float* b1     = (const float*)d_in[pt + 2];
    const float* ln1_g  = (const float*)d_in[pt + 3];
    const float* ln1_b  = (const float*)d_in[pt + 4];
    const float* norm_g = (const float*)d_in[pt + 5];
    const float* norm_b = (const float*)d_in[pt + 6];
    const float* lin_w  = (const float*)d_in[pt + 7];
    const float* lin_b  = (const float*)d_in[pt + 8];

    float* out_pos = (float*)d_out;                       // [4, 3136, 2]
    float* out_res = (float*)d_out + (size_t)BB * KEEP * 2; // [4, 3136, 512]

    wt_kernel<<<TABLE / 256, 256>>>(pre, w1, b1, ln1_g, ln1_b);
    prob_kernel<<<(BB * NPAD + 255) / 256, 256>>>(pos, lp);
    sort_kernel<<<BB, 1024>>>();
    idx_kernel<<<BB, 256>>>();
    token_kernel<<<BB * KEEP, 256>>>(pos, feat, member, cmask, lp, pe, norm_g, norm_b, out_pos);
    dim3 ggrid(BB * KEEP / BM, OUTD / BN);
    gemm_kernel<<<ggrid, 256>>>(lin_w, lin_b, out_res);
}

// round 4
// speedup vs baseline: 1.4139x; 1.4139x over previous
#include <cuda_runtime.h>
#include <cuda_bf16.h>
#include <math.h>
#include <cstdint>

#define BB 4
#define NN 12544
#define NBHD 48
#define DIM 256
#define OUTD 512
#define INNER 4
#define TABLE 4096
#define KEEP 3136
#define RESV 784
#define SAMP 2352
#define NPAD 16384
#define KDIM 1024
#define LNEPS 1e-5f
#define MTOT (BB * KEEP)   // 12544 rows

// ---------------- device scratch ----------------
__device__ float          g_wt[TABLE * INNER];
__device__ int            g_idx[BB * KEEP];
__device__ __nv_bfloat16  g_Xhi[(size_t)MTOT * KDIM];
__device__ __nv_bfloat16  g_Xlo[(size_t)MTOT * KDIM];
__device__ __nv_bfloat16  g_Whi[(size_t)OUTD * KDIM];   // [n][k] transposed
__device__ __nv_bfloat16  g_Wlo[(size_t)OUTD * KDIM];

__device__ __forceinline__ uint32_t smem_u32(const void* p) {
    uint32_t a;
    asm("{ .reg .u64 t; cvta.to.shared.u64 t, %1; cvt.u32.u64 %0, t; }" : "=r"(a) : "l"(p));
    return a;
}

// ---------------- weight_net table ----------------
__global__ void wt_kernel(const float* __restrict__ pre, const float* __restrict__ w1,
                          const float* __restrict__ b1, const float* __restrict__ g,
                          const float* __restrict__ bb) {
    int r = blockIdx.x * blockDim.x + threadIdx.x;
    if (r >= TABLE) return;
    float p[5];
#pragma unroll
    for (int k = 0; k < 5; k++) p[k] = pre[r * 5 + k];
    float h[4];
#pragma unroll
    for (int m = 0; m < 4; m++) {
        float s = b1[m];
#pragma unroll
        for (int k = 0; k < 5; k++) s += p[k] * w1[k * 4 + m];
        h[m] = s;
    }
    float mean = 0.25f * (h[0] + h[1] + h[2] + h[3]);
    float v = 0.f;
#pragma unroll
    for (int m = 0; m < 4; m++) { float d = h[m] - mean; v += d * d; }
    float rstd = rsqrtf(v * 0.25f + LNEPS);
#pragma unroll
    for (int m = 0; m < 4; m++) {
        float x = (h[m] - mean) * rstd * g[m] + bb[m];
        g_wt[r * 4 + m] = 0.5f * x * (1.f + erff(x * 0.70710678118654752440f));
    }
}

// ---------------- W transpose + hi/lo split ----------------
__global__ void wconv_kernel(const float* __restrict__ lw) {
    int i = blockIdx.x * blockDim.x + threadIdx.x;   // output order [n][k]
    if (i >= OUTD * KDIM) return;
    int n = i >> 10;
    int k = i & 1023;
    float v = lw[(size_t)k * OUTD + n];
    __nv_bfloat16 h = __float2bfloat16(v);
    g_Whi[i] = h;
    g_Wlo[i] = __float2bfloat16(v - __bfloat162float(h));
}

// ---------------- fused: key-gen + smem bitonic sort + index extraction ----------------
extern __shared__ unsigned long long s_keys[];   // NPAD * 8B = 128KB dynamic
__global__ void sort_kernel(const float* __restrict__ pos, const float* __restrict__ lp) {
    int b = blockIdx.x;
    int tid = threadIdx.x;
    for (int i = tid; i < NPAD; i += blockDim.x) {
        unsigned long long key;
        if (i < NN) {
            int px = (int)pos[((size_t)b * NN + i) * 2 + 0];
            int py = (int)pos[((size_t)b * NN + i) * 2 + 1];
            float fp = (((px & 1) == 0) && ((py & 1) == 0)) ? 1.f : 0.f;
            fp += lp[(size_t)b * NN + i] * 4.f;
            if (((px & 3) == 0) && ((py & 3) == 0)) fp -= 100.f;
            unsigned u = __float_as_uint(fp);
            u = (u & 0x80000000u) ? ~u : (u ^ 0x80000000u);
            unsigned inv = ~u;
            key = (((unsigned long long)inv) << 32) | (unsigned)i;
        } else {
            key = 0xFFFFFFFFFFFFFFFFull;
        }
        s_keys[i] = key;
    }
    __syncthreads();
    for (int k = 2; k <= NPAD; k <<= 1) {
        for (int j = k >> 1; j > 0; j >>= 1) {
            for (int i = tid; i < NPAD; i += blockDim.x) {
                int ixj = i ^ j;
                if (ixj > i) {
                    unsigned long long x = s_keys[i], y = s_keys[ixj];
                    bool up = ((i & k) == 0);
                    if (up ? (x > y) : (x < y)) { s_keys[i] = y; s_keys[ixj] = x; }
                }
            }
            __syncthreads();
        }
    }
    for (int t = tid; t < KEEP; t += blockDim.x) {
        int v;
        if (t < SAMP) {
            v = (int)(s_keys[t] & 0xFFFFFFFFull);
        } else {
            int r = t - SAMP;
            v = ((r / 28) * 4) * 112 + (r % 28) * 4;
        }
        g_idx[b * KEEP + t] = v;
    }
}

// ---------------- per-token: weighted neighbor sum + LN -> X_hi/X_lo bf16 ----------------
__global__ void token_kernel(const float* __restrict__ pos, const float* __restrict__ feat,
                             const int* __restrict__ member, const float* __restrict__ cmask,
                             const float* __restrict__ lp, const int* __restrict__ pe,
                             const float* __restrict__ ng, const float* __restrict__ nb,
                             float* __restrict__ out_pos) {
    int t = blockIdx.x;
    int b = t / KEEP;
    int tid = threadIdx.x;

    __shared__ int   s_mem[NBHD];
    __shared__ float s_w[NBHD * 4];
    __shared__ float red[8];
    __shared__ int   s_src;

    if (tid == 0) s_src = g_idx[t];
    __syncthreads();
    int src = s_src;

    if (tid < 2) out_pos[(size_t)t * 2 + tid] = pos[((size_t)b * NN + src) * 2 + tid];

    if (tid < NBHD) {
        size_t eoff = ((size_t)b * NN + src) * NBHD + tid;
        int mm = member[eoff];
        int pp = pe[eoff];
        float sc = lp[(size_t)b * NN + mm] * cmask[eoff];
        s_mem[tid] = mm;
#pragma unroll
        for (int m = 0; m < 4; m++) s_w[tid * 4 + m] = g_wt[pp * 4 + m] * sc;
    }
    __syncthreads();

    const float* fb = feat + (size_t)b * NN * DIM;
    float a0 = 0.f, a1 = 0.f, a2 = 0.f, a3 = 0.f;
    int c = tid;
#pragma unroll 4
    for (int j = 0; j < NBHD; j++) {
        float f = fb[(size_t)s_mem[j] * DIM + c];
        a0 += s_w[j * 4 + 0] * f;
        a1 += s_w[j * 4 + 1] * f;
        a2 += s_w[j * 4 + 2] * f;
        a3 += s_w[j * 4 + 3] * f;
    }

    float s = a0 + a1 + a2 + a3;
#pragma unroll
    for (int o = 16; o > 0; o >>= 1) s += __shfl_down_sync(0xffffffffu, s, o);
    if ((tid & 31) == 0) red[tid >> 5] = s;
    __syncthreads();
    float tot = red[0] + red[1] + red[2] + red[3] + red[4] + red[5] + red[6] + red[7];
    float mean = tot * (1.f / 1024.f);
    __syncthreads();

    float d0 = a0 - mean, d1 = a1 - mean, d2 = a2 - mean, d3 = a3 - mean;
    float vs = d0 * d0 + d1 * d1 + d2 * d2 + d3 * d3;
#pragma unroll
    for (int o = 16; o > 0; o >>= 1) vs += __shfl_down_sync(0xffffffffu, vs, o);
    if ((tid & 31) == 0) red[tid >> 5] = vs;
    __syncthreads();
    float vtot = red[0] + red[1] + red[2] + red[3] + red[4] + red[5] + red[6] + red[7];
    float rstd = rsqrtf(vtot * (1.f / 1024.f) + LNEPS);

    __nv_bfloat16* Xh = g_Xhi + (size_t)t * KDIM;
    __nv_bfloat16* Xl = g_Xlo + (size_t)t * KDIM;
    float dd[4] = {d0, d1, d2, d3};
#pragma unroll
    for (int m = 0; m < 4; m++) {
        int idx = m * 256 + c;
        float val = dd[m] * rstd * ng[idx] + nb[idx];
        __nv_bfloat16 h = __float2bfloat16(val);
        Xh[idx] = h;
        Xl[idx] = __float2bfloat16(val - __bfloat162float(h));
    }
}

// ---------------- mma.sync GEMM: [12544 x 1024] @ W^T[512 x 1024] + bias ----------------
// CTA 128x128, 8 warps (2x4), warp tile 64x32, BK=32, bf16 hi/lo 3-term.
#define BM 128
#define BN 128
#define BKK 32
#define ASTR 40   // padded smem row stride in bf16 (80B) -> conflict-free ldmatrix

#define LDMX4(r0, r1, r2, r3, a) \
    asm volatile("ldmatrix.sync.aligned.m8n8.x4.shared.b16 {%0,%1,%2,%3}, [%4];" \
                 : "=r"(r0), "=r"(r1), "=r"(r2), "=r"(r3) : "r"(a))
#define LDMX2(r0, r1, a) \
    asm volatile("ldmatrix.sync.aligned.m8n8.x2.shared.b16 {%0,%1}, [%2];" \
                 : "=r"(r0), "=r"(r1) : "r"(a))
#define MMA16816(c, a, b) \
    asm volatile("mma.sync.aligned.m16n8k16.row.col.f32.bf16.bf16.f32 " \
                 "{%0,%1,%2,%3}, {%4,%5,%6,%7}, {%8,%9}, {%0,%1,%2,%3};" \
                 : "+f"((c)[0]), "+f"((c)[1]), "+f"((c)[2]), "+f"((c)[3]) \
                 : "r"((a)[0]), "r"((a)[1]), "r"((a)[2]), "r"((a)[3]), "r"((b)[0]), "r"((b)[1]))

__global__ __launch_bounds__(256) void gemm_mma_kernel(const float* __restrict__ bias,
                                                       float* __restrict__ out) {
    __shared__ __nv_bfloat16 sAh[BM * ASTR];
    __shared__ __nv_bfloat16 sAl[BM * ASTR];
    __shared__ __nv_bfloat16 sBh[BN * ASTR];
    __shared__ __nv_bfloat16 sBl[BN * ASTR];

    int tid = threadIdx.x;
    int wid = tid >> 5, lane = tid & 31;
    int wm = wid >> 2, wn = wid & 3;
    int m0 = blockIdx.x * BM;
    int n0 = blockIdx.y * BN;

    uint32_t uAh = smem_u32(sAh), uAl = smem_u32(sAl);
    uint32_t uBh = smem_u32(sBh), uBl = smem_u32(sBl);

    float acc[4][4][4];
#pragma unroll
    for (int i = 0; i < 4; i++)
#pragma unroll
        for (int j = 0; j < 4; j++)
#pragma unroll
            for (int q = 0; q < 4; q++) acc[i][j][q] = 0.f;

    // per-thread copy coords: 2 chunks of 8 bf16 per array
    int row_c = tid >> 1;                 // 0..127
    int c8a = (tid & 1) * 16;             // 0 or 16

    for (int kt = 0; kt < KDIM / BKK; kt++) {
        int k0 = kt * BKK;
#pragma unroll
        for (int h = 0; h < 2; h++) {
            int cc = c8a + h * 8;
            *(float4*)(sAh + row_c * ASTR + cc) = *(const float4*)(g_Xhi + (size_t)(m0 + row_c) * KDIM + k0 + cc);
            *(float4*)(sAl + row_c * ASTR + cc) = *(const float4*)(g_Xlo + (size_t)(m0 + row_c) * KDIM + k0 + cc);
            *(float4*)(sBh + row_c * ASTR + cc) = *(const float4*)(g_Whi + (size_t)(n0 + row_c) * KDIM + k0 + cc);
            *(float4*)(sBl + row_c * ASTR + cc) = *(const float4*)(g_Wlo + (size_t)(n0 + row_c) * KDIM + k0 + cc);
        }
        __syncthreads();

#pragma unroll
        for (int s = 0; s < 2; s++) {
            int kk = s * 16;
            uint32_t ah[4][4], al[4][4], bh[4][2], bl[4][2];
            int arow = wm * 64 + (lane & 15);
            int acol = kk + (lane >> 4) * 8;
#pragma unroll
            for (int i = 0; i < 4; i++) {
                uint32_t off = (uint32_t)((arow + i * 16) * ASTR + acol) * 2;
                LDMX4(ah[i][0], ah[i][1], ah[i][2], ah[i][3], uAh + off);
                LDMX4(al[i][0], al[i][1], al[i][2], al[i][3], uAl + off);
            }
            int brow = wn * 32 + (lane & 7);
            int bcol = kk + ((lane >> 3) & 1) * 8;
#pragma unroll
            for (int j = 0; j < 4; j++) {
                uint32_t off = (uint32_t)((brow + j * 8) * ASTR + bcol) * 2;
                LDMX2(bh[j][0], bh[j][1], uBh + off);
                LDMX2(bl[j][0], bl[j][1], uBl + off);
            }
#pragma unroll
            for (int i = 0; i < 4; i++)
#pragma unroll
                for (int j = 0; j < 4; j++) {
                    MMA16816(acc[i][j], ah[i], bh[j]);
                    MMA16816(acc[i][j], ah[i], bl[j]);
                    MMA16816(acc[i][j], al[i], bh[j]);
                }
        }
        __syncthreads();
    }

    // epilogue
    int er = lane >> 2;
    int ec = (lane & 3) * 2;
#pragma unroll
    for (int i = 0; i < 4; i++) {
#pragma unroll
        for (int j = 0; j < 4; j++) {
            int m = m0 + wm * 64 + i * 16 + er;
            int n = n0 + wn * 32 + j * 8 + ec;
            float b0 = bias[n], b1 = bias[n + 1];
            float2 r0 = make_float2(acc[i][j][0] + b0, acc[i][j][1] + b1);
            float2 r1 = make_float2(acc[i][j][2] + b0, acc[i][j][3] + b1);
            *(float2*)(out + (size_t)m * OUTD + n) = r0;
            *(float2*)(out + (size_t)(m + 8) * OUTD + n) = r1;
        }
    }
}

// ---------------- launch ----------------
extern "C" void kernel_launch(void* const* d_in, const int* in_sizes, int n_in,
                              void* d_out, int out_size) {
    const float* pos    = (const float*)d_in[0];
    const float* feat   = (const float*)d_in[1];
    const int*   member = (const int*)d_in[2];
    const float* cmask  = (const float*)d_in[3];
    const float* lp     = (const float*)d_in[4];

    int pi = 5;
    if (pi < n_in && in_sizes[pi] == 1) pi++;
    const int* pe = (const int*)d_in[pi];

    int pt = pi + 1;
    while (pt < n_in && in_sizes[pt] != TABLE * 5) pt++;
    const float* pre    = (const float*)d_in[pt];
    const float* w1     = (const float*)d_in[pt + 1];
    const float* b1     = (const float*)d_in[pt + 2];
    const float* ln1_g  = (const float*)d_in[pt + 3];
    const float* ln1_b  = (const float*)d_in[pt + 4];
    const float* norm_g = (const float*)d_in[pt + 5];
    const float* norm_b = (const float*)d_in[pt + 6];
    const float* lin_w  = (const float*)d_in[pt + 7];
    const float* lin_b  = (const float*)d_in[pt + 8];

    float* out_pos = (float*)d_out;
    float* out_res = (float*)d_out + (size_t)BB * KEEP * 2;

    cudaFuncSetAttribute(sort_kernel, cudaFuncAttributeMaxDynamicSharedMemorySize, NPAD * 8);

    wt_kernel<<<TABLE / 256, 256>>>(pre, w1, b1, ln1_g, ln1_b);
    wconv_kernel<<<(OUTD * KDIM + 255) / 256, 256>>>(lin_w);
    sort_kernel<<<BB, 1024, NPAD * 8>>>(pos, lp);
    token_kernel<<<BB * KEEP, 256>>>(pos, feat, member, cmask, lp, pe, norm_g, norm_b, out_pos);
    dim3 ggrid(MTOT / BM, OUTD / BN);
    gemm_mma_kernel<<<ggrid, 256>>>(lin_b, out_res);
}

// round 6
// speedup vs baseline: 2.7826x; 1.9680x over previous
#include <cuda_runtime.h>
#include <cuda_bf16.h>
#include <cuda_fp16.h>
#include <math.h>
#include <cstdint>

#define BB 4
#define NN 12544
#define NBHD 48
#define DIM 256
#define OUTD 512
#define INNER 4
#define TABLE 4096
#define KEEP 3136
#define SAMP 2352
#define KDIM 1024
#define LNEPS 1e-5f
#define MTOT (BB * KEEP)   // 12544

// ---------------- device scratch ----------------
__device__ float          g_wt[TABLE * INNER];
__device__ int            g_idx[BB * KEEP];
__device__ __half         g_feat16[(size_t)BB * NN * DIM];      // 25.7MB
__device__ __nv_bfloat16  g_Xhi[(size_t)MTOT * KDIM];
__device__ __nv_bfloat16  g_Xlo[(size_t)MTOT * KDIM];
__device__ __nv_bfloat16  g_Whi[(size_t)OUTD * KDIM];           // [n][k]
__device__ __nv_bfloat16  g_Wlo[(size_t)OUTD * KDIM];

__device__ __forceinline__ uint32_t smem_u32(const void* p) {
    uint32_t a;
    asm("{ .reg .u64 t; cvta.to.shared.u64 t, %1; cvt.u32.u64 %0, t; }" : "=r"(a) : "l"(p));
    return a;
}

// ================= PREP kernel: selection + wt + wconv + feat16 =================
#define FEAT_BLKS 1568
#define WCONV_BLKS 512
#define WT_BLKS 4
#define PREP_GRID (4 + FEAT_BLKS + WCONV_BLKS + WT_BLKS)

__device__ __forceinline__ unsigned key_inv(const float* pos, const float* lp, int b, int i) {
    int px = (int)pos[((size_t)b * NN + i) * 2 + 0];
    int py = (int)pos[((size_t)b * NN + i) * 2 + 1];
    float fp = (((px & 1) == 0) && ((py & 1) == 0)) ? 1.f : 0.f;
    fp += lp[(size_t)b * NN + i] * 4.f;
    if (((px & 3) == 0) && ((py & 3) == 0)) fp -= 100.f;
    unsigned u = __float_as_uint(fp);
    u = (u & 0x80000000u) ? ~u : (u ^ 0x80000000u);   // ascending float encode
    return ~u;                                         // ascending = descending prob
}

extern __shared__ __align__(16) unsigned char dynsm[];

__global__ __launch_bounds__(1024) void prep_kernel(
    const float* __restrict__ pos, const float* __restrict__ lp,
    const float* __restrict__ pre, const float* __restrict__ w1,
    const float* __restrict__ b1, const float* __restrict__ ln1g,
    const float* __restrict__ ln1b, const float* __restrict__ lw,
    const float* __restrict__ feat) {
    int blk = blockIdx.x;
    int tid = threadIdx.x;

    if (blk < 4) {
        // ---------- selection for batch b ----------
        int b = blk;
        unsigned* bins = (unsigned*)dynsm;                       // 8192 x u32 = 32KB
        unsigned long long* skeys = (unsigned long long*)dynsm;  // reuse: 4096 x u64
        __shared__ int s_wsum[32];
        __shared__ int s_T, s_cnt;

        for (int i = tid; i < 8192; i += 1024) bins[i] = 0;
        if (tid == 0) { s_cnt = 0; s_T = 8191; }
        __syncthreads();
        for (int i = tid; i < NN; i += 1024) {
            unsigned inv = key_inv(pos, lp, b, i);
            atomicAdd(&bins[inv >> 19], 1u);
        }
        __syncthreads();
        // block exclusive scan of per-thread partials (8 bins each)
        int part = 0;
#pragma unroll
        for (int q = 0; q < 8; q++) part += (int)bins[tid * 8 + q];
        int lane = tid & 31, wrp = tid >> 5;
        int v = part;
#pragma unroll
        for (int o = 1; o < 32; o <<= 1) { int nv = __shfl_up_sync(~0u, v, o); if (lane >= o) v += nv; }
        if (lane == 31) s_wsum[wrp] = v;
        __syncthreads();
        if (wrp == 0) {
            int w = s_wsum[lane];
#pragma unroll
            for (int o = 1; o < 32; o <<= 1) { int nv = __shfl_up_sync(~0u, w, o); if (lane >= o) w += nv; }
            s_wsum[lane] = w;
        }
        __syncthreads();
        int excl = v - part + (wrp > 0 ? s_wsum[wrp - 1] : 0);
        int cum = excl;
#pragma unroll
        for (int q = 0; q < 8; q++) {
            int cnt = (int)bins[tid * 8 + q];
            if (cum < SAMP && cum + cnt >= SAMP) s_T = tid * 8 + q;
            cum += cnt;
        }
        __syncthreads();
        int T = s_T;
        __syncthreads();   // done reading bins before reuse
        for (int i = tid; i < 4096; i += 1024) skeys[i] = 0xFFFFFFFFFFFFFFFFull;
        __syncthreads();
        for (int i = tid; i < NN; i += 1024) {
            unsigned inv = key_inv(pos, lp, b, i);
            if ((int)(inv >> 19) <= T) {
                int p = atomicAdd(&s_cnt, 1);
                if (p < 4096) skeys[p] = (((unsigned long long)inv) << 32) | (unsigned)i;
            }
        }
        __syncthreads();
        // bitonic sort 4096 ascending
        for (int k = 2; k <= 4096; k <<= 1) {
            for (int j = k >> 1; j > 0; j >>= 1) {
                for (int i = tid; i < 4096; i += 1024) {
                    int ixj = i ^ j;
                    if (ixj > i) {
                        unsigned long long x = skeys[i], y = skeys[ixj];
                        bool up = ((i & k) == 0);
                        if (up ? (x > y) : (x < y)) { skeys[i] = y; skeys[ixj] = x; }
                    }
                }
                __syncthreads();
            }
        }
        for (int t = tid; t < KEEP; t += 1024) {
            int val;
            if (t < SAMP) val = (int)(skeys[t] & 0xFFFFFFFFull);
            else { int r = t - SAMP; val = ((r / 28) * 4) * 112 + (r % 28) * 4; }
            g_idx[b * KEEP + t] = val;
        }
        return;
    }
    blk -= 4;

    if (blk < FEAT_BLKS) {
        // ---------- feat fp32 -> fp16 ----------
        size_t g = (size_t)blk * 2048 + tid;   // float4 index; 2 per thread
#pragma unroll
        for (int it = 0; it < 2; it++) {
            size_t gg = g + (size_t)it * 1024;
            float4 f = ((const float4*)feat)[gg];
            __half2 h0 = __floats2half2_rn(f.x, f.y);
            __half2 h1 = __floats2half2_rn(f.z, f.w);
            uint2 o;
            o.x = *(uint32_t*)&h0;
            o.y = *(uint32_t*)&h1;
            ((uint2*)g_feat16)[gg] = o;
        }
        return;
    }
    blk -= FEAT_BLKS;

    if (blk < WCONV_BLKS) {
        // ---------- W transpose+split via smem tile (32x32) ----------
        __shared__ float tile[32][33];
        int tk = blk >> 4, tn = blk & 15;       // 32 x 16 tiles
        int k0 = tk * 32, n0 = tn * 32;
        int tx = tid & 31, ty = tid >> 5;
        tile[ty][tx] = lw[(size_t)(k0 + ty) * OUTD + n0 + tx];
        __syncthreads();
        int n = n0 + ty, k = k0 + tx;
        float val = tile[tx][ty];
        __nv_bfloat16 h = __float2bfloat16(val);
        g_Whi[(size_t)n * KDIM + k] = h;
        g_Wlo[(size_t)n * KDIM + k] = __float2bfloat16(val - __bfloat162float(h));
        return;
    }
    blk -= WCONV_BLKS;

    // ---------- weight_net table ----------
    int r = blk * 1024 + tid;
    if (r < TABLE) {
        float p[5];
#pragma unroll
        for (int k = 0; k < 5; k++) p[k] = pre[r * 5 + k];
        float h[4];
#pragma unroll
        for (int m = 0; m < 4; m++) {
            float s = b1[m];
#pragma unroll
            for (int k = 0; k < 5; k++) s += p[k] * w1[k * 4 + m];
            h[m] = s;
        }
        float mean = 0.25f * (h[0] + h[1] + h[2] + h[3]);
        float vv = 0.f;
#pragma unroll
        for (int m = 0; m < 4; m++) { float d = h[m] - mean; vv += d * d; }
        float rstd = rsqrtf(vv * 0.25f + LNEPS);
#pragma unroll
        for (int m = 0; m < 4; m++) {
            float x = (h[m] - mean) * rstd * ln1g[m] + ln1b[m];
            g_wt[r * 4 + m] = 0.5f * x * (1.f + erff(x * 0.70710678118654752440f));
        }
    }
}

// ================= token kernel: gather (fp16) + weighted sum + LN =================
__global__ __launch_bounds__(128) void token_kernel(
    const float* __restrict__ pos, const int* __restrict__ member,
    const float* __restrict__ cmask, const float* __restrict__ lp,
    const int* __restrict__ pe, const float* __restrict__ ng,
    const float* __restrict__ nb, float* __restrict__ out_pos) {
    int t = blockIdx.x;
    int b = t / KEEP;
    int tid = threadIdx.x;   // owns channels 2*tid, 2*tid+1

    __shared__ int    s_mem[NBHD];
    __shared__ float4 s_w4[NBHD];
    __shared__ float  red[4];
    __shared__ int    s_src;

    if (tid == 0) s_src = g_idx[t];
    __syncthreads();
    int src = s_src;

    if (tid < 2) out_pos[(size_t)t * 2 + tid] = pos[((size_t)b * NN + src) * 2 + tid];

    if (tid < NBHD) {
        size_t eoff = ((size_t)b * NN + src) * NBHD + tid;
        int mm = member[eoff];
        int pp = pe[eoff];
        float sc = lp[(size_t)b * NN + mm] * cmask[eoff];
        s_mem[tid] = mm;
        float4 w;
        w.x = g_wt[pp * 4 + 0] * sc;
        w.y = g_wt[pp * 4 + 1] * sc;
        w.z = g_wt[pp * 4 + 2] * sc;
        w.w = g_wt[pp * 4 + 3] * sc;
        s_w4[tid] = w;
    }
    __syncthreads();

    const __half2* fb = (const __half2*)(g_feat16 + (size_t)b * NN * DIM);
    float2 a0 = {0, 0}, a1 = {0, 0}, a2 = {0, 0}, a3 = {0, 0};
#pragma unroll 4
    for (int j = 0; j < NBHD; j++) {
        int mm = s_mem[j];
        float4 w = s_w4[j];
        float2 f = __half22float2(fb[(size_t)mm * 128 + tid]);
        a0.x += w.x * f.x; a0.y += w.x * f.y;
        a1.x += w.y * f.x; a1.y += w.y * f.y;
        a2.x += w.z * f.x; a2.y += w.z * f.y;
        a3.x += w.w * f.x; a3.y += w.w * f.y;
    }

    float s = a0.x + a0.y + a1.x + a1.y + a2.x + a2.y + a3.x + a3.y;
#pragma unroll
    for (int o = 16; o > 0; o >>= 1) s += __shfl_down_sync(0xffffffffu, s, o);
    if ((tid & 31) == 0) red[tid >> 5] = s;
    __syncthreads();
    float mean = (red[0] + red[1] + red[2] + red[3]) * (1.f / 1024.f);
    __syncthreads();

    float2 d0 = {a0.x - mean, a0.y - mean}, d1 = {a1.x - mean, a1.y - mean};
    float2 d2 = {a2.x - mean, a2.y - mean}, d3 = {a3.x - mean, a3.y - mean};
    float vs = d0.x * d0.x + d0.y * d0.y + d1.x * d1.x + d1.y * d1.y +
               d2.x * d2.x + d2.y * d2.y + d3.x * d3.x + d3.y * d3.y;
#pragma unroll
    for (int o = 16; o > 0; o >>= 1) vs += __shfl_down_sync(0xffffffffu, vs, o);
    if ((tid & 31) == 0) red[tid >> 5] = vs;
    __syncthreads();
    float rstd = rsqrtf((red[0] + red[1] + red[2] + red[3]) * (1.f / 1024.f) + LNEPS);

    __nv_bfloat16* Xh = g_Xhi + (size_t)t * KDIM;
    __nv_bfloat16* Xl = g_Xlo + (size_t)t * KDIM;
    float2 dd[4] = {d0, d1, d2, d3};
#pragma unroll
    for (int m = 0; m < 4; m++) {
        int idx = m * 256 + tid * 2;
        float2 gg = *(const float2*)(ng + idx);
        float2 bbv = *(const float2*)(nb + idx);
        float v0 = dd[m].x * rstd * gg.x + bbv.x;
        float v1 = dd[m].y * rstd * gg.y + bbv.y;
        __nv_bfloat16 h0 = __float2bfloat16(v0);
        __nv_bfloat16 h1 = __float2bfloat16(v1);
        __nv_bfloat162 hh; hh.x = h0; hh.y = h1;
        *(uint32_t*)(Xh + idx) = *(uint32_t*)&hh;
        __nv_bfloat162 ll;
        ll.x = __float2bfloat16(v0 - __bfloat162float(h0));
        ll.y = __float2bfloat16(v1 - __bfloat162float(h1));
        *(uint32_t*)(Xl + idx) = *(uint32_t*)&ll;
    }
}

// ================= GEMM: cp.async double-buffered mma.sync =================
#define BM 128
#define BN 128
#define BKK 32
#define NT (KDIM / BKK)   // 32
#define ASTR 40           // bf16 elems; 80B row stride
#define ARR_BYTES 10240   // 128 * 80
#define STAGE_BYTES (4 * ARR_BYTES)
#define GSMEM (2 * STAGE_BYTES)   // 81920

#define CP16(d, s) asm volatile("cp.async.cg.shared.global [%0], [%1], 16;" :: "r"(d), "l"(__cvta_generic_to_global(s)))
#define CP_COMMIT() asm volatile("cp.async.commit_group;" ::: "memory")
#define CP_WAIT1() asm volatile("cp.async.wait_group 1;" ::: "memory")
#define CP_WAIT0() asm volatile("cp.async.wait_group 0;" ::: "memory")

#define LDMX4(r0, r1, r2, r3, a) \
    asm volatile("ldmatrix.sync.aligned.m8n8.x4.shared.b16 {%0,%1,%2,%3}, [%4];" \
                 : "=r"(r0), "=r"(r1), "=r"(r2), "=r"(r3) : "r"(a))
#define LDMX2(r0, r1, a) \
    asm volatile("ldmatrix.sync.aligned.m8n8.x2.shared.b16 {%0,%1}, [%2];" \
                 : "=r"(r0), "=r"(r1) : "r"(a))
#define MMA16816(c, a, b) \
    asm volatile("mma.sync.aligned.m16n8k16.row.col.f32.bf16.bf16.f32 " \
                 "{%0,%1,%2,%3}, {%4,%5,%6,%7}, {%8,%9}, {%0,%1,%2,%3};" \
                 : "+f"((c)[0]), "+f"((c)[1]), "+f"((c)[2]), "+f"((c)[3]) \
                 : "r"((a)[0]), "r"((a)[1]), "r"((a)[2]), "r"((a)[3]), "r"((b)[0]), "r"((b)[1]))

// 128 rows x 4 chunks (16B) per array; 512 chunk-loads per array; 2 iters x 256 thr
__device__ __forceinline__ void gemm_load(uint32_t sbase, int m0, int n0, int kt, int tid) {
    int k0 = kt * BKK;
#pragma unroll
    for (int it = 0; it < 2; it++) {
        int id = tid + it * 256;          // 0..511
        int r = id >> 2, c = id & 3;      // r 0..127, c 0..3 (c*8 elems = 32 per row)
        uint32_t doff = (uint32_t)(r * 80 + c * 16);
        CP16(sbase + 0 * ARR_BYTES + doff, g_Xhi + (size_t)(m0 + r) * KDIM + k0 + c * 8);
        CP16(sbase + 1 * ARR_BYTES + doff, g_Xlo + (size_t)(m0 + r) * KDIM + k0 + c * 8);
        CP16(sbase + 2 * ARR_BYTES + doff, g_Whi + (size_t)(n0 + r) * KDIM + k0 + c * 8);
        CP16(sbase + 3 * ARR_BYTES + doff, g_Wlo + (size_t)(n0 + r) * KDIM + k0 + c * 8);
    }
}

__global__ __launch_bounds__(256) void gemm_mma_kernel(const float* __restrict__ bias,
                                                       float* __restrict__ out) {
    uint32_t sb = smem_u32(dynsm);
    int tid = threadIdx.x;
    int wid = tid >> 5, lane = tid & 31;
    int wm = wid >> 2, wn = wid & 3;
    int m0 = blockIdx.x * BM;
    int n0 = blockIdx.y * BN;

    float acc[4][4][4];
#pragma unroll
    for (int i = 0; i < 4; i++)
#pragma unroll
        for (int j = 0; j < 4; j++)
#pragma unroll
            for (int q = 0; q < 4; q++) acc[i][j][q] = 0.f;

    gemm_load(sb, m0, n0, 0, tid);
    CP_COMMIT();

    for (int kt = 0; kt < NT; kt++) {
        if (kt + 1 < NT) {
            gemm_load(sb + ((kt + 1) & 1) * STAGE_BYTES, m0, n0, kt + 1, tid);
            CP_COMMIT();
            CP_WAIT1();
        } else {
            CP_WAIT0();
        }
        __syncthreads();

        uint32_t base = sb + (kt & 1) * STAGE_BYTES;
        uint32_t uAh = base, uAl = base + ARR_BYTES;
        uint32_t uBh = base + 2 * ARR_BYTES, uBl = base + 3 * ARR_BYTES;

#pragma unroll
        for (int s = 0; s < 2; s++) {
            int kk = s * 16;
            uint32_t ah[4][4], al[4][4], bh[4][2], bl[4][2];
            int arow = wm * 64 + (lane & 15);
            int acol = kk + (lane >> 4) * 8;
#pragma unroll
            for (int i = 0; i < 4; i++) {
                uint32_t off = (uint32_t)((arow + i * 16) * ASTR + acol) * 2;
                LDMX4(ah[i][0], ah[i][1], ah[i][2], ah[i][3], uAh + off);
                LDMX4(al[i][0], al[i][1], al[i][2], al[i][3], uAl + off);
            }
            int brow = wn * 32 + (lane & 7);
            int bcol = kk + ((lane >> 3) & 1) * 8;
#pragma unroll
            for (int j = 0; j < 4; j++) {
                uint32_t off = (uint32_t)((brow + j * 8) * ASTR + bcol) * 2;
                LDMX2(bh[j][0], bh[j][1], uBh + off);
                LDMX2(bl[j][0], bl[j][1], uBl + off);
            }
#pragma unroll
            for (int i = 0; i < 4; i++)
#pragma unroll
                for (int j = 0; j < 4; j++) {
                    MMA16816(acc[i][j], ah[i], bh[j]);
                    MMA16816(acc[i][j], ah[i], bl[j]);
                    MMA16816(acc[i][j], al[i], bh[j]);
                }
        }
        __syncthreads();
    }

    int er = lane >> 2;
    int ec = (lane & 3) * 2;
#pragma unroll
    for (int i = 0; i < 4; i++) {
#pragma unroll
        for (int j = 0; j < 4; j++) {
            int m = m0 + wm * 64 + i * 16 + er;
            int n = n0 + wn * 32 + j * 8 + ec;
            float b0 = bias[n], b1 = bias[n + 1];
            float2 r0 = make_float2(acc[i][j][0] + b0, acc[i][j][1] + b1);
            float2 r1 = make_float2(acc[i][j][2] + b0, acc[i][j][3] + b1);
            *(float2*)(out + (size_t)m * OUTD + n) = r0;
            *(float2*)(out + (size_t)(m + 8) * OUTD + n) = r1;
        }
    }
}

// ---------------- launch ----------------
extern "C" void kernel_launch(void* const* d_in, const int* in_sizes, int n_in,
                              void* d_out, int out_size) {
    const float* pos    = (const float*)d_in[0];
    const float* feat   = (const float*)d_in[1];
    const int*   member = (const int*)d_in[2];
    const float* cmask  = (const float*)d_in[3];
    const float* lp     = (const float*)d_in[4];

    int pi = 5;
    if (pi < n_in && in_sizes[pi] == 1) pi++;
    const int* pe = (const int*)d_in[pi];

    int pt = pi + 1;
    while (pt < n_in && in_sizes[pt] != TABLE * 5) pt++;
    const float* pre    = (const float*)d_in[pt];
    const float* w1     = (const float*)d_in[pt + 1];
    const float* b1     = (const float*)d_in[pt + 2];
    const float* ln1_g  = (const float*)d_in[pt + 3];
    const float* ln1_b  = (const float*)d_in[pt + 4];
    const float* norm_g = (const float*)d_in[pt + 5];
    const float* norm_b = (const float*)d_in[pt + 6];
    const float* lin_w  = (const float*)d_in[pt + 7];
    const float* lin_b  = (const float*)d_in[pt + 8];

    float* out_pos = (float*)d_out;
    float* out_res = (float*)d_out + (size_t)BB * KEEP * 2;

    cudaFuncSetAttribute(gemm_mma_kernel, cudaFuncAttributeMaxDynamicSharedMemorySize, GSMEM);

    prep_kernel<<<PREP_GRID, 1024, 32768>>>(pos, lp, pre, w1, b1, ln1_g, ln1_b, lin_w, feat);
    token_kernel<<<MTOT, 128>>>(pos, member, cmask, lp, pe, norm_g, norm_b, out_pos);
    dim3 ggrid(MTOT / BM, OUTD / BN);
    gemm_mma_kernel<<<ggrid, 256, GSMEM>>>(lin_b, out_res);
}

// round 7
// speedup vs baseline: 3.2172x; 1.1562x over previous
#include <cuda_runtime.h>
#include <cuda_bf16.h>
#include <cuda_fp16.h>
#include <math.h>
#include <cstdint>

#define BB 4
#define NN 12544
#define NBHD 48
#define DIM 256
#define OUTD 512
#define INNER 4
#define TABLE 4096
#define KEEP 3136
#define SAMP 2352
#define KDIM 1024
#define LNEPS 1e-5f
#define MTOT (BB * KEEP)   // 12544

// ---------------- device scratch ----------------
__device__ float   g_wt[TABLE * INNER];
__device__ int     g_idx[BB * KEEP];
__device__ __half  g_feat16[(size_t)BB * NN * DIM];   // 25.7MB
__device__ __half  g_X16[(size_t)MTOT * KDIM];        // 25.7MB, fp16 LN output
__device__ __half  g_Wh16[(size_t)OUTD * KDIM];       // [n][k] fp16 hi
__device__ __half  g_Wl16[(size_t)OUTD * KDIM];       // [n][k] fp16 lo

__device__ __forceinline__ uint32_t smem_u32(const void* p) {
    uint32_t a;
    asm("{ .reg .u64 t; cvta.to.shared.u64 t, %1; cvt.u32.u64 %0, t; }" : "=r"(a) : "l"(p));
    return a;
}

// ================= PREP kernel: selection + wt + wconv + feat16 =================
#define FEAT_BLKS 784
#define WCONV_BLKS 512
#define WT_BLKS 4
#define PREP_GRID (4 + FEAT_BLKS + WCONV_BLKS + WT_BLKS)

__device__ __forceinline__ unsigned key_inv(const float* pos, const float* lp, int b, int i) {
    int px = (int)pos[((size_t)b * NN + i) * 2 + 0];
    int py = (int)pos[((size_t)b * NN + i) * 2 + 1];
    float fp = (((px & 1) == 0) && ((py & 1) == 0)) ? 1.f : 0.f;
    fp += lp[(size_t)b * NN + i] * 4.f;
    if (((px & 3) == 0) && ((py & 3) == 0)) fp -= 100.f;
    unsigned u = __float_as_uint(fp);
    u = (u & 0x80000000u) ? ~u : (u ^ 0x80000000u);
    return ~u;
}

extern __shared__ __align__(16) unsigned char dynsm[];

__global__ __launch_bounds__(1024) void prep_kernel(
    const float* __restrict__ pos, const float* __restrict__ lp,
    const float* __restrict__ pre, const float* __restrict__ w1,
    const float* __restrict__ b1, const float* __restrict__ ln1g,
    const float* __restrict__ ln1b, const float* __restrict__ lw,
    const float* __restrict__ feat) {
    int blk = blockIdx.x;
    int tid = threadIdx.x;

    if (blk < 4) {
        // ---------- selection for batch b ----------
        int b = blk;
        unsigned* bins = (unsigned*)dynsm;                       // 8192 x u32
        unsigned long long* skeys = (unsigned long long*)dynsm;  // reuse: 4096 x u64
        __shared__ int s_wsum[32];
        __shared__ int s_T, s_cnt;

        for (int i = tid; i < 8192; i += 1024) bins[i] = 0;
        if (tid == 0) { s_cnt = 0; s_T = 8191; }
        __syncthreads();
        for (int i = tid; i < NN; i += 1024) {
            unsigned inv = key_inv(pos, lp, b, i);
            atomicAdd(&bins[inv >> 19], 1u);
        }
        __syncthreads();
        int part = 0;
#pragma unroll
        for (int q = 0; q < 8; q++) part += (int)bins[tid * 8 + q];
        int lane = tid & 31, wrp = tid >> 5;
        int v = part;
#pragma unroll
        for (int o = 1; o < 32; o <<= 1) { int nv = __shfl_up_sync(~0u, v, o); if (lane >= o) v += nv; }
        if (lane == 31) s_wsum[wrp] = v;
        __syncthreads();
        if (wrp == 0) {
            int w = s_wsum[lane];
#pragma unroll
            for (int o = 1; o < 32; o <<= 1) { int nv = __shfl_up_sync(~0u, w, o); if (lane >= o) w += nv; }
            s_wsum[lane] = w;
        }
        __syncthreads();
        int excl = v - part + (wrp > 0 ? s_wsum[wrp - 1] : 0);
        int cum = excl;
#pragma unroll
        for (int q = 0; q < 8; q++) {
            int cnt = (int)bins[tid * 8 + q];
            if (cum < SAMP && cum + cnt >= SAMP) s_T = tid * 8 + q;
            cum += cnt;
        }
        __syncthreads();
        int T = s_T;
        __syncthreads();
        for (int i = tid; i < 4096; i += 1024) skeys[i] = 0xFFFFFFFFFFFFFFFFull;
        __syncthreads();
        for (int i = tid; i < NN; i += 1024) {
            unsigned inv = key_inv(pos, lp, b, i);
            if ((int)(inv >> 19) <= T) {
                int p = atomicAdd(&s_cnt, 1);
                if (p < 4096) skeys[p] = (((unsigned long long)inv) << 32) | (unsigned)i;
            }
        }
        __syncthreads();
        for (int k = 2; k <= 4096; k <<= 1) {
            for (int j = k >> 1; j > 0; j >>= 1) {
                for (int i = tid; i < 4096; i += 1024) {
                    int ixj = i ^ j;
                    if (ixj > i) {
                        unsigned long long x = skeys[i], y = skeys[ixj];
                        bool up = ((i & k) == 0);
                        if (up ? (x > y) : (x < y)) { skeys[i] = y; skeys[ixj] = x; }
                    }
                }
                __syncthreads();
            }
        }
        for (int t = tid; t < KEEP; t += 1024) {
            int val;
            if (t < SAMP) val = (int)(skeys[t] & 0xFFFFFFFFull);
            else { int r = t - SAMP; val = ((r / 28) * 4) * 112 + (r % 28) * 4; }
            g_idx[b * KEEP + t] = val;
        }
        return;
    }
    blk -= 4;

    if (blk < FEAT_BLKS) {
        // ---------- feat fp32 -> fp16 : 4 consecutive float4 per thread ----------
        size_t base = ((size_t)blk * 1024 + tid) * 4;   // float4 index
        float4 f0 = ((const float4*)feat)[base + 0];
        float4 f1 = ((const float4*)feat)[base + 1];
        float4 f2 = ((const float4*)feat)[base + 2];
        float4 f3 = ((const float4*)feat)[base + 3];
        uint4 o0, o1;
        __half2 h;
        h = __floats2half2_rn(f0.x, f0.y); o0.x = *(uint32_t*)&h;
        h = __floats2half2_rn(f0.z, f0.w); o0.y = *(uint32_t*)&h;
        h = __floats2half2_rn(f1.x, f1.y); o0.z = *(uint32_t*)&h;
        h = __floats2half2_rn(f1.z, f1.w); o0.w = *(uint32_t*)&h;
        h = __floats2half2_rn(f2.x, f2.y); o1.x = *(uint32_t*)&h;
        h = __floats2half2_rn(f2.z, f2.w); o1.y = *(uint32_t*)&h;
        h = __floats2half2_rn(f3.x, f3.y); o1.z = *(uint32_t*)&h;
        h = __floats2half2_rn(f3.z, f3.w); o1.w = *(uint32_t*)&h;
        ((uint4*)g_feat16)[base / 2 + 0] = o0;
        ((uint4*)g_feat16)[base / 2 + 1] = o1;
        return;
    }
    blk -= FEAT_BLKS;

    if (blk < WCONV_BLKS) {
        // ---------- W transpose + fp16 hi/lo split via smem tile ----------
        __shared__ float tile[32][33];
        int tk = blk >> 4, tn = blk & 15;
        int k0 = tk * 32, n0 = tn * 32;
        int tx = tid & 31, ty = tid >> 5;
        tile[ty][tx] = lw[(size_t)(k0 + ty) * OUTD + n0 + tx];
        __syncthreads();
        int n = n0 + ty, k = k0 + tx;
        float val = tile[tx][ty];
        __half hh = __float2half_rn(val);
        g_Wh16[(size_t)n * KDIM + k] = hh;
        g_Wl16[(size_t)n * KDIM + k] = __float2half_rn(val - __half2float(hh));
        return;
    }
    blk -= WCONV_BLKS;

    // ---------- weight_net table ----------
    int r = blk * 1024 + tid;
    if (r < TABLE) {
        float p[5];
#pragma unroll
        for (int k = 0; k < 5; k++) p[k] = pre[r * 5 + k];
        float h[4];
#pragma unroll
        for (int m = 0; m < 4; m++) {
            float s = b1[m];
#pragma unroll
            for (int k = 0; k < 5; k++) s += p[k] * w1[k * 4 + m];
            h[m] = s;
        }
        float mean = 0.25f * (h[0] + h[1] + h[2] + h[3]);
        float vv = 0.f;
#pragma unroll
        for (int m = 0; m < 4; m++) { float d = h[m] - mean; vv += d * d; }
        float rstd = rsqrtf(vv * 0.25f + LNEPS);
#pragma unroll
        for (int m = 0; m < 4; m++) {
            float x = (h[m] - mean) * rstd * ln1g[m] + ln1b[m];
            g_wt[r * 4 + m] = 0.5f * x * (1.f + erff(x * 0.70710678118654752440f));
        }
    }
}

// ================= token kernel: gather (fp16) + weighted sum + LN -> X fp16 =================
__global__ __launch_bounds__(128) void token_kernel(
    const float* __restrict__ pos, const int* __restrict__ member,
    const float* __restrict__ cmask, const float* __restrict__ lp,
    const int* __restrict__ pe, const float* __restrict__ ng,
    const float* __restrict__ nb, float* __restrict__ out_pos) {
    int t = blockIdx.x;
    int b = t / KEEP;
    int tid = threadIdx.x;   // owns channels 2*tid, 2*tid+1

    __shared__ int    s_mem[NBHD];
    __shared__ float4 s_w4[NBHD];
    __shared__ float  red[4];
    __shared__ int    s_src;

    if (tid == 0) s_src = g_idx[t];
    __syncthreads();
    int src = s_src;

    if (tid < 2) out_pos[(size_t)t * 2 + tid] = pos[((size_t)b * NN + src) * 2 + tid];

    if (tid < NBHD) {
        size_t eoff = ((size_t)b * NN + src) * NBHD + tid;
        int mm = member[eoff];
        int pp = pe[eoff];
        float sc = lp[(size_t)b * NN + mm] * cmask[eoff];
        s_mem[tid] = mm;
        float4 w;
        w.x = g_wt[pp * 4 + 0] * sc;
        w.y = g_wt[pp * 4 + 1] * sc;
        w.z = g_wt[pp * 4 + 2] * sc;
        w.w = g_wt[pp * 4 + 3] * sc;
        s_w4[tid] = w;
    }
    __syncthreads();

    const __half2* fb = (const __half2*)(g_feat16 + (size_t)b * NN * DIM);
    float2 a0 = {0, 0}, a1 = {0, 0}, a2 = {0, 0}, a3 = {0, 0};
#pragma unroll 4
    for (int j = 0; j < NBHD; j++) {
        int mm = s_mem[j];
        float4 w = s_w4[j];
        float2 f = __half22float2(fb[(size_t)mm * 128 + tid]);
        a0.x += w.x * f.x; a0.y += w.x * f.y;
        a1.x += w.y * f.x; a1.y += w.y * f.y;
        a2.x += w.z * f.x; a2.y += w.z * f.y;
        a3.x += w.w * f.x; a3.y += w.w * f.y;
    }

    float s = a0.x + a0.y + a1.x + a1.y + a2.x + a2.y + a3.x + a3.y;
#pragma unroll
    for (int o = 16; o > 0; o >>= 1) s += __shfl_down_sync(0xffffffffu, s, o);
    if ((tid & 31) == 0) red[tid >> 5] = s;
    __syncthreads();
    float mean = (red[0] + red[1] + red[2] + red[3]) * (1.f / 1024.f);
    __syncthreads();

    float2 d0 = {a0.x - mean, a0.y - mean}, d1 = {a1.x - mean, a1.y - mean};
    float2 d2 = {a2.x - mean, a2.y - mean}, d3 = {a3.x - mean, a3.y - mean};
    float vs = d0.x * d0.x + d0.y * d0.y + d1.x * d1.x + d1.y * d1.y +
               d2.x * d2.x + d2.y * d2.y + d3.x * d3.x + d3.y * d3.y;
#pragma unroll
    for (int o = 16; o > 0; o >>= 1) vs += __shfl_down_sync(0xffffffffu, vs, o);
    if ((tid & 31) == 0) red[tid >> 5] = vs;
    __syncthreads();
    float rstd = rsqrtf((red[0] + red[1] + red[2] + red[3]) * (1.f / 1024.f) + LNEPS);

    __half* X = g_X16 + (size_t)t * KDIM;
    float2 dd[4] = {d0, d1, d2, d3};
#pragma unroll
    for (int m = 0; m < 4; m++) {
        int idx = m * 256 + tid * 2;
        float2 gg = *(const float2*)(ng + idx);
        float2 bbv = *(const float2*)(nb + idx);
        float v0 = dd[m].x * rstd * gg.x + bbv.x;
        float v1 = dd[m].y * rstd * gg.y + bbv.y;
        __half2 hh = __floats2half2_rn(v0, v1);
        *(uint32_t*)(X + idx) = *(uint32_t*)&hh;
    }
}

// ================= GEMM: cp.async double-buffered fp16 mma.sync (2-term) =================
#define BM 128
#define BN 128
#define BKK 32
#define NT (KDIM / BKK)   // 32
#define ASTR 40           // fp16 elems; 80B row stride
#define ARR_BYTES 10240   // 128 * 80
#define STAGE_BYTES (3 * ARR_BYTES)
#define GSMEM (2 * STAGE_BYTES)   // 61440

#define CP16(d, s) asm volatile("cp.async.cg.shared.global [%0], [%1], 16;" :: "r"(d), "l"(__cvta_generic_to_global(s)))
#define CP_COMMIT() asm volatile("cp.async.commit_group;" ::: "memory")
#define CP_WAIT1() asm volatile("cp.async.wait_group 1;" ::: "memory")
#define CP_WAIT0() asm volatile("cp.async.wait_group 0;" ::: "memory")

#define LDMX4(r0, r1, r2, r3, a) \
    asm volatile("ldmatrix.sync.aligned.m8n8.x4.shared.b16 {%0,%1,%2,%3}, [%4];" \
                 : "=r"(r0), "=r"(r1), "=r"(r2), "=r"(r3) : "r"(a))
#define LDMX2(r0, r1, a) \
    asm volatile("ldmatrix.sync.aligned.m8n8.x2.shared.b16 {%0,%1}, [%2];" \
                 : "=r"(r0), "=r"(r1) : "r"(a))
#define MMAF16(c, a, b) \
    asm volatile("mma.sync.aligned.m16n8k16.row.col.f32.f16.f16.f32 " \
                 "{%0,%1,%2,%3}, {%4,%5,%6,%7}, {%8,%9}, {%0,%1,%2,%3};" \
                 : "+f"((c)[0]), "+f"((c)[1]), "+f"((c)[2]), "+f"((c)[3]) \
                 : "r"((a)[0]), "r"((a)[1]), "r"((a)[2]), "r"((a)[3]), "r"((b)[0]), "r"((b)[1]))

// 128 rows x 4 chunks (16B); 512 chunk-loads per array; 2 iters x 256 thr
__device__ __forceinline__ void gemm_load(uint32_t sbase, int m0, int n0, int kt, int tid) {
    int k0 = kt * BKK;
#pragma unroll
    for (int it = 0; it < 2; it++) {
        int id = tid + it * 256;          // 0..511
        int r = id >> 2, c = id & 3;
        uint32_t doff = (uint32_t)(r * 80 + c * 16);
        CP16(sbase + 0 * ARR_BYTES + doff, g_X16  + (size_t)(m0 + r) * KDIM + k0 + c * 8);
        CP16(sbase + 1 * ARR_BYTES + doff, g_Wh16 + (size_t)(n0 + r) * KDIM + k0 + c * 8);
        CP16(sbase + 2 * ARR_BYTES + doff, g_Wl16 + (size_t)(n0 + r) * KDIM + k0 + c * 8);
    }
}

__global__ __launch_bounds__(256) void gemm_mma_kernel(const float* __restrict__ bias,
                                                       float* __restrict__ out) {
    uint32_t sb = smem_u32(dynsm);
    int tid = threadIdx.x;
    int wid = tid >> 5, lane = tid & 31;
    int wm = wid >> 2, wn = wid & 3;
    int n0 = blockIdx.x * BN;      // x = N (4 blocks) -> consecutive bids share M-stripe in L2
    int m0 = blockIdx.y * BM;

    float acc[4][4][4];
#pragma unroll
    for (int i = 0; i < 4; i++)
#pragma unroll
        for (int j = 0; j < 4; j++)
#pragma unroll
            for (int q = 0; q < 4; q++) acc[i][j][q] = 0.f;

    gemm_load(sb, m0, n0, 0, tid);
    CP_COMMIT();

    for (int kt = 0; kt < NT; kt++) {
        if (kt + 1 < NT) {
            gemm_load(sb + ((kt + 1) & 1) * STAGE_BYTES, m0, n0, kt + 1, tid);
            CP_COMMIT();
            CP_WAIT1();
        } else {
            CP_WAIT0();
        }
        __syncthreads();

        uint32_t base = sb + (kt & 1) * STAGE_BYTES;
        uint32_t uA = base;
        uint32_t uBh = base + 1 * ARR_BYTES, uBl = base + 2 * ARR_BYTES;

#pragma unroll
        for (int s = 0; s < 2; s++) {
            int kk = s * 16;
            uint32_t a[4][4], bh[4][2], bl[4][2];
            int arow = wm * 64 + (lane & 15);
            int acol = kk + (lane >> 4) * 8;
#pragma unroll
            for (int i = 0; i < 4; i++) {
                uint32_t off = (uint32_t)((arow + i * 16) * ASTR + acol) * 2;
                LDMX4(a[i][0], a[i][1], a[i][2], a[i][3], uA + off);
            }
            int brow = wn * 32 + (lane & 7);
            int bcol = kk + ((lane >> 3) & 1) * 8;
#pragma unroll
            for (int j = 0; j < 4; j++) {
                uint32_t off = (uint32_t)((brow + j * 8) * ASTR + bcol) * 2;
                LDMX2(bh[j][0], bh[j][1], uBh + off);
                LDMX2(bl[j][0], bl[j][1], uBl + off);
            }
#pragma unroll
            for (int i = 0; i < 4; i++)
#pragma unroll
                for (int j = 0; j < 4; j++) {
                    MMAF16(acc[i][j], a[i], bh[j]);
                    MMAF16(acc[i][j], a[i], bl[j]);
                }
        }
        __syncthreads();
    }

    int er = lane >> 2;
    int ec = (lane & 3) * 2;
#pragma unroll
    for (int i = 0; i < 4; i++) {
#pragma unroll
        for (int j = 0; j < 4; j++) {
            int m = m0 + wm * 64 + i * 16 + er;
            int n = n0 + wn * 32 + j * 8 + ec;
            float b0 = bias[n], b1 = bias[n + 1];
            float2 r0 = make_float2(acc[i][j][0] + b0, acc[i][j][1] + b1);
            float2 r1 = make_float2(acc[i][j][2] + b0, acc[i][j][3] + b1);
            *(float2*)(out + (size_t)m * OUTD + n) = r0;
            *(float2*)(out + (size_t)(m + 8) * OUTD + n) = r1;
        }
    }
}

// ---------------- launch ----------------
extern "C" void kernel_launch(void* const* d_in, const int* in_sizes, int n_in,
                              void* d_out, int out_size) {
    const float* pos    = (const float*)d_in[0];
    const float* feat   = (const float*)d_in[1];
    const int*   member = (const int*)d_in[2];
    const float* cmask  = (const float*)d_in[3];
    const float* lp     = (const float*)d_in[4];

    int pi = 5;
    if (pi < n_in && in_sizes[pi] == 1) pi++;
    const int* pe = (const int*)d_in[pi];

    int pt = pi + 1;
    while (pt < n_in && in_sizes[pt] != TABLE * 5) pt++;
    const float* pre    = (const float*)d_in[pt];
    const float* w1     = (const float*)d_in[pt + 1];
    const float* b1     = (const float*)d_in[pt + 2];
    const float* ln1_g  = (const float*)d_in[pt + 3];
    const float* ln1_b  = (const float*)d_in[pt + 4];
    const float* norm_g = (const float*)d_in[pt + 5];
    const float* norm_b = (const float*)d_in[pt + 6];
    const float* lin_w  = (const float*)d_in[pt + 7];
    const float* lin_b  = (const float*)d_in[pt + 8];

    float* out_pos = (float*)d_out;
    float* out_res = (float*)d_out + (size_t)BB * KEEP * 2;

    cudaFuncSetAttribute(gemm_mma_kernel, cudaFuncAttributeMaxDynamicSharedMemorySize, GSMEM);

    prep_kernel<<<PREP_GRID, 1024, 32768>>>(pos, lp, pre, w1, b1, ln1_g, ln1_b, lin_w, feat);
    token_kernel<<<MTOT, 128>>>(pos, member, cmask, lp, pe, norm_g, norm_b, out_pos);
    dim3 ggrid(OUTD / BN, MTOT / BM);
    gemm_mma_kernel<<<ggrid, 256, GSMEM>>>(lin_b, out_res);
}

// round 8
// speedup vs baseline: 3.3736x; 1.0486x over previous
#include <cuda_runtime.h>
#include <cuda_bf16.h>
#include <cuda_fp16.h>
#include <math.h>
#include <cstdint>

#define BB 4
#define NN 12544
#define NBHD 48
#define DIM 256
#define OUTD 512
#define INNER 4
#define TABLE 4096
#define KEEP 3136
#define SAMP 2352
#define KDIM 1024
#define LNEPS 1e-5f
#define MTOT (BB * KEEP)   // 12544
#define CAND_CAP 3584

// ---------------- device scratch ----------------
__device__ float   g_wt[TABLE * INNER];
__device__ int     g_idx[BB * KEEP];
__device__ __half  g_feat16[(size_t)BB * NN * DIM];   // 25.7MB
__device__ __half  g_X16[(size_t)MTOT * KDIM];        // 25.7MB
__device__ __half  g_Wh16[(size_t)OUTD * KDIM];       // [n][k] fp16 hi
__device__ __half  g_Wl16[(size_t)OUTD * KDIM];       // [n][k] fp16 lo

__device__ __forceinline__ uint32_t smem_u32(const void* p) {
    uint32_t a;
    asm("{ .reg .u64 t; cvta.to.shared.u64 t, %1; cvt.u32.u64 %0, t; }" : "=r"(a) : "l"(p));
    return a;
}

// ================= PREP kernel =================
#define FEAT_BLKS 784
#define WCONV_BLKS 512
#define WT_BLKS 4
#define PREP_GRID (4 + FEAT_BLKS + WCONV_BLKS + WT_BLKS)
// selection smem: bins 32KB + pref 32KB + cand 28KB = 94208B
#define PREP_SMEM (8192 * 4 * 2 + CAND_CAP * 8)

__device__ __forceinline__ unsigned key_inv(const float* pos, const float* lp, int b, int i) {
    int px = (int)pos[((size_t)b * NN + i) * 2 + 0];
    int py = (int)pos[((size_t)b * NN + i) * 2 + 1];
    float fp = (((px & 1) == 0) && ((py & 1) == 0)) ? 1.f : 0.f;
    fp += lp[(size_t)b * NN + i] * 4.f;
    if (((px & 3) == 0) && ((py & 3) == 0)) fp -= 100.f;
    unsigned u = __float_as_uint(fp);
    u = (u & 0x80000000u) ? ~u : (u ^ 0x80000000u);
    return ~u;   // ascending inv = descending prob
}

extern __shared__ __align__(16) unsigned char dynsm[];

__global__ __launch_bounds__(1024) void prep_kernel(
    const float* __restrict__ pos, const float* __restrict__ lp,
    const float* __restrict__ pre, const float* __restrict__ w1,
    const float* __restrict__ b1, const float* __restrict__ ln1g,
    const float* __restrict__ ln1b, const float* __restrict__ lw,
    const float* __restrict__ feat) {
    int blk = blockIdx.x;
    int tid = threadIdx.x;

    if (blk < 4) {
        // ---------- selection for batch b: histogram-rank (no sort) ----------
        int b = blk;
        unsigned* bins = (unsigned*)dynsm;                          // [8192]
        unsigned* pref = (unsigned*)(dynsm + 32768);                // [8192]
        unsigned long long* cand = (unsigned long long*)(dynsm + 65536);  // [CAND_CAP]
        __shared__ int s_wsum[32];
        __shared__ int s_T, s_total;

        for (int i = tid; i < 8192; i += 1024) bins[i] = 0;
        if (tid == 0) s_T = 8191;
        __syncthreads();
        for (int i = tid; i < NN; i += 1024)
            atomicAdd(&bins[key_inv(pos, lp, b, i) >> 19], 1u);
        __syncthreads();

        // exclusive scan over 8192 bins (8 per thread)
        int part = 0;
        unsigned mybin[8];
#pragma unroll
        for (int q = 0; q < 8; q++) { mybin[q] = bins[tid * 8 + q]; part += (int)mybin[q]; }
        int lane = tid & 31, wrp = tid >> 5;
        int v = part;
#pragma unroll
        for (int o = 1; o < 32; o <<= 1) { int nv = __shfl_up_sync(~0u, v, o); if (lane >= o) v += nv; }
        if (lane == 31) s_wsum[wrp] = v;
        __syncthreads();
        if (wrp == 0) {
            int w = s_wsum[lane];
#pragma unroll
            for (int o = 1; o < 32; o <<= 1) { int nv = __shfl_up_sync(~0u, w, o); if (lane >= o) w += nv; }
            s_wsum[lane] = w;
        }
        __syncthreads();
        int excl = v - part + (wrp > 0 ? s_wsum[wrp - 1] : 0);
        int cum = excl;
#pragma unroll
        for (int q = 0; q < 8; q++) {
            pref[tid * 8 + q] = (unsigned)cum;
            int cnt = (int)mybin[q];
            if (cum < SAMP && cum + cnt >= SAMP) s_T = tid * 8 + q;
            cum += cnt;
        }
        __syncthreads();
        int T = s_T;
        if (tid == 0) s_total = (int)pref[T] + (int)bins[T];
        __syncthreads();
        int total = s_total;
        if (total > CAND_CAP) total = CAND_CAP;

        // scatter candidates grouped by bin (pref[b] becomes end offset)
        for (int i = tid; i < NN; i += 1024) {
            unsigned inv = key_inv(pos, lp, b, i);
            int bb = (int)(inv >> 19);
            if (bb <= T) {
                unsigned slot = atomicAdd(&pref[bb], 1u);
                if (slot < CAND_CAP)
                    cand[slot] = (((unsigned long long)inv) << 32) | (unsigned)i;
            }
        }
        __syncthreads();

        // rank within bin -> write ordered indices
        for (int s = tid; s < total; s += 1024) {
            unsigned long long key = cand[s];
            int bb = (int)(key >> 51);
            int end = (int)pref[bb]; if (end > total) end = total;
            int start = end - (int)bins[bb]; if (start < 0) start = 0;
            int r = start;
            for (int j = start; j < end; j++)
                if (cand[j] < key) r++;
            if (r < SAMP) g_idx[b * KEEP + r] = (int)(key & 0xFFFFFFFFull);
        }
        // reserve indices
        for (int t = SAMP + tid; t < KEEP; t += 1024) {
            int r = t - SAMP;
            g_idx[b * KEEP + t] = ((r / 28) * 4) * 112 + (r % 28) * 4;
        }
        return;
    }
    blk -= 4;

    if (blk < FEAT_BLKS) {
        // ---------- feat fp32 -> fp16 ----------
        size_t base = ((size_t)blk * 1024 + tid) * 4;   // float4 index
        float4 f0 = ((const float4*)feat)[base + 0];
        float4 f1 = ((const float4*)feat)[base + 1];
        float4 f2 = ((const float4*)feat)[base + 2];
        float4 f3 = ((const float4*)feat)[base + 3];
        uint4 o0, o1;
        __half2 h;
        h = __floats2half2_rn(f0.x, f0.y); o0.x = *(uint32_t*)&h;
        h = __floats2half2_rn(f0.z, f0.w); o0.y = *(uint32_t*)&h;
        h = __floats2half2_rn(f1.x, f1.y); o0.z = *(uint32_t*)&h;
        h = __floats2half2_rn(f1.z, f1.w); o0.w = *(uint32_t*)&h;
        h = __floats2half2_rn(f2.x, f2.y); o1.x = *(uint32_t*)&h;
        h = __floats2half2_rn(f2.z, f2.w); o1.y = *(uint32_t*)&h;
        h = __floats2half2_rn(f3.x, f3.y); o1.z = *(uint32_t*)&h;
        h = __floats2half2_rn(f3.z, f3.w); o1.w = *(uint32_t*)&h;
        ((uint4*)g_feat16)[base / 2 + 0] = o0;
        ((uint4*)g_feat16)[base / 2 + 1] = o1;
        return;
    }
    blk -= FEAT_BLKS;

    if (blk < WCONV_BLKS) {
        // ---------- W transpose + fp16 hi/lo split ----------
        __shared__ float tile[32][33];
        int tk = blk >> 4, tn = blk & 15;
        int k0 = tk * 32, n0 = tn * 32;
        int tx = tid & 31, ty = tid >> 5;
        tile[ty][tx] = lw[(size_t)(k0 + ty) * OUTD + n0 + tx];
        __syncthreads();
        int n = n0 + ty, k = k0 + tx;
        float val = tile[tx][ty];
        __half hh = __float2half_rn(val);
        g_Wh16[(size_t)n * KDIM + k] = hh;
        g_Wl16[(size_t)n * KDIM + k] = __float2half_rn(val - __half2float(hh));
        return;
    }
    blk -= WCONV_BLKS;

    // ---------- weight_net table ----------
    int r = blk * 1024 + tid;
    if (r < TABLE) {
        float p[5];
#pragma unroll
        for (int k = 0; k < 5; k++) p[k] = pre[r * 5 + k];
        float h[4];
#pragma unroll
        for (int m = 0; m < 4; m++) {
            float s = b1[m];
#pragma unroll
            for (int k = 0; k < 5; k++) s += p[k] * w1[k * 4 + m];
            h[m] = s;
        }
        float mean = 0.25f * (h[0] + h[1] + h[2] + h[3]);
        float vv = 0.f;
#pragma unroll
        for (int m = 0; m < 4; m++) { float d = h[m] - mean; vv += d * d; }
        float rstd = rsqrtf(vv * 0.25f + LNEPS);
#pragma unroll
        for (int m = 0; m < 4; m++) {
            float x = (h[m] - mean) * rstd * ln1g[m] + ln1b[m];
            g_wt[r * 4 + m] = 0.5f * x * (1.f + erff(x * 0.70710678118654752440f));
        }
    }
}

// ================= token kernel: 2 tokens per 256-thr block =================
__global__ __launch_bounds__(256) void token_kernel(
    const float* __restrict__ pos, const int* __restrict__ member,
    const float* __restrict__ cmask, const float* __restrict__ lp,
    const int* __restrict__ pe, const float* __restrict__ ng,
    const float* __restrict__ nb, float* __restrict__ out_pos) {
    int tid = threadIdx.x;
    int half = tid >> 7;         // 0 or 1
    int htid = tid & 127;        // channel pair id within half
    int t = blockIdx.x * 2 + half;
    int b = t / KEEP;

    __shared__ int    s_mem[2][NBHD];
    __shared__ float4 s_w4[2][NBHD];
    __shared__ float  red[8];
    __shared__ int    s_src[2];

    if (htid == 0) s_src[half] = g_idx[t];
    __syncthreads();
    int src = s_src[half];

    if (htid < 2) out_pos[(size_t)t * 2 + htid] = pos[((size_t)b * NN + src) * 2 + htid];

    if (htid < NBHD) {
        size_t eoff = ((size_t)b * NN + src) * NBHD + htid;
        int mm = member[eoff];
        int pp = pe[eoff];
        float sc = lp[(size_t)b * NN + mm] * cmask[eoff];
        s_mem[half][htid] = mm;
        float4 w;
        w.x = g_wt[pp * 4 + 0] * sc;
        w.y = g_wt[pp * 4 + 1] * sc;
        w.z = g_wt[pp * 4 + 2] * sc;
        w.w = g_wt[pp * 4 + 3] * sc;
        s_w4[half][htid] = w;
    }
    __syncthreads();

    const __half2* fb = (const __half2*)(g_feat16 + (size_t)b * NN * DIM);
    float2 a0 = {0, 0}, a1 = {0, 0}, a2 = {0, 0}, a3 = {0, 0};
#pragma unroll 4
    for (int j = 0; j < NBHD; j++) {
        int mm = s_mem[half][j];
        float4 w = s_w4[half][j];
        float2 f = __half22float2(fb[(size_t)mm * 128 + htid]);
        a0.x += w.x * f.x; a0.y += w.x * f.y;
        a1.x += w.y * f.x; a1.y += w.y * f.y;
        a2.x += w.z * f.x; a2.y += w.z * f.y;
        a3.x += w.w * f.x; a3.y += w.w * f.y;
    }

    float s = a0.x + a0.y + a1.x + a1.y + a2.x + a2.y + a3.x + a3.y;
#pragma unroll
    for (int o = 16; o > 0; o >>= 1) s += __shfl_down_sync(0xffffffffu, s, o);
    if ((tid & 31) == 0) red[tid >> 5] = s;
    __syncthreads();
    float mean = (red[half * 4 + 0] + red[half * 4 + 1] + red[half * 4 + 2] + red[half * 4 + 3]) * (1.f / 1024.f);
    __syncthreads();

    float2 d0 = {a0.x - mean, a0.y - mean}, d1 = {a1.x - mean, a1.y - mean};
    float2 d2 = {a2.x - mean, a2.y - mean}, d3 = {a3.x - mean, a3.y - mean};
    float vs = d0.x * d0.x + d0.y * d0.y + d1.x * d1.x + d1.y * d1.y +
               d2.x * d2.x + d2.y * d2.y + d3.x * d3.x + d3.y * d3.y;
#pragma unroll
    for (int o = 16; o > 0; o >>= 1) vs += __shfl_down_sync(0xffffffffu, vs, o);
    if ((tid & 31) == 0) red[tid >> 5] = vs;
    __syncthreads();
    float rstd = rsqrtf((red[half * 4 + 0] + red[half * 4 + 1] + red[half * 4 + 2] + red[half * 4 + 3]) * (1.f / 1024.f) + LNEPS);

    __half* X = g_X16 + (size_t)t * KDIM;
    float2 dd[4] = {d0, d1, d2, d3};
#pragma unroll
    for (int m = 0; m < 4; m++) {
        int idx = m * 256 + htid * 2;
        float2 gg = *(const float2*)(ng + idx);
        float2 bbv = *(const float2*)(nb + idx);
        float v0 = dd[m].x * rstd * gg.x + bbv.x;
        float v1 = dd[m].y * rstd * gg.y + bbv.y;
        __half2 hh = __floats2half2_rn(v0, v1);
        *(uint32_t*)(X + idx) = *(uint32_t*)&hh;
    }
}

// ================= GEMM: cp.async double-buffered fp16 mma.sync (2-term) =================
#define BM 128
#define BN 128
#define BKK 32
#define NT (KDIM / BKK)   // 32
#define ASTR 40           // fp16 elems; 80B row stride
#define ARR_BYTES 10240
#define STAGE_BYTES (3 * ARR_BYTES)
#define GSMEM (2 * STAGE_BYTES)   // 61440

#define CP16(d, s) asm volatile("cp.async.cg.shared.global [%0], [%1], 16;" :: "r"(d), "l"(__cvta_generic_to_global(s)))
#define CP_COMMIT() asm volatile("cp.async.commit_group;" ::: "memory")
#define CP_WAIT1() asm volatile("cp.async.wait_group 1;" ::: "memory")
#define CP_WAIT0() asm volatile("cp.async.wait_group 0;" ::: "memory")

#define LDMX4(r0, r1, r2, r3, a) \
    asm volatile("ldmatrix.sync.aligned.m8n8.x4.shared.b16 {%0,%1,%2,%3}, [%4];" \
                 : "=r"(r0), "=r"(r1), "=r"(r2), "=r"(r3) : "r"(a))
#define LDMX2(r0, r1, a) \
    asm volatile("ldmatrix.sync.aligned.m8n8.x2.shared.b16 {%0,%1}, [%2];" \
                 : "=r"(r0), "=r"(r1) : "r"(a))
#define MMAF16(c, a, b) \
    asm volatile("mma.sync.aligned.m16n8k16.row.col.f32.f16.f16.f32 " \
                 "{%0,%1,%2,%3}, {%4,%5,%6,%7}, {%8,%9}, {%0,%1,%2,%3};" \
                 : "+f"((c)[0]), "+f"((c)[1]), "+f"((c)[2]), "+f"((c)[3]) \
                 : "r"((a)[0]), "r"((a)[1]), "r"((a)[2]), "r"((a)[3]), "r"((b)[0]), "r"((b)[1]))

__device__ __forceinline__ void gemm_load(uint32_t sbase, int m0, int n0, int kt, int tid) {
    int k0 = kt * BKK;
#pragma unroll
    for (int it = 0; it < 2; it++) {
        int id = tid + it * 256;          // 0..511
        int r = id >> 2, c = id & 3;
        uint32_t doff = (uint32_t)(r * 80 + c * 16);
        CP16(sbase + 0 * ARR_BYTES + doff, g_X16  + (size_t)(m0 + r) * KDIM + k0 + c * 8);
        CP16(sbase + 1 * ARR_BYTES + doff, g_Wh16 + (size_t)(n0 + r) * KDIM + k0 + c * 8);
        CP16(sbase + 2 * ARR_BYTES + doff, g_Wl16 + (size_t)(n0 + r) * KDIM + k0 + c * 8);
    }
}

__global__ __launch_bounds__(256) void gemm_mma_kernel(const float* __restrict__ bias,
                                                       float* __restrict__ out) {
    uint32_t sb = smem_u32(dynsm);
    int tid = threadIdx.x;
    int wid = tid >> 5, lane = tid & 31;
    int wm = wid >> 2, wn = wid & 3;
    int n0 = blockIdx.x * BN;      // 4 N-blocks consecutive -> share M-stripe in L2
    int m0 = blockIdx.y * BM;

    float acc[4][4][4];
#pragma unroll
    for (int i = 0; i < 4; i++)
#pragma unroll
        for (int j = 0; j < 4; j++)
#pragma unroll
            for (int q = 0; q < 4; q++) acc[i][j][q] = 0.f;

    gemm_load(sb, m0, n0, 0, tid);
    CP_COMMIT();

    for (int kt = 0; kt < NT; kt++) {
        if (kt + 1 < NT) {
            gemm_load(sb + ((kt + 1) & 1) * STAGE_BYTES, m0, n0, kt + 1, tid);
            CP_COMMIT();
            CP_WAIT1();
        } else {
            CP_WAIT0();
        }
        __syncthreads();

        uint32_t base = sb + (kt & 1) * STAGE_BYTES;
        uint32_t uA = base;
        uint32_t uBh = base + 1 * ARR_BYTES, uBl = base + 2 * ARR_BYTES;

#pragma unroll
        for (int s = 0; s < 2; s++) {
            int kk = s * 16;
            uint32_t a[4][4], bh[4][2], bl[4][2];
            int arow = wm * 64 + (lane & 15);
            int acol = kk + (lane >> 4) * 8;
#pragma unroll
            for (int i = 0; i < 4; i++) {
                uint32_t off = (uint32_t)((arow + i * 16) * ASTR + acol) * 2;
                LDMX4(a[i][0], a[i][1], a[i][2], a[i][3], uA + off);
            }
            int brow = wn * 32 + (lane & 7);
            int bcol = kk + ((lane >> 3) & 1) * 8;
#pragma unroll
            for (int j = 0; j < 4; j++) {
                uint32_t off = (uint32_t)((brow + j * 8) * ASTR + bcol) * 2;
                LDMX2(bh[j][0], bh[j][1], uBh + off);
                LDMX2(bl[j][0], bl[j][1], uBl + off);
            }
#pragma unroll
            for (int i = 0; i < 4; i++)
#pragma unroll
                for (int j = 0; j < 4; j++) {
                    MMAF16(acc[i][j], a[i], bh[j]);
                    MMAF16(acc[i][j], a[i], bl[j]);
                }
        }
        __syncthreads();
    }

    int er = lane >> 2;
    int ec = (lane & 3) * 2;
#pragma unroll
    for (int i = 0; i < 4; i++) {
#pragma unroll
        for (int j = 0; j < 4; j++) {
            int m = m0 + wm * 64 + i * 16 + er;
            int n = n0 + wn * 32 + j * 8 + ec;
            float b0 = bias[n], b1 = bias[n + 1];
            float2 r0 = make_float2(acc[i][j][0] + b0, acc[i][j][1] + b1);
            float2 r1 = make_float2(acc[i][j][2] + b0, acc[i][j][3] + b1);
            *(float2*)(out + (size_t)m * OUTD + n) = r0;
            *(float2*)(out + (size_t)(m + 8) * OUTD + n) = r1;
        }
    }
}

// ---------------- launch ----------------
extern "C" void kernel_launch(void* const* d_in, const int* in_sizes, int n_in,
                              void* d_out, int out_size) {
    const float* pos    = (const float*)d_in[0];
    const float* feat   = (const float*)d_in[1];
    const int*   member = (const int*)d_in[2];
    const float* cmask  = (const float*)d_in[3];
    const float* lp     = (const float*)d_in[4];

    int pi = 5;
    if (pi < n_in && in_sizes[pi] == 1) pi++;
    const int* pe = (const int*)d_in[pi];

    int pt = pi + 1;
    while (pt < n_in && in_sizes[pt] != TABLE * 5) pt++;
    const float* pre    = (const float*)d_in[pt];
    const float* w1     = (const float*)d_in[pt + 1];
    const float* b1     = (const float*)d_in[pt + 2];
    const float* ln1_g  = (const float*)d_in[pt + 3];
    const float* ln1_b  = (const float*)d_in[pt + 4];
    const float* norm_g = (const float*)d_in[pt + 5];
    const float* norm_b = (const float*)d_in[pt + 6];
    const float* lin_w  = (const float*)d_in[pt + 7];
    const float* lin_b  = (const float*)d_in[pt + 8];

    float* out_pos = (float*)d_out;
    float* out_res = (float*)d_out + (size_t)BB * KEEP * 2;

    cudaFuncSetAttribute(prep_kernel, cudaFuncAttributeMaxDynamicSharedMemorySize, PREP_SMEM);
    cudaFuncSetAttribute(gemm_mma_kernel, cudaFuncAttributeMaxDynamicSharedMemorySize, GSMEM);

    prep_kernel<<<PREP_GRID, 1024, PREP_SMEM>>>(pos, lp, pre, w1, b1, ln1_g, ln1_b, lin_w, feat);
    token_kernel<<<MTOT / 2, 256>>>(pos, member, cmask, lp, pe, norm_g, norm_b, out_pos);
    dim3 ggrid(OUTD / BN, MTOT / BM);
    gemm_mma_kernel<<<ggrid, 256, GSMEM>>>(lin_b, out_res);
}

// round 9
// speedup vs baseline: 4.5552x; 1.3502x over previous
#include <cuda_runtime.h>
#include <cuda_bf16.h>
#include <cuda_fp16.h>
#include <math.h>
#include <cstdint>

#define BB 4
#define NN 12544
#define NBHD 48
#define DIM 256
#define OUTD 512
#define INNER 4
#define TABLE 4096
#define KEEP 3136
#define SAMP 2352
#define KDIM 1024
#define LNEPS 1e-5f
#define MTOT (BB * KEEP)   // 12544
#define CAND_CAP 3584
#define NBINS 8192
#define BIN_SCALE 1560.0f
#define BIN_OFF 5.25f

// ---------------- device scratch ----------------
__device__ float   g_wt[TABLE * INNER];
__device__ int     g_idx[BB * KEEP];
__device__ __half  g_feat16[(size_t)BB * NN * DIM];   // 25.7MB
__device__ __half  g_X16[(size_t)MTOT * KDIM];        // 25.7MB
__device__ __half  g_Wh16[(size_t)OUTD * KDIM];       // [n][k] fp16

__device__ __forceinline__ uint32_t smem_u32(const void* p) {
    uint32_t a;
    asm("{ .reg .u64 t; cvta.to.shared.u64 t, %1; cvt.u32.u64 %0, t; }" : "=r"(a) : "l"(p));
    return a;
}

// ================= PREP kernel =================
#define FEAT_BLKS 784
#define WCONV_BLKS 512
#define WT_BLKS 4
#define PREP_GRID (4 + FEAT_BLKS + WCONV_BLKS + WT_BLKS)
// selection smem: bins 32KB + pref 32KB + cand 28KB
#define PREP_SMEM (NBINS * 4 * 2 + CAND_CAP * 8)

__device__ __forceinline__ float prob_of(const float* pos, const float* lp, int b, int i) {
    int px = (int)pos[((size_t)b * NN + i) * 2 + 0];
    int py = (int)pos[((size_t)b * NN + i) * 2 + 1];
    float fp = (((px & 1) == 0) && ((py & 1) == 0)) ? 1.f : 0.f;
    fp += lp[(size_t)b * NN + i] * 4.f;
    if (((px & 3) == 0) && ((py & 3) == 0)) fp -= 100.f;
    return fp;
}
__device__ __forceinline__ unsigned inv_of(float fp) {
    unsigned u = __float_as_uint(fp);
    u = (u & 0x80000000u) ? ~u : (u ^ 0x80000000u);
    return ~u;   // ascending inv = descending prob
}
__device__ __forceinline__ float fp_of_inv(unsigned inv) {
    unsigned enc = ~inv;
    unsigned u = (enc & 0x80000000u) ? (enc ^ 0x80000000u) : ~enc;
    return __uint_as_float(u);
}
__device__ __forceinline__ int bin_of_fp(float fp) {
    int bb = (int)((BIN_OFF - fp) * BIN_SCALE);
    return bb < 0 ? 0 : (bb > NBINS - 1 ? NBINS - 1 : bb);
}

extern __shared__ __align__(16) unsigned char dynsm[];

__global__ __launch_bounds__(1024) void prep_kernel(
    const float* __restrict__ pos, const float* __restrict__ lp,
    const float* __restrict__ pre, const float* __restrict__ w1,
    const float* __restrict__ b1, const float* __restrict__ ln1g,
    const float* __restrict__ ln1b, const float* __restrict__ lw,
    const float* __restrict__ feat) {
    int blk = blockIdx.x;
    int tid = threadIdx.x;

    if (blk < 4) {
        // ---------- selection for batch b: linear-bin histogram rank ----------
        int b = blk;
        unsigned* bins = (unsigned*)dynsm;                                // [NBINS]
        unsigned* pref = (unsigned*)(dynsm + NBINS * 4);                  // [NBINS]
        unsigned long long* cand = (unsigned long long*)(dynsm + NBINS * 8);  // [CAND_CAP]
        __shared__ int s_wsum[32];
        __shared__ int s_T, s_total;

        for (int i = tid; i < NBINS; i += 1024) bins[i] = 0;
        if (tid == 0) s_T = NBINS - 1;
        __syncthreads();
        for (int i = tid; i < NN; i += 1024)
            atomicAdd(&bins[bin_of_fp(prob_of(pos, lp, b, i))], 1u);
        __syncthreads();

        // exclusive scan over NBINS (8 per thread)
        int part = 0;
        unsigned mybin[8];
#pragma unroll
        for (int q = 0; q < 8; q++) { mybin[q] = bins[tid * 8 + q]; part += (int)mybin[q]; }
        int lane = tid & 31, wrp = tid >> 5;
        int v = part;
#pragma unroll
        for (int o = 1; o < 32; o <<= 1) { int nv = __shfl_up_sync(~0u, v, o); if (lane >= o) v += nv; }
        if (lane == 31) s_wsum[wrp] = v;
        __syncthreads();
        if (wrp == 0) {
            int w = s_wsum[lane];
#pragma unroll
            for (int o = 1; o < 32; o <<= 1) { int nv = __shfl_up_sync(~0u, w, o); if (lane >= o) w += nv; }
            s_wsum[lane] = w;
        }
        __syncthreads();
        int excl = v - part + (wrp > 0 ? s_wsum[wrp - 1] : 0);
        int cum = excl;
#pragma unroll
        for (int q = 0; q < 8; q++) {
            pref[tid * 8 + q] = (unsigned)cum;
            int cnt = (int)mybin[q];
            if (cum < SAMP && cum + cnt >= SAMP) s_T = tid * 8 + q;
            cum += cnt;
        }
        __syncthreads();
        int T = s_T;
        if (tid == 0) s_total = (int)pref[T] + (int)bins[T];
        __syncthreads();
        int total = s_total;
        if (total > CAND_CAP) total = CAND_CAP;

        // scatter candidates grouped by bin (pref[b] becomes end offset)
        for (int i = tid; i < NN; i += 1024) {
            float fp = prob_of(pos, lp, b, i);
            int bb = bin_of_fp(fp);
            if (bb <= T) {
                unsigned slot = atomicAdd(&pref[bb], 1u);
                if (slot < CAND_CAP)
                    cand[slot] = (((unsigned long long)inv_of(fp)) << 32) | (unsigned)i;
            }
        }
        __syncthreads();

        // rank within bin -> write ordered indices
        for (int s = tid; s < total; s += 1024) {
            unsigned long long key = cand[s];
            int bb = bin_of_fp(fp_of_inv((unsigned)(key >> 32)));
            int end = (int)pref[bb]; if (end > total) end = total;
            int start = end - (int)bins[bb]; if (start < 0) start = 0;
            int r = start;
            for (int j = start; j < end; j++)
                if (cand[j] < key) r++;
            if (r < SAMP) g_idx[b * KEEP + r] = (int)(key & 0xFFFFFFFFull);
        }
        // reserve indices
        for (int t = SAMP + tid; t < KEEP; t += 1024) {
            int r = t - SAMP;
            g_idx[b * KEEP + t] = ((r / 28) * 4) * 112 + (r % 28) * 4;
        }
        return;
    }
    blk -= 4;

    if (blk < FEAT_BLKS) {
        // ---------- feat fp32 -> fp16 ----------
        size_t base = ((size_t)blk * 1024 + tid) * 4;   // float4 index
        float4 f0 = ((const float4*)feat)[base + 0];
        float4 f1 = ((const float4*)feat)[base + 1];
        float4 f2 = ((const float4*)feat)[base + 2];
        float4 f3 = ((const float4*)feat)[base + 3];
        uint4 o0, o1;
        __half2 h;
        h = __floats2half2_rn(f0.x, f0.y); o0.x = *(uint32_t*)&h;
        h = __floats2half2_rn(f0.z, f0.w); o0.y = *(uint32_t*)&h;
        h = __floats2half2_rn(f1.x, f1.y); o0.z = *(uint32_t*)&h;
        h = __floats2half2_rn(f1.z, f1.w); o0.w = *(uint32_t*)&h;
        h = __floats2half2_rn(f2.x, f2.y); o1.x = *(uint32_t*)&h;
        h = __floats2half2_rn(f2.z, f2.w); o1.y = *(uint32_t*)&h;
        h = __floats2half2_rn(f3.x, f3.y); o1.z = *(uint32_t*)&h;
        h = __floats2half2_rn(f3.z, f3.w); o1.w = *(uint32_t*)&h;
        ((uint4*)g_feat16)[base / 2 + 0] = o0;
        ((uint4*)g_feat16)[base / 2 + 1] = o1;
        return;
    }
    blk -= FEAT_BLKS;

    if (blk < WCONV_BLKS) {
        // ---------- W transpose -> fp16 ----------
        __shared__ float tile[32][33];
        int tk = blk >> 4, tn = blk & 15;
        int k0 = tk * 32, n0 = tn * 32;
        int tx = tid & 31, ty = tid >> 5;
        tile[ty][tx] = lw[(size_t)(k0 + ty) * OUTD + n0 + tx];
        __syncthreads();
        int n = n0 + ty, k = k0 + tx;
        g_Wh16[(size_t)n * KDIM + k] = __float2half_rn(tile[tx][ty]);
        return;
    }
    blk -= WCONV_BLKS;

    // ---------- weight_net table ----------
    int r = blk * 1024 + tid;
    if (r < TABLE) {
        float p[5];
#pragma unroll
        for (int k = 0; k < 5; k++) p[k] = pre[r * 5 + k];
        float h[4];
#pragma unroll
        for (int m = 0; m < 4; m++) {
            float s = b1[m];
#pragma unroll
            for (int k = 0; k < 5; k++) s += p[k] * w1[k * 4 + m];
            h[m] = s;
        }
        float mean = 0.25f * (h[0] + h[1] + h[2] + h[3]);
        float vv = 0.f;
#pragma unroll
        for (int m = 0; m < 4; m++) { float d = h[m] - mean; vv += d * d; }
        float rstd = rsqrtf(vv * 0.25f + LNEPS);
#pragma unroll
        for (int m = 0; m < 4; m++) {
            float x = (h[m] - mean) * rstd * ln1g[m] + ln1b[m];
            g_wt[r * 4 + m] = 0.5f * x * (1.f + erff(x * 0.70710678118654752440f));
        }
    }
}

// ================= token kernel: 2 tokens per 256-thr block =================
__global__ __launch_bounds__(256) void token_kernel(
    const float* __restrict__ pos, const int* __restrict__ member,
    const float* __restrict__ cmask, const float* __restrict__ lp,
    const int* __restrict__ pe, const float* __restrict__ ng,
    const float* __restrict__ nb, float* __restrict__ out_pos) {
    int tid = threadIdx.x;
    int half = tid >> 7;
    int htid = tid & 127;
    int t = blockIdx.x * 2 + half;
    int b = t / KEEP;

    __shared__ int    s_mem[2][NBHD];
    __shared__ float4 s_w4[2][NBHD];
    __shared__ float  red[8];
    __shared__ int    s_src[2];

    if (htid == 0) s_src[half] = g_idx[t];
    __syncthreads();
    int src = s_src[half];

    if (htid < 2) out_pos[(size_t)t * 2 + htid] = pos[((size_t)b * NN + src) * 2 + htid];

    if (htid < NBHD) {
        size_t eoff = ((size_t)b * NN + src) * NBHD + htid;
        int mm = member[eoff];
        int pp = pe[eoff];
        float sc = lp[(size_t)b * NN + mm] * cmask[eoff];
        s_mem[half][htid] = mm;
        float4 w;
        w.x = g_wt[pp * 4 + 0] * sc;
        w.y = g_wt[pp * 4 + 1] * sc;
        w.z = g_wt[pp * 4 + 2] * sc;
        w.w = g_wt[pp * 4 + 3] * sc;
        s_w4[half][htid] = w;
    }
    __syncthreads();

    const __half2* fb = (const __half2*)(g_feat16 + (size_t)b * NN * DIM);
    float2 a0 = {0, 0}, a1 = {0, 0}, a2 = {0, 0}, a3 = {0, 0};
#pragma unroll 4
    for (int j = 0; j < NBHD; j++) {
        int mm = s_mem[half][j];
        float4 w = s_w4[half][j];
        float2 f = __half22float2(fb[(size_t)mm * 128 + htid]);
        a0.x += w.x * f.x; a0.y += w.x * f.y;
        a1.x += w.y * f.x; a1.y += w.y * f.y;
        a2.x += w.z * f.x; a2.y += w.z * f.y;
        a3.x += w.w * f.x; a3.y += w.w * f.y;
    }

    float s = a0.x + a0.y + a1.x + a1.y + a2.x + a2.y + a3.x + a3.y;
#pragma unroll
    for (int o = 16; o > 0; o >>= 1) s += __shfl_down_sync(0xffffffffu, s, o);
    if ((tid & 31) == 0) red[tid >> 5] = s;
    __syncthreads();
    float mean = (red[half * 4 + 0] + red[half * 4 + 1] + red[half * 4 + 2] + red[half * 4 + 3]) * (1.f / 1024.f);
    __syncthreads();

    float2 d0 = {a0.x - mean, a0.y - mean}, d1 = {a1.x - mean, a1.y - mean};
    float2 d2 = {a2.x - mean, a2.y - mean}, d3 = {a3.x - mean, a3.y - mean};
    float vs = d0.x * d0.x + d0.y * d0.y + d1.x * d1.x + d1.y * d1.y +
               d2.x * d2.x + d2.y * d2.y + d3.x * d3.x + d3.y * d3.y;
#pragma unroll
    for (int o = 16; o > 0; o >>= 1) vs += __shfl_down_sync(0xffffffffu, vs, o);
    if ((tid & 31) == 0) red[tid >> 5] = vs;
    __syncthreads();
    float rstd = rsqrtf((red[half * 4 + 0] + red[half * 4 + 1] + red[half * 4 + 2] + red[half * 4 + 3]) * (1.f / 1024.f) + LNEPS);

    __half* X = g_X16 + (size_t)t * KDIM;
    float2 dd[4] = {d0, d1, d2, d3};
#pragma unroll
    for (int m = 0; m < 4; m++) {
        int idx = m * 256 + htid * 2;
        float2 gg = *(const float2*)(ng + idx);
        float2 bbv = *(const float2*)(nb + idx);
        float v0 = dd[m].x * rstd * gg.x + bbv.x;
        float v1 = dd[m].y * rstd * gg.y + bbv.y;
        __half2 hh = __floats2half2_rn(v0, v1);
        *(uint32_t*)(X + idx) = *(uint32_t*)&hh;
    }
}

// ================= GEMM: cp.async double-buffered fp16 mma.sync (1 W term) =================
#define BM 128
#define BN 128
#define BKK 32
#define NT (KDIM / BKK)   // 32
#define ASTR 40           // fp16 elems; 80B row stride
#define ARR_BYTES 10240
#define STAGE_BYTES (2 * ARR_BYTES)
#define GSMEM (2 * STAGE_BYTES)   // 40960

#define CP16(d, s) asm volatile("cp.async.cg.shared.global [%0], [%1], 16;" :: "r"(d), "l"(__cvta_generic_to_global(s)))
#define CP_COMMIT() asm volatile("cp.async.commit_group;" ::: "memory")
#define CP_WAIT1() asm volatile("cp.async.wait_group 1;" ::: "memory")
#define CP_WAIT0() asm volatile("cp.async.wait_group 0;" ::: "memory")

#define LDMX4(r0, r1, r2, r3, a) \
    asm volatile("ldmatrix.sync.aligned.m8n8.x4.shared.b16 {%0,%1,%2,%3}, [%4];" \
                 : "=r"(r0), "=r"(r1), "=r"(r2), "=r"(r3) : "r"(a))
#define LDMX2(r0, r1, a) \
    asm volatile("ldmatrix.sync.aligned.m8n8.x2.shared.b16 {%0,%1}, [%2];" \
                 : "=r"(r0), "=r"(r1) : "r"(a))
#define MMAF16(c, a, b) \
    asm volatile("mma.sync.aligned.m16n8k16.row.col.f32.f16.f16.f32 " \
                 "{%0,%1,%2,%3}, {%4,%5,%6,%7}, {%8,%9}, {%0,%1,%2,%3};" \
                 : "+f"((c)[0]), "+f"((c)[1]), "+f"((c)[2]), "+f"((c)[3]) \
                 : "r"((a)[0]), "r"((a)[1]), "r"((a)[2]), "r"((a)[3]), "r"((b)[0]), "r"((b)[1]))

__device__ __forceinline__ void gemm_load(uint32_t sbase, int m0, int n0, int kt, int tid) {
    int k0 = kt * BKK;
#pragma unroll
    for (int it = 0; it < 2; it++) {
        int id = tid + it * 256;          // 0..511
        int r = id >> 2, c = id & 3;
        uint32_t doff = (uint32_t)(r * 80 + c * 16);
        CP16(sbase + 0 * ARR_BYTES + doff, g_X16  + (size_t)(m0 + r) * KDIM + k0 + c * 8);
        CP16(sbase + 1 * ARR_BYTES + doff, g_Wh16 + (size_t)(n0 + r) * KDIM + k0 + c * 8);
    }
}

__global__ __launch_bounds__(256) void gemm_mma_kernel(const float* __restrict__ bias,
                                                       float* __restrict__ out) {
    uint32_t sb = smem_u32(dynsm);
    int tid = threadIdx.x;
    int wid = tid >> 5, lane = tid & 31;
    int wm = wid >> 2, wn = wid & 3;
    int n0 = blockIdx.x * BN;      // 4 N-blocks consecutive -> share M-stripe in L2
    int m0 = blockIdx.y * BM;

    float acc[4][4][4];
#pragma unroll
    for (int i = 0; i < 4; i++)
#pragma unroll
        for (int j = 0; j < 4; j++)
#pragma unroll
            for (int q = 0; q < 4; q++) acc[i][j][q] = 0.f;

    gemm_load(sb, m0, n0, 0, tid);
    CP_COMMIT();

    for (int kt = 0; kt < NT; kt++) {
        if (kt + 1 < NT) {
            gemm_load(sb + ((kt + 1) & 1) * STAGE_BYTES, m0, n0, kt + 1, tid);
            CP_COMMIT();
            CP_WAIT1();
        } else {
            CP_WAIT0();
        }
        __syncthreads();

        uint32_t base = sb + (kt & 1) * STAGE_BYTES;
        uint32_t uA = base;
        uint32_t uB = base + ARR_BYTES;

#pragma unroll
        for (int s = 0; s < 2; s++) {
            int kk = s * 16;
            uint32_t a[4][4], bh[4][2];
            int arow = wm * 64 + (lane & 15);
            int acol = kk + (lane >> 4) * 8;
#pragma unroll
            for (int i = 0; i < 4; i++) {
                uint32_t off = (uint32_t)((arow + i * 16) * ASTR + acol) * 2;
                LDMX4(a[i][0], a[i][1], a[i][2], a[i][3], uA + off);
            }
            int brow = wn * 32 + (lane & 7);
            int bcol = kk + ((lane >> 3) & 1) * 8;
#pragma unroll
            for (int j = 0; j < 4; j++) {
                uint32_t off = (uint32_t)((brow + j * 8) * ASTR + bcol) * 2;
                LDMX2(bh[j][0], bh[j][1], uB + off);
            }
#pragma unroll
            for (int i = 0; i < 4; i++)
#pragma unroll
                for (int j = 0; j < 4; j++)
                    MMAF16(acc[i][j], a[i], bh[j]);
        }
        __syncthreads();
    }

    int er = lane >> 2;
    int ec = (lane & 3) * 2;
#pragma unroll
    for (int i = 0; i < 4; i++) {
#pragma unroll
        for (int j = 0; j < 4; j++) {
            int m = m0 + wm * 64 + i * 16 + er;
            int n = n0 + wn * 32 + j * 8 + ec;
            float b0 = bias[n], b1 = bias[n + 1];
            float2 r0 = make_float2(acc[i][j][0] + b0, acc[i][j][1] + b1);
            float2 r1 = make_float2(acc[i][j][2] + b0, acc[i][j][3] + b1);
            *(float2*)(out + (size_t)m * OUTD + n) = r0;
            *(float2*)(out + (size_t)(m + 8) * OUTD + n) = r1;
        }
    }
}

// ---------------- launch ----------------
extern "C" void kernel_launch(void* const* d_in, const int* in_sizes, int n_in,
                              void* d_out, int out_size) {
    const float* pos    = (const float*)d_in[0];
    const float* feat   = (const float*)d_in[1];
    const int*   member = (const int*)d_in[2];
    const float* cmask  = (const float*)d_in[3];
    const float* lp     = (const float*)d_in[4];

    int pi = 5;
    if (pi < n_in && in_sizes[pi] == 1) pi++;
    const int* pe = (const int*)d_in[pi];

    int pt = pi + 1;
    while (pt < n_in && in_sizes[pt] != TABLE * 5) pt++;
    const float* pre    = (const float*)d_in[pt];
    const float* w1     = (const float*)d_in[pt + 1];
    const float* b1     = (const float*)d_in[pt + 2];
    const float* ln1_g  = (const float*)d_in[pt + 3];
    const float* ln1_b  = (const float*)d_in[pt + 4];
    const float* norm_g = (const float*)d_in[pt + 5];
    const float* norm_b = (const float*)d_in[pt + 6];
    const float* lin_w  = (const float*)d_in[pt + 7];
    const float* lin_b  = (const float*)d_in[pt + 8];

    float* out_pos = (float*)d_out;
    float* out_res = (float*)d_out + (size_t)BB * KEEP * 2;

    cudaFuncSetAttribute(prep_kernel, cudaFuncAttributeMaxDynamicSharedMemorySize, PREP_SMEM);
    cudaFuncSetAttribute(gemm_mma_kernel, cudaFuncAttributeMaxDynamicSharedMemorySize, GSMEM);

    prep_kernel<<<PREP_GRID, 1024, PREP_SMEM>>>(pos, lp, pre, w1, b1, ln1_g, ln1_b, lin_w, feat);
    token_kernel<<<MTOT / 2, 256>>>(pos, member, cmask, lp, pe, norm_g, norm_b, out_pos);
    dim3 ggrid(OUTD / BN, MTOT / BM);
    gemm_mma_kernel<<<ggrid, 256, GSMEM>>>(lin_b, out_res);
}

// round 10
// speedup vs baseline: 5.0999x; 1.1196x over previous
#include <cuda_runtime.h>
#include <cuda_bf16.h>
#include <cuda_fp16.h>
#include <math.h>
#include <cstdint>

#define BB 4
#define NN 12544
#define NBHD 48
#define DIM 256
#define OUTD 512
#define INNER 4
#define TABLE 4096
#define KEEP 3136
#define SAMP 2352
#define KDIM 1024
#define LNEPS 1e-5f
#define MTOT (BB * KEEP)   // 12544
#define CAND_CAP 3584
#define NBINS 8192
#define BIN_SCALE 1560.0f
#define BIN_OFF 5.25f

// ---------------- device scratch ----------------
__device__ float   g_wt[TABLE * INNER];
__device__ int     g_idx[BB * KEEP];
__device__ __half  g_feat16[(size_t)BB * NN * DIM];   // 25.7MB
__device__ __half  g_X16[(size_t)MTOT * KDIM];        // 25.7MB
__device__ __half  g_Wh16[(size_t)OUTD * KDIM];       // [n][k] fp16

__device__ __forceinline__ uint32_t smem_u32(const void* p) {
    uint32_t a;
    asm("{ .reg .u64 t; cvta.to.shared.u64 t, %1; cvt.u32.u64 %0, t; }" : "=r"(a) : "l"(p));
    return a;
}

// ================= PREP kernel =================
#define FEAT_BLKS 392
#define WCONV_BLKS 512
#define WT_BLKS 4
#define PREP_GRID (4 + FEAT_BLKS + WCONV_BLKS + WT_BLKS)
#define PREP_SMEM (NBINS * 4 * 2 + CAND_CAP * 8)

__device__ __forceinline__ float prob_of(const float* pos, const float* lp, int b, int i) {
    int px = (int)pos[((size_t)b * NN + i) * 2 + 0];
    int py = (int)pos[((size_t)b * NN + i) * 2 + 1];
    float fp = (((px & 1) == 0) && ((py & 1) == 0)) ? 1.f : 0.f;
    fp += lp[(size_t)b * NN + i] * 4.f;
    if (((px & 3) == 0) && ((py & 3) == 0)) fp -= 100.f;
    return fp;
}
__device__ __forceinline__ unsigned inv_of(float fp) {
    unsigned u = __float_as_uint(fp);
    u = (u & 0x80000000u) ? ~u : (u ^ 0x80000000u);
    return ~u;
}
__device__ __forceinline__ float fp_of_inv(unsigned inv) {
    unsigned enc = ~inv;
    unsigned u = (enc & 0x80000000u) ? (enc ^ 0x80000000u) : ~enc;
    return __uint_as_float(u);
}
__device__ __forceinline__ int bin_of_fp(float fp) {
    int bb = (int)((BIN_OFF - fp) * BIN_SCALE);
    return bb < 0 ? 0 : (bb > NBINS - 1 ? NBINS - 1 : bb);
}

extern __shared__ __align__(16) unsigned char dynsm[];

__global__ __launch_bounds__(1024) void prep_kernel(
    const float* __restrict__ pos, const float* __restrict__ lp,
    const float* __restrict__ pre, const float* __restrict__ w1,
    const float* __restrict__ b1, const float* __restrict__ ln1g,
    const float* __restrict__ ln1b, const float* __restrict__ lw,
    const float* __restrict__ feat) {
    int blk = blockIdx.x;
    int tid = threadIdx.x;

    if (blk < 4) {
        // ---------- selection: linear-bin histogram rank ----------
        int b = blk;
        unsigned* bins = (unsigned*)dynsm;
        unsigned* pref = (unsigned*)(dynsm + NBINS * 4);
        unsigned long long* cand = (unsigned long long*)(dynsm + NBINS * 8);
        __shared__ int s_wsum[32];
        __shared__ int s_T, s_total;

        for (int i = tid; i < NBINS; i += 1024) bins[i] = 0;
        if (tid == 0) s_T = NBINS - 1;
        __syncthreads();
        for (int i = tid; i < NN; i += 1024)
            atomicAdd(&bins[bin_of_fp(prob_of(pos, lp, b, i))], 1u);
        __syncthreads();

        int part = 0;
        unsigned mybin[8];
#pragma unroll
        for (int q = 0; q < 8; q++) { mybin[q] = bins[tid * 8 + q]; part += (int)mybin[q]; }
        int lane = tid & 31, wrp = tid >> 5;
        int v = part;
#pragma unroll
        for (int o = 1; o < 32; o <<= 1) { int nv = __shfl_up_sync(~0u, v, o); if (lane >= o) v += nv; }
        if (lane == 31) s_wsum[wrp] = v;
        __syncthreads();
        if (wrp == 0) {
            int w = s_wsum[lane];
#pragma unroll
            for (int o = 1; o < 32; o <<= 1) { int nv = __shfl_up_sync(~0u, w, o); if (lane >= o) w += nv; }
            s_wsum[lane] = w;
        }
        __syncthreads();
        int excl = v - part + (wrp > 0 ? s_wsum[wrp - 1] : 0);
        int cum = excl;
#pragma unroll
        for (int q = 0; q < 8; q++) {
            pref[tid * 8 + q] = (unsigned)cum;
            int cnt = (int)mybin[q];
            if (cum < SAMP && cum + cnt >= SAMP) s_T = tid * 8 + q;
            cum += cnt;
        }
        __syncthreads();
        int T = s_T;
        if (tid == 0) s_total = (int)pref[T] + (int)bins[T];
        __syncthreads();
        int total = s_total;
        if (total > CAND_CAP) total = CAND_CAP;

        for (int i = tid; i < NN; i += 1024) {
            float fp = prob_of(pos, lp, b, i);
            int bb = bin_of_fp(fp);
            if (bb <= T) {
                unsigned slot = atomicAdd(&pref[bb], 1u);
                if (slot < CAND_CAP)
                    cand[slot] = (((unsigned long long)inv_of(fp)) << 32) | (unsigned)i;
            }
        }
        __syncthreads();

        for (int s = tid; s < total; s += 1024) {
            unsigned long long key = cand[s];
            int bb = bin_of_fp(fp_of_inv((unsigned)(key >> 32)));
            int end = (int)pref[bb]; if (end > total) end = total;
            int start = end - (int)bins[bb]; if (start < 0) start = 0;
            int r = start;
            for (int j = start; j < end; j++)
                if (cand[j] < key) r++;
            if (r < SAMP) g_idx[b * KEEP + r] = (int)(key & 0xFFFFFFFFull);
        }
        for (int t = SAMP + tid; t < KEEP; t += 1024) {
            int r = t - SAMP;
            g_idx[b * KEEP + t] = ((r / 28) * 4) * 112 + (r % 28) * 4;
        }
        return;
    }
    blk -= 4;

    if (blk < FEAT_BLKS) {
        // ---------- feat fp32 -> fp16 : 8 consecutive float4 per thread ----------
        size_t base = ((size_t)blk * 1024 + tid) * 8;   // float4 index
#pragma unroll
        for (int it = 0; it < 8; it += 2) {
            float4 f0 = ((const float4*)feat)[base + it + 0];
            float4 f1 = ((const float4*)feat)[base + it + 1];
            uint4 o;
            __half2 h;
            h = __floats2half2_rn(f0.x, f0.y); o.x = *(uint32_t*)&h;
            h = __floats2half2_rn(f0.z, f0.w); o.y = *(uint32_t*)&h;
            h = __floats2half2_rn(f1.x, f1.y); o.z = *(uint32_t*)&h;
            h = __floats2half2_rn(f1.z, f1.w); o.w = *(uint32_t*)&h;
            ((uint4*)g_feat16)[(base + it) / 2] = o;
        }
        return;
    }
    blk -= FEAT_BLKS;

    if (blk < WCONV_BLKS) {
        // ---------- W transpose -> fp16 ----------
        __shared__ float tile[32][33];
        int tk = blk >> 4, tn = blk & 15;
        int k0 = tk * 32, n0 = tn * 32;
        int tx = tid & 31, ty = tid >> 5;
        tile[ty][tx] = lw[(size_t)(k0 + ty) * OUTD + n0 + tx];
        __syncthreads();
        int n = n0 + ty, k = k0 + tx;
        g_Wh16[(size_t)n * KDIM + k] = __float2half_rn(tile[tx][ty]);
        return;
    }
    blk -= WCONV_BLKS;

    // ---------- weight_net table ----------
    int r = blk * 1024 + tid;
    if (r < TABLE) {
        float p[5];
#pragma unroll
        for (int k = 0; k < 5; k++) p[k] = pre[r * 5 + k];
        float h[4];
#pragma unroll
        for (int m = 0; m < 4; m++) {
            float s = b1[m];
#pragma unroll
            for (int k = 0; k < 5; k++) s += p[k] * w1[k * 4 + m];
            h[m] = s;
        }
        float mean = 0.25f * (h[0] + h[1] + h[2] + h[3]);
        float vv = 0.f;
#pragma unroll
        for (int m = 0; m < 4; m++) { float d = h[m] - mean; vv += d * d; }
        float rstd = rsqrtf(vv * 0.25f + LNEPS);
#pragma unroll
        for (int m = 0; m < 4; m++) {
            float x = (h[m] - mean) * rstd * ln1g[m] + ln1b[m];
            g_wt[r * 4 + m] = 0.5f * x * (1.f + erff(x * 0.70710678118654752440f));
        }
    }
}

// ================= token kernel: 2 tokens per 128-thr block, 4 ch/thread =================
__global__ __launch_bounds__(128) void token_kernel(
    const float* __restrict__ pos, const int* __restrict__ member,
    const float* __restrict__ cmask, const float* __restrict__ lp,
    const int* __restrict__ pe, const float* __restrict__ ng,
    const float* __restrict__ nb, float* __restrict__ out_pos) {
    int tid = threadIdx.x;
    int half = tid >> 6;         // 0/1: token within block
    int qtid = tid & 63;         // owns channels [qtid*4, qtid*4+4)
    int t = blockIdx.x * 2 + half;
    int b = t / KEEP;

    __shared__ int    s_mem[2][NBHD];
    __shared__ float4 s_w4[2][NBHD];
    __shared__ float  red[4];
    __shared__ int    s_src[2];

    if (qtid == 0) s_src[half] = g_idx[t];
    __syncthreads();
    int src = s_src[half];

    if (qtid < 2) out_pos[(size_t)t * 2 + qtid] = pos[((size_t)b * NN + src) * 2 + qtid];

    if (qtid < NBHD) {
        size_t eoff = ((size_t)b * NN + src) * NBHD + qtid;
        int mm = member[eoff];
        int pp = pe[eoff];
        float sc = lp[(size_t)b * NN + mm] * cmask[eoff];
        s_mem[half][qtid] = mm;
        float4 w;
        w.x = g_wt[pp * 4 + 0] * sc;
        w.y = g_wt[pp * 4 + 1] * sc;
        w.z = g_wt[pp * 4 + 2] * sc;
        w.w = g_wt[pp * 4 + 3] * sc;
        s_w4[half][qtid] = w;
    }
    __syncthreads();

    const uint2* fb2 = (const uint2*)(g_feat16 + (size_t)b * NN * DIM);
    float a[4][4];
#pragma unroll
    for (int m = 0; m < 4; m++)
#pragma unroll
        for (int c = 0; c < 4; c++) a[m][c] = 0.f;

#pragma unroll 4
    for (int j = 0; j < NBHD; j++) {
        int mm = s_mem[half][j];
        float4 w = s_w4[half][j];
        uint2 fv = fb2[(size_t)mm * 64 + qtid];
        float2 f01 = __half22float2(*(__half2*)&fv.x);
        float2 f23 = __half22float2(*(__half2*)&fv.y);
        float f[4] = {f01.x, f01.y, f23.x, f23.y};
        float wm[4] = {w.x, w.y, w.z, w.w};
#pragma unroll
        for (int m = 0; m < 4; m++)
#pragma unroll
            for (int c = 0; c < 4; c++) a[m][c] += wm[m] * f[c];
    }

    // LayerNorm over 1024 values (16 per thread, 64 threads = 2 warps per token)
    float s = 0.f;
#pragma unroll
    for (int m = 0; m < 4; m++)
#pragma unroll
        for (int c = 0; c < 4; c++) s += a[m][c];
#pragma unroll
    for (int o = 16; o > 0; o >>= 1) s += __shfl_down_sync(0xffffffffu, s, o);
    if ((tid & 31) == 0) red[tid >> 5] = s;
    __syncthreads();
    float mean = (red[half * 2 + 0] + red[half * 2 + 1]) * (1.f / 1024.f);
    __syncthreads();

    float vs = 0.f;
#pragma unroll
    for (int m = 0; m < 4; m++)
#pragma unroll
        for (int c = 0; c < 4; c++) { float d = a[m][c] - mean; vs += d * d; }
#pragma unroll
    for (int o = 16; o > 0; o >>= 1) vs += __shfl_down_sync(0xffffffffu, vs, o);
    if ((tid & 31) == 0) red[tid >> 5] = vs;
    __syncthreads();
    float rstd = rsqrtf((red[half * 2 + 0] + red[half * 2 + 1]) * (1.f / 1024.f) + LNEPS);

    __half* X = g_X16 + (size_t)t * KDIM;
#pragma unroll
    for (int m = 0; m < 4; m++) {
        int idx = m * 256 + qtid * 4;
        float4 gg = *(const float4*)(ng + idx);
        float4 bbv = *(const float4*)(nb + idx);
        float v0 = (a[m][0] - mean) * rstd * gg.x + bbv.x;
        float v1 = (a[m][1] - mean) * rstd * gg.y + bbv.y;
        float v2 = (a[m][2] - mean) * rstd * gg.z + bbv.z;
        float v3 = (a[m][3] - mean) * rstd * gg.w + bbv.w;
        __half2 h0 = __floats2half2_rn(v0, v1);
        __half2 h1 = __floats2half2_rn(v2, v3);
        uint2 o;
        o.x = *(uint32_t*)&h0;
        o.y = *(uint32_t*)&h1;
        *(uint2*)(X + idx) = o;
    }
}

// ================= GEMM: 3-stage cp.async fp16 mma.sync =================
#define BM 128
#define BN 128
#define BKK 32
#define NT (KDIM / BKK)   // 32
#define ASTR 40           // fp16 elems; 80B row stride
#define ARR_BYTES 10240
#define STAGE_BYTES (2 * ARR_BYTES)
#define NSTAGE 3
#define GSMEM (NSTAGE * STAGE_BYTES)   // 61440

#define CP16(d, s) asm volatile("cp.async.cg.shared.global [%0], [%1], 16;" :: "r"(d), "l"(__cvta_generic_to_global(s)))
#define CP_COMMIT() asm volatile("cp.async.commit_group;" ::: "memory")
#define CP_WAIT2() asm volatile("cp.async.wait_group 2;" ::: "memory")
#define CP_WAIT1() asm volatile("cp.async.wait_group 1;" ::: "memory")
#define CP_WAIT0() asm volatile("cp.async.wait_group 0;" ::: "memory")

#define LDMX4(r0, r1, r2, r3, a) \
    asm volatile("ldmatrix.sync.aligned.m8n8.x4.shared.b16 {%0,%1,%2,%3}, [%4];" \
                 : "=r"(r0), "=r"(r1), "=r"(r2), "=r"(r3) : "r"(a))
#define LDMX2(r0, r1, a) \
    asm volatile("ldmatrix.sync.aligned.m8n8.x2.shared.b16 {%0,%1}, [%2];" \
                 : "=r"(r0), "=r"(r1) : "r"(a))
#define MMAF16(c, a, b) \
    asm volatile("mma.sync.aligned.m16n8k16.row.col.f32.f16.f16.f32 " \
                 "{%0,%1,%2,%3}, {%4,%5,%6,%7}, {%8,%9}, {%0,%1,%2,%3};" \
                 : "+f"((c)[0]), "+f"((c)[1]), "+f"((c)[2]), "+f"((c)[3]) \
                 : "r"((a)[0]), "r"((a)[1]), "r"((a)[2]), "r"((a)[3]), "r"((b)[0]), "r"((b)[1]))

__device__ __forceinline__ void gemm_load(uint32_t sbase, int m0, int n0, int kt, int tid) {
    int k0 = kt * BKK;
#pragma unroll
    for (int it = 0; it < 2; it++) {
        int id = tid + it * 256;          // 0..511
        int r = id >> 2, c = id & 3;
        uint32_t doff = (uint32_t)(r * 80 + c * 16);
        CP16(sbase + 0 * ARR_BYTES + doff, g_X16  + (size_t)(m0 + r) * KDIM + k0 + c * 8);
        CP16(sbase + 1 * ARR_BYTES + doff, g_Wh16 + (size_t)(n0 + r) * KDIM + k0 + c * 8);
    }
}

__global__ __launch_bounds__(256) void gemm_mma_kernel(const float* __restrict__ bias,
                                                       float* __restrict__ out) {
    uint32_t sb = smem_u32(dynsm);
    int tid = threadIdx.x;
    int wid = tid >> 5, lane = tid & 31;
    int wm = wid >> 2, wn = wid & 3;
    int n0 = blockIdx.x * BN;
    int m0 = blockIdx.y * BM;

    float acc[4][4][4];
#pragma unroll
    for (int i = 0; i < 4; i++)
#pragma unroll
        for (int j = 0; j < 4; j++)
#pragma unroll
            for (int q = 0; q < 4; q++) acc[i][j][q] = 0.f;

    gemm_load(sb + 0 * STAGE_BYTES, m0, n0, 0, tid);
    CP_COMMIT();
    gemm_load(sb + 1 * STAGE_BYTES, m0, n0, 1, tid);
    CP_COMMIT();

    int slot = 0;
    for (int kt = 0; kt < NT; kt++) {
        if (kt + 2 < NT) {
            int ns = (slot + 2) % NSTAGE;
            gemm_load(sb + ns * STAGE_BYTES, m0, n0, kt + 2, tid);
            CP_COMMIT();
            CP_WAIT2();
        } else if (kt + 1 < NT) {
            CP_WAIT1();
        } else {
            CP_WAIT0();
        }
        __syncthreads();

        uint32_t base = sb + slot * STAGE_BYTES;
        uint32_t uA = base;
        uint32_t uB = base + ARR_BYTES;

#pragma unroll
        for (int s = 0; s < 2; s++) {
            int kk = s * 16;
            uint32_t a[4][4], bh[4][2];
            int arow = wm * 64 + (lane & 15);
            int acol = kk + (lane >> 4) * 8;
#pragma unroll
            for (int i = 0; i < 4; i++) {
                uint32_t off = (uint32_t)((arow + i * 16) * ASTR + acol) * 2;
                LDMX4(a[i][0], a[i][1], a[i][2], a[i][3], uA + off);
            }
            int brow = wn * 32 + (lane & 7);
            int bcol = kk + ((lane >> 3) & 1) * 8;
#pragma unroll
            for (int j = 0; j < 4; j++) {
                uint32_t off = (uint32_t)((brow + j * 8) * ASTR + bcol) * 2;
                LDMX2(bh[j][0], bh[j][1], uB + off);
            }
#pragma unroll
            for (int i = 0; i < 4; i++)
#pragma unroll
                for (int j = 0; j < 4; j++)
                    MMAF16(acc[i][j], a[i], bh[j]);
        }
        __syncthreads();
        slot = (slot + 1) % NSTAGE;
    }

    int er = lane >> 2;
    int ec = (lane & 3) * 2;
#pragma unroll
    for (int i = 0; i < 4; i++) {
#pragma unroll
        for (int j = 0; j < 4; j++) {
            int m = m0 + wm * 64 + i * 16 + er;
            int n = n0 + wn * 32 + j * 8 + ec;
            float b0 = bias[n], b1 = bias[n + 1];
            float2 r0 = make_float2(acc[i][j][0] + b0, acc[i][j][1] + b1);
            float2 r1 = make_float2(acc[i][j][2] + b0, acc[i][j][3] + b1);
            *(float2*)(out + (size_t)m * OUTD + n) = r0;
            *(float2*)(out + (size_t)(m + 8) * OUTD + n) = r1;
        }
    }
}

// ---------------- launch ----------------
extern "C" void kernel_launch(void* const* d_in, const int* in_sizes, int n_in,
                              void* d_out, int out_size) {
    const float* pos    = (const float*)d_in[0];
    const float* feat   = (const float*)d_in[1];
    const int*   member = (const int*)d_in[2];
    const float* cmask  = (const float*)d_in[3];
    const float* lp     = (const float*)d_in[4];

    int pi = 5;
    if (pi < n_in && in_sizes[pi] == 1) pi++;
    const int* pe = (const int*)d_in[pi];

    int pt = pi + 1;
    while (pt < n_in && in_sizes[pt] != TABLE * 5) pt++;
    const float* pre    = (const float*)d_in[pt];
    const float* w1     = (const float*)d_in[pt + 1];
    const float* b1     = (const float*)d_in[pt + 2];
    const float* ln1_g  = (const float*)d_in[pt + 3];
    const float* ln1_b  = (const float*)d_in[pt + 4];
    const float* norm_g = (const float*)d_in[pt + 5];
    const float* norm_b = (const float*)d_in[pt + 6];
    const float* lin_w  = (const float*)d_in[pt + 7];
    const float* lin_b  = (const float*)d_in[pt + 8];

    float* out_pos = (float*)d_out;
    float* out_res = (float*)d_out + (size_t)BB * KEEP * 2;

    cudaFuncSetAttribute(prep_kernel, cudaFuncAttributeMaxDynamicSharedMemorySize, PREP_SMEM);
    cudaFuncSetAttribute(gemm_mma_kernel, cudaFuncAttributeMaxDynamicSharedMemorySize, GSMEM);

    prep_kernel<<<PREP_GRID, 1024, PREP_SMEM>>>(pos, lp, pre, w1, b1, ln1_g, ln1_b, lin_w, feat);
    token_kernel<<<MTOT / 2, 128>>>(pos, member, cmask, lp, pe, norm_g, norm_b, out_pos);
    dim3 ggrid(OUTD / BN, MTOT / BM);
    gemm_mma_kernel<<<ggrid, 256, GSMEM>>>(lin_b, out_res);
}

// round 11
// speedup vs baseline: 5.3319x; 1.0455x over previous
#include <cuda_runtime.h>
#include <cuda_bf16.h>
#include <cuda_fp16.h>
#include <math.h>
#include <cstdint>

#define BB 4
#define NN 12544
#define NBHD 48
#define DIM 256
#define OUTD 512
#define INNER 4
#define TABLE 4096
#define KEEP 3136
#define SAMP 2352
#define KDIM 1024
#define LNEPS 1e-5f
#define MTOT (BB * KEEP)   // 12544
#define CAND_CAP 3584
#define NBINS 8192
#define BIN_SCALE 1560.0f
#define BIN_OFF 5.25f

// ---------------- device scratch ----------------
__device__ float   g_wt[TABLE * INNER];
__device__ int     g_idx[BB * KEEP];
__device__ __half  g_feat16[(size_t)BB * NN * DIM];   // 25.7MB
__device__ __half  g_X16[(size_t)MTOT * KDIM];        // 25.7MB
__device__ __half  g_Wh16[(size_t)OUTD * KDIM];       // [n][k] fp16

__device__ __forceinline__ uint32_t smem_u32(const void* p) {
    uint32_t a;
    asm("{ .reg .u64 t; cvta.to.shared.u64 t, %1; cvt.u32.u64 %0, t; }" : "=r"(a) : "l"(p));
    return a;
}

// ================= PREP kernel =================
#define FEAT_BLKS 784
#define WCONV_BLKS 512
#define WT_BLKS 4
#define PREP_GRID (4 + FEAT_BLKS + WCONV_BLKS + WT_BLKS)
#define PREP_SMEM (NBINS * 4 * 2 + CAND_CAP * 8)

__device__ __forceinline__ float prob_of(const float* pos, const float* lp, int b, int i) {
    int px = (int)pos[((size_t)b * NN + i) * 2 + 0];
    int py = (int)pos[((size_t)b * NN + i) * 2 + 1];
    float fp = (((px & 1) == 0) && ((py & 1) == 0)) ? 1.f : 0.f;
    fp += lp[(size_t)b * NN + i] * 4.f;
    if (((px & 3) == 0) && ((py & 3) == 0)) fp -= 100.f;
    return fp;
}
__device__ __forceinline__ unsigned inv_of(float fp) {
    unsigned u = __float_as_uint(fp);
    u = (u & 0x80000000u) ? ~u : (u ^ 0x80000000u);
    return ~u;
}
__device__ __forceinline__ float fp_of_inv(unsigned inv) {
    unsigned enc = ~inv;
    unsigned u = (enc & 0x80000000u) ? (enc ^ 0x80000000u) : ~enc;
    return __uint_as_float(u);
}
__device__ __forceinline__ int bin_of_fp(float fp) {
    int bb = (int)((BIN_OFF - fp) * BIN_SCALE);
    return bb < 0 ? 0 : (bb > NBINS - 1 ? NBINS - 1 : bb);
}

extern __shared__ __align__(16) unsigned char dynsm[];

__global__ __launch_bounds__(1024) void prep_kernel(
    const float* __restrict__ pos, const float* __restrict__ lp,
    const float* __restrict__ pre, const float* __restrict__ w1,
    const float* __restrict__ b1, const float* __restrict__ ln1g,
    const float* __restrict__ ln1b, const float* __restrict__ lw,
    const float* __restrict__ feat) {
    int blk = blockIdx.x;
    int tid = threadIdx.x;

    if (blk < 4) {
        // ---------- selection: linear-bin histogram rank ----------
        int b = blk;
        unsigned* bins = (unsigned*)dynsm;
        unsigned* pref = (unsigned*)(dynsm + NBINS * 4);
        unsigned long long* cand = (unsigned long long*)(dynsm + NBINS * 8);
        __shared__ int s_wsum[32];
        __shared__ int s_T, s_total;

        for (int i = tid; i < NBINS; i += 1024) bins[i] = 0;
        if (tid == 0) s_T = NBINS - 1;
        __syncthreads();
        for (int i = tid; i < NN; i += 1024)
            atomicAdd(&bins[bin_of_fp(prob_of(pos, lp, b, i))], 1u);
        __syncthreads();

        int part = 0;
        unsigned mybin[8];
#pragma unroll
        for (int q = 0; q < 8; q++) { mybin[q] = bins[tid * 8 + q]; part += (int)mybin[q]; }
        int lane = tid & 31, wrp = tid >> 5;
        int v = part;
#pragma unroll
        for (int o = 1; o < 32; o <<= 1) { int nv = __shfl_up_sync(~0u, v, o); if (lane >= o) v += nv; }
        if (lane == 31) s_wsum[wrp] = v;
        __syncthreads();
        if (wrp == 0) {
            int w = s_wsum[lane];
#pragma unroll
            for (int o = 1; o < 32; o <<= 1) { int nv = __shfl_up_sync(~0u, w, o); if (lane >= o) w += nv; }
            s_wsum[lane] = w;
        }
        __syncthreads();
        int excl = v - part + (wrp > 0 ? s_wsum[wrp - 1] : 0);
        int cum = excl;
#pragma unroll
        for (int q = 0; q < 8; q++) {
            pref[tid * 8 + q] = (unsigned)cum;
            int cnt = (int)mybin[q];
            if (cum < SAMP && cum + cnt >= SAMP) s_T = tid * 8 + q;
            cum += cnt;
        }
        __syncthreads();
        int T = s_T;
        if (tid == 0) s_total = (int)pref[T] + (int)bins[T];
        __syncthreads();
        int total = s_total;
        if (total > CAND_CAP) total = CAND_CAP;

        for (int i = tid; i < NN; i += 1024) {
            float fp = prob_of(pos, lp, b, i);
            int bb = bin_of_fp(fp);
            if (bb <= T) {
                unsigned slot = atomicAdd(&pref[bb], 1u);
                if (slot < CAND_CAP)
                    cand[slot] = (((unsigned long long)inv_of(fp)) << 32) | (unsigned)i;
            }
        }
        __syncthreads();

        for (int s = tid; s < total; s += 1024) {
            unsigned long long key = cand[s];
            int bb = bin_of_fp(fp_of_inv((unsigned)(key >> 32)));
            int end = (int)pref[bb]; if (end > total) end = total;
            int start = end - (int)bins[bb]; if (start < 0) start = 0;
            int r = start;
            for (int j = start; j < end; j++)
                if (cand[j] < key) r++;
            if (r < SAMP) g_idx[b * KEEP + r] = (int)(key & 0xFFFFFFFFull);
        }
        for (int t = SAMP + tid; t < KEEP; t += 1024) {
            int r = t - SAMP;
            g_idx[b * KEEP + t] = ((r / 28) * 4) * 112 + (r % 28) * 4;
        }
        return;
    }
    blk -= 4;

    if (blk < FEAT_BLKS) {
        // ---------- feat fp32 -> fp16 : 4 consecutive float4 per thread (R9 shape) ----------
        size_t base = ((size_t)blk * 1024 + tid) * 4;   // float4 index
        float4 f0 = ((const float4*)feat)[base + 0];
        float4 f1 = ((const float4*)feat)[base + 1];
        float4 f2 = ((const float4*)feat)[base + 2];
        float4 f3 = ((const float4*)feat)[base + 3];
        uint4 o0, o1;
        __half2 h;
        h = __floats2half2_rn(f0.x, f0.y); o0.x = *(uint32_t*)&h;
        h = __floats2half2_rn(f0.z, f0.w); o0.y = *(uint32_t*)&h;
        h = __floats2half2_rn(f1.x, f1.y); o0.z = *(uint32_t*)&h;
        h = __floats2half2_rn(f1.z, f1.w); o0.w = *(uint32_t*)&h;
        h = __floats2half2_rn(f2.x, f2.y); o1.x = *(uint32_t*)&h;
        h = __floats2half2_rn(f2.z, f2.w); o1.y = *(uint32_t*)&h;
        h = __floats2half2_rn(f3.x, f3.y); o1.z = *(uint32_t*)&h;
        h = __floats2half2_rn(f3.z, f3.w); o1.w = *(uint32_t*)&h;
        ((uint4*)g_feat16)[base / 2 + 0] = o0;
        ((uint4*)g_feat16)[base / 2 + 1] = o1;
        return;
    }
    blk -= FEAT_BLKS;

    if (blk < WCONV_BLKS) {
        // ---------- W transpose -> fp16 ----------
        __shared__ float tile[32][33];
        int tk = blk >> 4, tn = blk & 15;
        int k0 = tk * 32, n0 = tn * 32;
        int tx = tid & 31, ty = tid >> 5;
        tile[ty][tx] = lw[(size_t)(k0 + ty) * OUTD + n0 + tx];
        __syncthreads();
        int n = n0 + ty, k = k0 + tx;
        g_Wh16[(size_t)n * KDIM + k] = __float2half_rn(tile[tx][ty]);
        return;
    }
    blk -= WCONV_BLKS;

    // ---------- weight_net table ----------
    int r = blk * 1024 + tid;
    if (r < TABLE) {
        float p[5];
#pragma unroll
        for (int k = 0; k < 5; k++) p[k] = pre[r * 5 + k];
        float h[4];
#pragma unroll
        for (int m = 0; m < 4; m++) {
            float s = b1[m];
#pragma unroll
            for (int k = 0; k < 5; k++) s += p[k] * w1[k * 4 + m];
            h[m] = s;
        }
        float mean = 0.25f * (h[0] + h[1] + h[2] + h[3]);
        float vv = 0.f;
#pragma unroll
        for (int m = 0; m < 4; m++) { float d = h[m] - mean; vv += d * d; }
        float rstd = rsqrtf(vv * 0.25f + LNEPS);
#pragma unroll
        for (int m = 0; m < 4; m++) {
            float x = (h[m] - mean) * rstd * ln1g[m] + ln1b[m];
            g_wt[r * 4 + m] = 0.5f * x * (1.f + erff(x * 0.70710678118654752440f));
        }
    }
}

// ================= token kernel: 2 tokens per 128-thr block, 4 ch/thread =================
__global__ __launch_bounds__(128) void token_kernel(
    const float* __restrict__ pos, const int* __restrict__ member,
    const float* __restrict__ cmask, const float* __restrict__ lp,
    const int* __restrict__ pe, const float* __restrict__ ng,
    const float* __restrict__ nb, float* __restrict__ out_pos) {
    int tid = threadIdx.x;
    int half = tid >> 6;
    int qtid = tid & 63;
    int t = blockIdx.x * 2 + half;
    int b = t / KEEP;

    __shared__ int    s_mem[2][NBHD];
    __shared__ float4 s_w4[2][NBHD];
    __shared__ float  red[4];
    __shared__ int    s_src[2];

    if (qtid == 0) s_src[half] = g_idx[t];
    __syncthreads();
    int src = s_src[half];

    if (qtid < 2) out_pos[(size_t)t * 2 + qtid] = pos[((size_t)b * NN + src) * 2 + qtid];

    if (qtid < NBHD) {
        size_t eoff = ((size_t)b * NN + src) * NBHD + qtid;
        int mm = member[eoff];
        int pp = pe[eoff];
        float sc = lp[(size_t)b * NN + mm] * cmask[eoff];
        s_mem[half][qtid] = mm;
        float4 w;
        w.x = g_wt[pp * 4 + 0] * sc;
        w.y = g_wt[pp * 4 + 1] * sc;
        w.z = g_wt[pp * 4 + 2] * sc;
        w.w = g_wt[pp * 4 + 3] * sc;
        s_w4[half][qtid] = w;
    }
    __syncthreads();

    const uint2* fb2 = (const uint2*)(g_feat16 + (size_t)b * NN * DIM);
    float a[4][4];
#pragma unroll
    for (int m = 0; m < 4; m++)
#pragma unroll
        for (int c = 0; c < 4; c++) a[m][c] = 0.f;

#pragma unroll 4
    for (int j = 0; j < NBHD; j++) {
        int mm = s_mem[half][j];
        float4 w = s_w4[half][j];
        uint2 fv = fb2[(size_t)mm * 64 + qtid];
        float2 f01 = __half22float2(*(__half2*)&fv.x);
        float2 f23 = __half22float2(*(__half2*)&fv.y);
        float f[4] = {f01.x, f01.y, f23.x, f23.y};
        float wm[4] = {w.x, w.y, w.z, w.w};
#pragma unroll
        for (int m = 0; m < 4; m++)
#pragma unroll
            for (int c = 0; c < 4; c++) a[m][c] += wm[m] * f[c];
    }

    float s = 0.f;
#pragma unroll
    for (int m = 0; m < 4; m++)
#pragma unroll
        for (int c = 0; c < 4; c++) s += a[m][c];
#pragma unroll
    for (int o = 16; o > 0; o >>= 1) s += __shfl_down_sync(0xffffffffu, s, o);
    if ((tid & 31) == 0) red[tid >> 5] = s;
    __syncthreads();
    float mean = (red[half * 2 + 0] + red[half * 2 + 1]) * (1.f / 1024.f);
    __syncthreads();

    float vs = 0.f;
#pragma unroll
    for (int m = 0; m < 4; m++)
#pragma unroll
        for (int c = 0; c < 4; c++) { float d = a[m][c] - mean; vs += d * d; }
#pragma unroll
    for (int o = 16; o > 0; o >>= 1) vs += __shfl_down_sync(0xffffffffu, vs, o);
    if ((tid & 31) == 0) red[tid >> 5] = vs;
    __syncthreads();
    float rstd = rsqrtf((red[half * 2 + 0] + red[half * 2 + 1]) * (1.f / 1024.f) + LNEPS);

    __half* X = g_X16 + (size_t)t * KDIM;
#pragma unroll
    for (int m = 0; m < 4; m++) {
        int idx = m * 256 + qtid * 4;
        float4 gg = *(const float4*)(ng + idx);
        float4 bbv = *(const float4*)(nb + idx);
        float v0 = (a[m][0] - mean) * rstd * gg.x + bbv.x;
        float v1 = (a[m][1] - mean) * rstd * gg.y + bbv.y;
        float v2 = (a[m][2] - mean) * rstd * gg.z + bbv.z;
        float v3 = (a[m][3] - mean) * rstd * gg.w + bbv.w;
        __half2 h0 = __floats2half2_rn(v0, v1);
        __half2 h1 = __floats2half2_rn(v2, v3);
        uint2 o;
        o.x = *(uint32_t*)&h0;
        o.y = *(uint32_t*)&h1;
        *(uint2*)(X + idx) = o;
    }
}

// ================= GEMM: 4-stage cp.async fp16 mma.sync =================
#define BM 128
#define BN 128
#define BKK 32
#define NT (KDIM / BKK)   // 32
#define ASTR 40           // fp16 elems; 80B row stride
#define ARR_BYTES 10240
#define STAGE_BYTES (2 * ARR_BYTES)
#define NSTAGE 4
#define GSMEM (NSTAGE * STAGE_BYTES)   // 81920

#define CP16(d, s) asm volatile("cp.async.cg.shared.global [%0], [%1], 16;" :: "r"(d), "l"(__cvta_generic_to_global(s)))
#define CP_COMMIT() asm volatile("cp.async.commit_group;" ::: "memory")
#define CP_WAIT3() asm volatile("cp.async.wait_group 3;" ::: "memory")
#define CP_WAIT2() asm volatile("cp.async.wait_group 2;" ::: "memory")
#define CP_WAIT1() asm volatile("cp.async.wait_group 1;" ::: "memory")
#define CP_WAIT0() asm volatile("cp.async.wait_group 0;" ::: "memory")

#define LDMX4(r0, r1, r2, r3, a) \
    asm volatile("ldmatrix.sync.aligned.m8n8.x4.shared.b16 {%0,%1,%2,%3}, [%4];" \
                 : "=r"(r0), "=r"(r1), "=r"(r2), "=r"(r3) : "r"(a))
#define LDMX2(r0, r1, a) \
    asm volatile("ldmatrix.sync.aligned.m8n8.x2.shared.b16 {%0,%1}, [%2];" \
                 : "=r"(r0), "=r"(r1) : "r"(a))
#define MMAF16(c, a, b) \
    asm volatile("mma.sync.aligned.m16n8k16.row.col.f32.f16.f16.f32 " \
                 "{%0,%1,%2,%3}, {%4,%5,%6,%7}, {%8,%9}, {%0,%1,%2,%3};" \
                 : "+f"((c)[0]), "+f"((c)[1]), "+f"((c)[2]), "+f"((c)[3]) \
                 : "r"((a)[0]), "r"((a)[1]), "r"((a)[2]), "r"((a)[3]), "r"((b)[0]), "r"((b)[1]))

__device__ __forceinline__ void gemm_load(uint32_t sbase, int m0, int n0, int kt, int tid) {
    int k0 = kt * BKK;
#pragma unroll
    for (int it = 0; it < 2; it++) {
        int id = tid + it * 256;          // 0..511
        int r = id >> 2, c = id & 3;
        uint32_t doff = (uint32_t)(r * 80 + c * 16);
        CP16(sbase + 0 * ARR_BYTES + doff, g_X16  + (size_t)(m0 + r) * KDIM + k0 + c * 8);
        CP16(sbase + 1 * ARR_BYTES + doff, g_Wh16 + (size_t)(n0 + r) * KDIM + k0 + c * 8);
    }
}

__global__ __launch_bounds__(256) void gemm_mma_kernel(const float* __restrict__ bias,
                                                       float* __restrict__ out) {
    uint32_t sb = smem_u32(dynsm);
    int tid = threadIdx.x;
    int wid = tid >> 5, lane = tid & 31;
    int wm = wid >> 2, wn = wid & 3;
    int n0 = blockIdx.x * BN;
    int m0 = blockIdx.y * BM;

    float acc[4][4][4];
#pragma unroll
    for (int i = 0; i < 4; i++)
#pragma unroll
        for (int j = 0; j < 4; j++)
#pragma unroll
            for (int q = 0; q < 4; q++) acc[i][j][q] = 0.f;

    gemm_load(sb + 0 * STAGE_BYTES, m0, n0, 0, tid);
    CP_COMMIT();
    gemm_load(sb + 1 * STAGE_BYTES, m0, n0, 1, tid);
    CP_COMMIT();
    gemm_load(sb + 2 * STAGE_BYTES, m0, n0, 2, tid);
    CP_COMMIT();

    int slot = 0;
    for (int kt = 0; kt < NT; kt++) {
        if (kt + 3 < NT) {
            int ns = (slot + 3) % NSTAGE;
            gemm_load(sb + ns * STAGE_BYTES, m0, n0, kt + 3, tid);
            CP_COMMIT();
            CP_WAIT3();
        } else if (kt + 2 < NT) {
            CP_WAIT2();
        } else if (kt + 1 < NT) {
            CP_WAIT1();
        } else {
            CP_WAIT0();
        }
        __syncthreads();

        uint32_t base = sb + slot * STAGE_BYTES;
        uint32_t uA = base;
        uint32_t uB = base + ARR_BYTES;

#pragma unroll
        for (int s = 0; s < 2; s++) {
            int kk = s * 16;
            uint32_t a[4][4], bh[4][2];
            int arow = wm * 64 + (lane & 15);
            int acol = kk + (lane >> 4) * 8;
#pragma unroll
            for (int i = 0; i < 4; i++) {
                uint32_t off = (uint32_t)((arow + i * 16) * ASTR + acol) * 2;
                LDMX4(a[i][0], a[i][1], a[i][2], a[i][3], uA + off);
            }
            int brow = wn * 32 + (lane & 7);
            int bcol = kk + ((lane >> 3) & 1) * 8;
#pragma unroll
            for (int j = 0; j < 4; j++) {
                uint32_t off = (uint32_t)((brow + j * 8) * ASTR + bcol) * 2;
                LDMX2(bh[j][0], bh[j][1], uB + off);
            }
#pragma unroll
            for (int i = 0; i < 4; i++)
#pragma unroll
                for (int j = 0; j < 4; j++)
                    MMAF16(acc[i][j], a[i], bh[j]);
        }
        __syncthreads();
        slot = (slot + 1) % NSTAGE;
    }

    int er = lane >> 2;
    int ec = (lane & 3) * 2;
#pragma unroll
    for (int i = 0; i < 4; i++) {
#pragma unroll
        for (int j = 0; j < 4; j++) {
            int m = m0 + wm * 64 + i * 16 + er;
            int n = n0 + wn * 32 + j * 8 + ec;
            float b0 = bias[n], b1 = bias[n + 1];
            float2 r0 = make_float2(acc[i][j][0] + b0, acc[i][j][1] + b1);
            float2 r1 = make_float2(acc[i][j][2] + b0, acc[i][j][3] + b1);
            *(float2*)(out + (size_t)m * OUTD + n) = r0;
            *(float2*)(out + (size_t)(m + 8) * OUTD + n) = r1;
        }
    }
}

// ---------------- launch ----------------
extern "C" void kernel_launch(void* const* d_in, const int* in_sizes, int n_in,
                              void* d_out, int out_size) {
    const float* pos    = (const float*)d_in[0];
    const float* feat   = (const float*)d_in[1];
    const int*   member = (const int*)d_in[2];
    const float* cmask  = (const float*)d_in[3];
    const float* lp     = (const float*)d_in[4];

    int pi = 5;
    if (pi < n_in && in_sizes[pi] == 1) pi++;
    const int* pe = (const int*)d_in[pi];

    int pt = pi + 1;
    while (pt < n_in && in_sizes[pt] != TABLE * 5) pt++;
    const float* pre    = (const float*)d_in[pt];
    const float* w1     = (const float*)d_in[pt + 1];
    const float* b1     = (const float*)d_in[pt + 2];
    const float* ln1_g  = (const float*)d_in[pt + 3];
    const float* ln1_b  = (const float*)d_in[pt + 4];
    const float* norm_g = (const float*)d_in[pt + 5];
    const float* norm_b = (const float*)d_in[pt + 6];
    const float* lin_w  = (const float*)d_in[pt + 7];
    const float* lin_b  = (const float*)d_in[pt + 8];

    float* out_pos = (float*)d_out;
    float* out_res = (float*)d_out + (size_t)BB * KEEP * 2;

    cudaFuncSetAttribute(prep_kernel, cudaFuncAttributeMaxDynamicSharedMemorySize, PREP_SMEM);
    cudaFuncSetAttribute(gemm_mma_kernel, cudaFuncAttributeMaxDynamicSharedMemorySize, GSMEM);

    prep_kernel<<<PREP_GRID, 1024, PREP_SMEM>>>(pos, lp, pre, w1, b1, ln1_g, ln1_b, lin_w, feat);
    token_kernel<<<MTOT / 2, 128>>>(pos, member, cmask, lp, pe, norm_g, norm_b, out_pos);
    dim3 ggrid(OUTD / BN, MTOT / BM);
    gemm_mma_kernel<<<ggrid, 256, GSMEM>>>(lin_b, out_res);
}

// round 12
// speedup vs baseline: 5.6015x; 1.0506x over previous
#include <cuda_runtime.h>
#include <cuda_bf16.h>
#include <cuda_fp16.h>
#include <math.h>
#include <cstdint>

#define BB 4
#define NN 12544
#define NBHD 48
#define DIM 256
#define OUTD 512
#define INNER 4
#define TABLE 4096
#define KEEP 3136
#define SAMP 2352
#define KDIM 1024
#define LNEPS 1e-5f
#define MTOT (BB * KEEP)   // 12544
#define CAND_CAP 3584
#define NBINS 8192
#define BIN_SCALE 1560.0f
#define BIN_OFF 5.25f

// ---------------- device scratch ----------------
__device__ float   g_wt[TABLE * INNER];
__device__ int     g_idx[BB * KEEP];
__device__ __half  g_feat16[(size_t)BB * NN * DIM];   // 25.7MB
__device__ __half  g_X16[(size_t)MTOT * KDIM];        // 25.7MB
__device__ __half  g_Wh16[(size_t)OUTD * KDIM];       // [n][k] fp16

__device__ __forceinline__ uint32_t smem_u32(const void* p) {
    uint32_t a;
    asm("{ .reg .u64 t; cvta.to.shared.u64 t, %1; cvt.u32.u64 %0, t; }" : "=r"(a) : "l"(p));
    return a;
}

// ================= PREP kernel =================
#define FEAT_BLKS 784
#define WCONV_BLKS 512
#define WT_BLKS 4
#define PREP_GRID (4 + FEAT_BLKS + WCONV_BLKS + WT_BLKS)
#define PREP_SMEM (NBINS * 4 * 2 + CAND_CAP * 8)

__device__ __forceinline__ float prob_of(const float* pos, const float* lp, int b, int i) {
    int px = (int)pos[((size_t)b * NN + i) * 2 + 0];
    int py = (int)pos[((size_t)b * NN + i) * 2 + 1];
    float fp = (((px & 1) == 0) && ((py & 1) == 0)) ? 1.f : 0.f;
    fp += lp[(size_t)b * NN + i] * 4.f;
    if (((px & 3) == 0) && ((py & 3) == 0)) fp -= 100.f;
    return fp;
}
__device__ __forceinline__ unsigned inv_of(float fp) {
    unsigned u = __float_as_uint(fp);
    u = (u & 0x80000000u) ? ~u : (u ^ 0x80000000u);
    return ~u;
}
__device__ __forceinline__ float fp_of_inv(unsigned inv) {
    unsigned enc = ~inv;
    unsigned u = (enc & 0x80000000u) ? (enc ^ 0x80000000u) : ~enc;
    return __uint_as_float(u);
}
__device__ __forceinline__ int bin_of_fp(float fp) {
    int bb = (int)((BIN_OFF - fp) * BIN_SCALE);
    return bb < 0 ? 0 : (bb > NBINS - 1 ? NBINS - 1 : bb);
}

extern __shared__ __align__(16) unsigned char dynsm[];

__global__ __launch_bounds__(1024) void prep_kernel(
    const float* __restrict__ pos, const float* __restrict__ lp,
    const float* __restrict__ pre, const float* __restrict__ w1,
    const float* __restrict__ b1, const float* __restrict__ ln1g,
    const float* __restrict__ ln1b, const float* __restrict__ lw,
    const float* __restrict__ feat) {
    int blk = blockIdx.x;
    int tid = threadIdx.x;

    if (blk < 4) {
        // ---------- selection: linear-bin histogram rank ----------
        int b = blk;
        unsigned* bins = (unsigned*)dynsm;
        unsigned* pref = (unsigned*)(dynsm + NBINS * 4);
        unsigned long long* cand = (unsigned long long*)(dynsm + NBINS * 8);
        __shared__ int s_wsum[32];
        __shared__ int s_T, s_total;

        for (int i = tid; i < NBINS; i += 1024) bins[i] = 0;
        if (tid == 0) s_T = NBINS - 1;
        __syncthreads();
        for (int i = tid; i < NN; i += 1024)
            atomicAdd(&bins[bin_of_fp(prob_of(pos, lp, b, i))], 1u);
        __syncthreads();

        int part = 0;
        unsigned mybin[8];
#pragma unroll
        for (int q = 0; q < 8; q++) { mybin[q] = bins[tid * 8 + q]; part += (int)mybin[q]; }
        int lane = tid & 31, wrp = tid >> 5;
        int v = part;
#pragma unroll
        for (int o = 1; o < 32; o <<= 1) { int nv = __shfl_up_sync(~0u, v, o); if (lane >= o) v += nv; }
        if (lane == 31) s_wsum[wrp] = v;
        __syncthreads();
        if (wrp == 0) {
            int w = s_wsum[lane];
#pragma unroll
            for (int o = 1; o < 32; o <<= 1) { int nv = __shfl_up_sync(~0u, w, o); if (lane >= o) w += nv; }
            s_wsum[lane] = w;
        }
        __syncthreads();
        int excl = v - part + (wrp > 0 ? s_wsum[wrp - 1] : 0);
        int cum = excl;
#pragma unroll
        for (int q = 0; q < 8; q++) {
            pref[tid * 8 + q] = (unsigned)cum;
            int cnt = (int)mybin[q];
            if (cum < SAMP && cum + cnt >= SAMP) s_T = tid * 8 + q;
            cum += cnt;
        }
        __syncthreads();
        int T = s_T;
        if (tid == 0) s_total = (int)pref[T] + (int)bins[T];
        __syncthreads();
        int total = s_total;
        if (total > CAND_CAP) total = CAND_CAP;

        for (int i = tid; i < NN; i += 1024) {
            float fp = prob_of(pos, lp, b, i);
            int bb = bin_of_fp(fp);
            if (bb <= T) {
                unsigned slot = atomicAdd(&pref[bb], 1u);
                if (slot < CAND_CAP)
                    cand[slot] = (((unsigned long long)inv_of(fp)) << 32) | (unsigned)i;
            }
        }
        __syncthreads();

        for (int s = tid; s < total; s += 1024) {
            unsigned long long key = cand[s];
            int bb = bin_of_fp(fp_of_inv((unsigned)(key >> 32)));
            int end = (int)pref[bb]; if (end > total) end = total;
            int start = end - (int)bins[bb]; if (start < 0) start = 0;
            int r = start;
            for (int j = start; j < end; j++)
                if (cand[j] < key) r++;
            if (r < SAMP) g_idx[b * KEEP + r] = (int)(key & 0xFFFFFFFFull);
        }
        for (int t = SAMP + tid; t < KEEP; t += 1024) {
            int r = t - SAMP;
            g_idx[b * KEEP + t] = ((r / 28) * 4) * 112 + (r % 28) * 4;
        }
        return;
    }
    blk -= 4;

    if (blk < FEAT_BLKS) {
        // ---------- feat fp32 -> fp16 : 4 consecutive float4 per thread ----------
        size_t base = ((size_t)blk * 1024 + tid) * 4;   // float4 index
        float4 f0 = ((const float4*)feat)[base + 0];
        float4 f1 = ((const float4*)feat)[base + 1];
        float4 f2 = ((const float4*)feat)[base + 2];
        float4 f3 = ((const float4*)feat)[base + 3];
        uint4 o0, o1;
        __half2 h;
        h = __floats2half2_rn(f0.x, f0.y); o0.x = *(uint32_t*)&h;
        h = __floats2half2_rn(f0.z, f0.w); o0.y = *(uint32_t*)&h;
        h = __floats2half2_rn(f1.x, f1.y); o0.z = *(uint32_t*)&h;
        h = __floats2half2_rn(f1.z, f1.w); o0.w = *(uint32_t*)&h;
        h = __floats2half2_rn(f2.x, f2.y); o1.x = *(uint32_t*)&h;
        h = __floats2half2_rn(f2.z, f2.w); o1.y = *(uint32_t*)&h;
        h = __floats2half2_rn(f3.x, f3.y); o1.z = *(uint32_t*)&h;
        h = __floats2half2_rn(f3.z, f3.w); o1.w = *(uint32_t*)&h;
        ((uint4*)g_feat16)[base / 2 + 0] = o0;
        ((uint4*)g_feat16)[base / 2 + 1] = o1;
        return;
    }
    blk -= FEAT_BLKS;

    if (blk < WCONV_BLKS) {
        // ---------- W transpose -> fp16 ----------
        __shared__ float tile[32][33];
        int tk = blk >> 4, tn = blk & 15;
        int k0 = tk * 32, n0 = tn * 32;
        int tx = tid & 31, ty = tid >> 5;
        tile[ty][tx] = lw[(size_t)(k0 + ty) * OUTD + n0 + tx];
        __syncthreads();
        int n = n0 + ty, k = k0 + tx;
        g_Wh16[(size_t)n * KDIM + k] = __float2half_rn(tile[tx][ty]);
        return;
    }
    blk -= WCONV_BLKS;

    // ---------- weight_net table ----------
    int r = blk * 1024 + tid;
    if (r < TABLE) {
        float p[5];
#pragma unroll
        for (int k = 0; k < 5; k++) p[k] = pre[r * 5 + k];
        float h[4];
#pragma unroll
        for (int m = 0; m < 4; m++) {
            float s = b1[m];
#pragma unroll
            for (int k = 0; k < 5; k++) s += p[k] * w1[k * 4 + m];
            h[m] = s;
        }
        float mean = 0.25f * (h[0] + h[1] + h[2] + h[3]);
        float vv = 0.f;
#pragma unroll
        for (int m = 0; m < 4; m++) { float d = h[m] - mean; vv += d * d; }
        float rstd = rsqrtf(vv * 0.25f + LNEPS);
#pragma unroll
        for (int m = 0; m < 4; m++) {
            float x = (h[m] - mean) * rstd * ln1g[m] + ln1b[m];
            g_wt[r * 4 + m] = 0.5f * x * (1.f + erff(x * 0.70710678118654752440f));
        }
    }
}

// ================= token kernel: 4 tokens per 256-thr block, 4 ch/thread =================
__global__ __launch_bounds__(256) void token_kernel(
    const float* __restrict__ pos, const int* __restrict__ member,
    const float* __restrict__ cmask, const float* __restrict__ lp,
    const int* __restrict__ pe, const float* __restrict__ ng,
    const float* __restrict__ nb, float* __restrict__ out_pos) {
    int tid = threadIdx.x;
    int quad = tid >> 6;         // 0..3: token within block
    int qtid = tid & 63;         // owns channels [qtid*4, qtid*4+4)
    int t = blockIdx.x * 4 + quad;
    int b = t / KEEP;

    __shared__ int    s_mem[4][NBHD];
    __shared__ float4 s_w4[4][NBHD];
    __shared__ float  red[8];
    __shared__ int    s_src[4];

    if (qtid == 0) s_src[quad] = g_idx[t];
    __syncthreads();
    int src = s_src[quad];

    if (qtid < 2) out_pos[(size_t)t * 2 + qtid] = pos[((size_t)b * NN + src) * 2 + qtid];

    if (qtid < NBHD) {
        size_t eoff = ((size_t)b * NN + src) * NBHD + qtid;
        int mm = member[eoff];
        int pp = pe[eoff];
        float sc = lp[(size_t)b * NN + mm] * cmask[eoff];
        s_mem[quad][qtid] = mm;
        float4 w;
        w.x = g_wt[pp * 4 + 0] * sc;
        w.y = g_wt[pp * 4 + 1] * sc;
        w.z = g_wt[pp * 4 + 2] * sc;
        w.w = g_wt[pp * 4 + 3] * sc;
        s_w4[quad][qtid] = w;
    }
    __syncthreads();

    const uint2* fb2 = (const uint2*)(g_feat16 + (size_t)b * NN * DIM);
    float a[4][4];
#pragma unroll
    for (int m = 0; m < 4; m++)
#pragma unroll
        for (int c = 0; c < 4; c++) a[m][c] = 0.f;

#pragma unroll 4
    for (int j = 0; j < NBHD; j++) {
        int mm = s_mem[quad][j];
        float4 w = s_w4[quad][j];
        uint2 fv = fb2[(size_t)mm * 64 + qtid];
        float2 f01 = __half22float2(*(__half2*)&fv.x);
        float2 f23 = __half22float2(*(__half2*)&fv.y);
        float f[4] = {f01.x, f01.y, f23.x, f23.y};
        float wm[4] = {w.x, w.y, w.z, w.w};
#pragma unroll
        for (int m = 0; m < 4; m++)
#pragma unroll
            for (int c = 0; c < 4; c++) a[m][c] += wm[m] * f[c];
    }

    // LayerNorm over 1024 values (16 per thread, 64 threads = 2 warps per token)
    float s = 0.f;
#pragma unroll
    for (int m = 0; m < 4; m++)
#pragma unroll
        for (int c = 0; c < 4; c++) s += a[m][c];
#pragma unroll
    for (int o = 16; o > 0; o >>= 1) s += __shfl_down_sync(0xffffffffu, s, o);
    if ((tid & 31) == 0) red[tid >> 5] = s;
    __syncthreads();
    float mean = (red[quad * 2 + 0] + red[quad * 2 + 1]) * (1.f / 1024.f);
    __syncthreads();

    float vs = 0.f;
#pragma unroll
    for (int m = 0; m < 4; m++)
#pragma unroll
        for (int c = 0; c < 4; c++) { float d = a[m][c] - mean; vs += d * d; }
#pragma unroll
    for (int o = 16; o > 0; o >>= 1) vs += __shfl_down_sync(0xffffffffu, vs, o);
    if ((tid & 31) == 0) red[tid >> 5] = vs;
    __syncthreads();
    float rstd = rsqrtf((red[quad * 2 + 0] + red[quad * 2 + 1]) * (1.f / 1024.f) + LNEPS);

    __half* X = g_X16 + (size_t)t * KDIM;
#pragma unroll
    for (int m = 0; m < 4; m++) {
        int idx = m * 256 + qtid * 4;
        float4 gg = *(const float4*)(ng + idx);
        float4 bbv = *(const float4*)(nb + idx);
        float v0 = (a[m][0] - mean) * rstd * gg.x + bbv.x;
        float v1 = (a[m][1] - mean) * rstd * gg.y + bbv.y;
        float v2 = (a[m][2] - mean) * rstd * gg.z + bbv.z;
        float v3 = (a[m][3] - mean) * rstd * gg.w + bbv.w;
        __half2 h0 = __floats2half2_rn(v0, v1);
        __half2 h1 = __floats2half2_rn(v2, v3);
        uint2 o;
        o.x = *(uint32_t*)&h0;
        o.y = *(uint32_t*)&h1;
        *(uint2*)(X + idx) = o;
    }
}

// ================= GEMM: 4-stage cp.async fp16 mma.sync, 1 sync/iter =================
#define BM 128
#define BN 128
#define BKK 32
#define NT (KDIM / BKK)   // 32
#define ASTR 40           // fp16 elems; 80B row stride
#define ARR_BYTES 10240
#define STAGE_BYTES (2 * ARR_BYTES)
#define NSTAGE 4
#define GSMEM (NSTAGE * STAGE_BYTES)   // 81920

#define CP16(d, s) asm volatile("cp.async.cg.shared.global [%0], [%1], 16;" :: "r"(d), "l"(__cvta_generic_to_global(s)))
#define CP_COMMIT() asm volatile("cp.async.commit_group;" ::: "memory")
#define CP_WAIT2() asm volatile("cp.async.wait_group 2;" ::: "memory")
#define CP_WAIT1() asm volatile("cp.async.wait_group 1;" ::: "memory")
#define CP_WAIT0() asm volatile("cp.async.wait_group 0;" ::: "memory")

#define LDMX4(r0, r1, r2, r3, a) \
    asm volatile("ldmatrix.sync.aligned.m8n8.x4.shared.b16 {%0,%1,%2,%3}, [%4];" \
                 : "=r"(r0), "=r"(r1), "=r"(r2), "=r"(r3) : "r"(a))
#define MMAF16(c, a, b) \
    asm volatile("mma.sync.aligned.m16n8k16.row.col.f32.f16.f16.f32 " \
                 "{%0,%1,%2,%3}, {%4,%5,%6,%7}, {%8,%9}, {%0,%1,%2,%3};" \
                 : "+f"((c)[0]), "+f"((c)[1]), "+f"((c)[2]), "+f"((c)[3]) \
                 : "r"((a)[0]), "r"((a)[1]), "r"((a)[2]), "r"((a)[3]), "r"((b)[0]), "r"((b)[1]))

__device__ __forceinline__ void gemm_load(uint32_t sbase, int m0, int n0, int kt, int tid) {
    int k0 = kt * BKK;
#pragma unroll
    for (int it = 0; it < 2; it++) {
        int id = tid + it * 256;          // 0..511
        int r = id >> 2, c = id & 3;
        uint32_t doff = (uint32_t)(r * 80 + c * 16);
        CP16(sbase + 0 * ARR_BYTES + doff, g_X16  + (size_t)(m0 + r) * KDIM + k0 + c * 8);
        CP16(sbase + 1 * ARR_BYTES + doff, g_Wh16 + (size_t)(n0 + r) * KDIM + k0 + c * 8);
    }
}

__global__ __launch_bounds__(256) void gemm_mma_kernel(const float* __restrict__ bias,
                                                       float* __restrict__ out) {
    uint32_t sb = smem_u32(dynsm);
    int tid = threadIdx.x;
    int wid = tid >> 5, lane = tid & 31;
    int wm = wid >> 2, wn = wid & 3;
    int n0 = blockIdx.x * BN;
    int m0 = blockIdx.y * BM;

    float acc[4][4][4];
#pragma unroll
    for (int i = 0; i < 4; i++)
#pragma unroll
        for (int j = 0; j < 4; j++)
#pragma unroll
            for (int q = 0; q < 4; q++) acc[i][j][q] = 0.f;

    gemm_load(sb + 0 * STAGE_BYTES, m0, n0, 0, tid);
    CP_COMMIT();
    gemm_load(sb + 1 * STAGE_BYTES, m0, n0, 1, tid);
    CP_COMMIT();
    gemm_load(sb + 2 * STAGE_BYTES, m0, n0, 2, tid);
    CP_COMMIT();

    int slot = 0;
    for (int kt = 0; kt < NT; kt++) {
        // at top of iter kt, committed groups = min(kt+3, NT); need group kt done
        if (kt + 2 < NT) { CP_WAIT2(); }
        else if (kt + 1 < NT) { CP_WAIT1(); }
        else { CP_WAIT0(); }
        __syncthreads();   // one barrier: orders prev-iter reads before reload AND publishes this slot

        uint32_t base = sb + slot * STAGE_BYTES;
        uint32_t uA = base;
        uint32_t uB = base + ARR_BYTES;

#pragma unroll
        for (int s = 0; s < 2; s++) {
            int kk = s * 16;
            uint32_t a[4][4], bf[4][2];
            int arow = wm * 64 + (lane & 15);
            int acol = kk + (lane >> 4) * 8;
#pragma unroll
            for (int i = 0; i < 4; i++) {
                uint32_t off = (uint32_t)((arow + i * 16) * ASTR + acol) * 2;
                LDMX4(a[i][0], a[i][1], a[i][2], a[i][3], uA + off);
            }
            // B: two ldmatrix.x4, each covering 16 n-rows x 16 k
            {
                int q = lane >> 3;                       // 0..3
                int brow_base = wn * 32 + (lane & 7);
#pragma unroll
                for (int jj = 0; jj < 2; jj++) {
                    int row = brow_base + jj * 16 + (q >> 1) * 8;
                    int col = kk + (q & 1) * 8;
                    uint32_t off = (uint32_t)(row * ASTR + col) * 2;
                    LDMX4(bf[jj * 2][0], bf[jj * 2][1], bf[jj * 2 + 1][0], bf[jj * 2 + 1][1], uB + off);
                }
            }
#pragma unroll
            for (int i = 0; i < 4; i++)
#pragma unroll
                for (int j = 0; j < 4; j++)
                    MMAF16(acc[i][j], a[i], bf[j]);
        }

        if (kt + 3 < NT) {
            gemm_load(sb + ((slot + 3) % NSTAGE) * STAGE_BYTES, m0, n0, kt + 3, tid);
            CP_COMMIT();
        }
        slot = (slot + 1) % NSTAGE;
    }

    int er = lane >> 2;
    int ec = (lane & 3) * 2;
#pragma unroll
    for (int i = 0; i < 4; i++) {
#pragma unroll
        for (int j = 0; j < 4; j++) {
            int m = m0 + wm * 64 + i * 16 + er;
            int n = n0 + wn * 32 + j * 8 + ec;
            float b0 = bias[n], b1 = bias[n + 1];
            float2 r0 = make_float2(acc[i][j][0] + b0, acc[i][j][1] + b1);
            float2 r1 = make_float2(acc[i][j][2] + b0, acc[i][j][3] + b1);
            *(float2*)(out + (size_t)m * OUTD + n) = r0;
            *(float2*)(out + (size_t)(m + 8) * OUTD + n) = r1;
        }
    }
}

// ---------------- launch ----------------
extern "C" void kernel_launch(void* const* d_in, const int* in_sizes, int n_in,
                              void* d_out, int out_size) {
    const float* pos    = (const float*)d_in[0];
    const float* feat   = (const float*)d_in[1];
    const int*   member = (const int*)d_in[2];
    const float* cmask  = (const float*)d_in[3];
    const float* lp     = (const float*)d_in[4];

    int pi = 5;
    if (pi < n_in && in_sizes[pi] == 1) pi++;
    const int* pe = (const int*)d_in[pi];

    int pt = pi + 1;
    while (pt < n_in && in_sizes[pt] != TABLE * 5) pt++;
    const float* pre    = (const float*)d_in[pt];
    const float* w1     = (const float*)d_in[pt + 1];
    const float* b1     = (const float*)d_in[pt + 2];
    const float* ln1_g  = (const float*)d_in[pt + 3];
    const float* ln1_b  = (const float*)d_in[pt + 4];
    const float* norm_g = (const float*)d_in[pt + 5];
    const float* norm_b = (const float*)d_in[pt + 6];
    const float* lin_w  = (const float*)d_in[pt + 7];
    const float* lin_b  = (const float*)d_in[pt + 8];

    float* out_pos = (float*)d_out;
    float* out_res = (float*)d_out + (size_t)BB * KEEP * 2;

    cudaFuncSetAttribute(prep_kernel, cudaFuncAttributeMaxDynamicSharedMemorySize, PREP_SMEM);
    cudaFuncSetAttribute(gemm_mma_kernel, cudaFuncAttributeMaxDynamicSharedMemorySize, GSMEM);

    prep_kernel<<<PREP_GRID, 1024, PREP_SMEM>>>(pos, lp, pre, w1, b1, ln1_g, ln1_b, lin_w, feat);
    token_kernel<<<MTOT / 4, 256>>>(pos, member, cmask, lp, pe, norm_g, norm_b, out_pos);
    dim3 ggrid(OUTD / BN, MTOT / BM);
    gemm_mma_kernel<<<ggrid, 256, GSMEM>>>(lin_b, out_res);
}

// round 13
// speedup vs baseline: 5.6498x; 1.0086x over previous
#include <cuda_runtime.h>
#include <cuda_bf16.h>
#include <cuda_fp16.h>
#include <math.h>
#include <cstdint>

#define BB 4
#define NN 12544
#define NBHD 48
#define DIM 256
#define OUTD 512
#define INNER 4
#define TABLE 4096
#define KEEP 3136
#define SAMP 2352
#define KDIM 1024
#define LNEPS 1e-5f
#define MTOT (BB * KEEP)   // 12544
#define CAND_CAP 3584
#define NBINS 8192
#define BIN_SCALE 1560.0f
#define BIN_OFF 5.25f

// ---------------- device scratch ----------------
__device__ float   g_wt[TABLE * INNER];
__device__ int     g_idx[BB * KEEP];
__device__ __half  g_feat16[(size_t)BB * NN * DIM];   // 25.7MB
__device__ __half  g_X16[(size_t)MTOT * KDIM];        // 25.7MB
__device__ __half  g_Wh16[(size_t)OUTD * KDIM];       // [n][k] fp16

__device__ __forceinline__ uint32_t smem_u32(const void* p) {
    uint32_t a;
    asm("{ .reg .u64 t; cvta.to.shared.u64 t, %1; cvt.u32.u64 %0, t; }" : "=r"(a) : "l"(p));
    return a;
}

// ================= PREP kernel =================
#define FEAT_BLKS 784
#define WCONV_BLKS 512
#define WT_BLKS 4
#define PREP_GRID (4 + FEAT_BLKS + WCONV_BLKS + WT_BLKS)
#define PREP_SMEM (NBINS * 4 * 2 + CAND_CAP * 8)

__device__ __forceinline__ float prob_of(const float* pos, const float* lp, int b, int i) {
    int px = (int)pos[((size_t)b * NN + i) * 2 + 0];
    int py = (int)pos[((size_t)b * NN + i) * 2 + 1];
    float fp = (((px & 1) == 0) && ((py & 1) == 0)) ? 1.f : 0.f;
    fp += lp[(size_t)b * NN + i] * 4.f;
    if (((px & 3) == 0) && ((py & 3) == 0)) fp -= 100.f;
    return fp;
}
__device__ __forceinline__ unsigned inv_of(float fp) {
    unsigned u = __float_as_uint(fp);
    u = (u & 0x80000000u) ? ~u : (u ^ 0x80000000u);
    return ~u;
}
__device__ __forceinline__ float fp_of_inv(unsigned inv) {
    unsigned enc = ~inv;
    unsigned u = (enc & 0x80000000u) ? (enc ^ 0x80000000u) : ~enc;
    return __uint_as_float(u);
}
__device__ __forceinline__ int bin_of_fp(float fp) {
    int bb = (int)((BIN_OFF - fp) * BIN_SCALE);
    return bb < 0 ? 0 : (bb > NBINS - 1 ? NBINS - 1 : bb);
}

extern __shared__ __align__(16) unsigned char dynsm[];

__global__ __launch_bounds__(1024) void prep_kernel(
    const float* __restrict__ pos, const float* __restrict__ lp,
    const float* __restrict__ pre, const float* __restrict__ w1,
    const float* __restrict__ b1, const float* __restrict__ ln1g,
    const float* __restrict__ ln1b, const float* __restrict__ lw,
    const float* __restrict__ feat) {
    int blk = blockIdx.x;
    int tid = threadIdx.x;

    if (blk < 4) {
        // ---------- selection: linear-bin histogram rank ----------
        int b = blk;
        unsigned* bins = (unsigned*)dynsm;
        unsigned* pref = (unsigned*)(dynsm + NBINS * 4);
        unsigned long long* cand = (unsigned long long*)(dynsm + NBINS * 8);
        __shared__ int s_wsum[32];
        __shared__ int s_T, s_total;

        for (int i = tid; i < NBINS; i += 1024) bins[i] = 0;
        if (tid == 0) s_T = NBINS - 1;
        __syncthreads();
        for (int i = tid; i < NN; i += 1024)
            atomicAdd(&bins[bin_of_fp(prob_of(pos, lp, b, i))], 1u);
        __syncthreads();

        int part = 0;
        unsigned mybin[8];
#pragma unroll
        for (int q = 0; q < 8; q++) { mybin[q] = bins[tid * 8 + q]; part += (int)mybin[q]; }
        int lane = tid & 31, wrp = tid >> 5;
        int v = part;
#pragma unroll
        for (int o = 1; o < 32; o <<= 1) { int nv = __shfl_up_sync(~0u, v, o); if (lane >= o) v += nv; }
        if (lane == 31) s_wsum[wrp] = v;
        __syncthreads();
        if (wrp == 0) {
            int w = s_wsum[lane];
#pragma unroll
            for (int o = 1; o < 32; o <<= 1) { int nv = __shfl_up_sync(~0u, w, o); if (lane >= o) w += nv; }
            s_wsum[lane] = w;
        }
        __syncthreads();
        int excl = v - part + (wrp > 0 ? s_wsum[wrp - 1] : 0);
        int cum = excl;
#pragma unroll
        for (int q = 0; q < 8; q++) {
            pref[tid * 8 + q] = (unsigned)cum;
            int cnt = (int)mybin[q];
            if (cum < SAMP && cum + cnt >= SAMP) s_T = tid * 8 + q;
            cum += cnt;
        }
        __syncthreads();
        int T = s_T;
        if (tid == 0) s_total = (int)pref[T] + (int)bins[T];
        __syncthreads();
        int total = s_total;
        if (total > CAND_CAP) total = CAND_CAP;

        for (int i = tid; i < NN; i += 1024) {
            float fp = prob_of(pos, lp, b, i);
            int bb = bin_of_fp(fp);
            if (bb <= T) {
                unsigned slot = atomicAdd(&pref[bb], 1u);
                if (slot < CAND_CAP)
                    cand[slot] = (((unsigned long long)inv_of(fp)) << 32) | (unsigned)i;
            }
        }
        __syncthreads();

        for (int s = tid; s < total; s += 1024) {
            unsigned long long key = cand[s];
            int bb = bin_of_fp(fp_of_inv((unsigned)(key >> 32)));
            int end = (int)pref[bb]; if (end > total) end = total;
            int start = end - (int)bins[bb]; if (start < 0) start = 0;
            int r = start;
            for (int j = start; j < end; j++)
                if (cand[j] < key) r++;
            if (r < SAMP) g_idx[b * KEEP + r] = (int)(key & 0xFFFFFFFFull);
        }
        for (int t = SAMP + tid; t < KEEP; t += 1024) {
            int r = t - SAMP;
            g_idx[b * KEEP + t] = ((r / 28) * 4) * 112 + (r % 28) * 4;
        }
        return;
    }
    blk -= 4;

    if (blk < FEAT_BLKS) {
        // ---------- feat fp32 -> fp16 : 4 consecutive float4 per thread ----------
        size_t base = ((size_t)blk * 1024 + tid) * 4;   // float4 index
        float4 f0 = ((const float4*)feat)[base + 0];
        float4 f1 = ((const float4*)feat)[base + 1];
        float4 f2 = ((const float4*)feat)[base + 2];
        float4 f3 = ((const float4*)feat)[base + 3];
        uint4 o0, o1;
        __half2 h;
        h = __floats2half2_rn(f0.x, f0.y); o0.x = *(uint32_t*)&h;
        h = __floats2half2_rn(f0.z, f0.w); o0.y = *(uint32_t*)&h;
        h = __floats2half2_rn(f1.x, f1.y); o0.z = *(uint32_t*)&h;
        h = __floats2half2_rn(f1.z, f1.w); o0.w = *(uint32_t*)&h;
        h = __floats2half2_rn(f2.x, f2.y); o1.x = *(uint32_t*)&h;
        h = __floats2half2_rn(f2.z, f2.w); o1.y = *(uint32_t*)&h;
        h = __floats2half2_rn(f3.x, f3.y); o1.z = *(uint32_t*)&h;
        h = __floats2half2_rn(f3.z, f3.w); o1.w = *(uint32_t*)&h;
        ((uint4*)g_feat16)[base / 2 + 0] = o0;
        ((uint4*)g_feat16)[base / 2 + 1] = o1;
        return;
    }
    blk -= FEAT_BLKS;

    if (blk < WCONV_BLKS) {
        // ---------- W transpose -> fp16 ----------
        __shared__ float tile[32][33];
        int tk = blk >> 4, tn = blk & 15;
        int k0 = tk * 32, n0 = tn * 32;
        int tx = tid & 31, ty = tid >> 5;
        tile[ty][tx] = lw[(size_t)(k0 + ty) * OUTD + n0 + tx];
        __syncthreads();
        int n = n0 + ty, k = k0 + tx;
        g_Wh16[(size_t)n * KDIM + k] = __float2half_rn(tile[tx][ty]);
        return;
    }
    blk -= WCONV_BLKS;

    // ---------- weight_net table ----------
    int r = blk * 1024 + tid;
    if (r < TABLE) {
        float p[5];
#pragma unroll
        for (int k = 0; k < 5; k++) p[k] = pre[r * 5 + k];
        float h[4];
#pragma unroll
        for (int m = 0; m < 4; m++) {
            float s = b1[m];
#pragma unroll
            for (int k = 0; k < 5; k++) s += p[k] * w1[k * 4 + m];
            h[m] = s;
        }
        float mean = 0.25f * (h[0] + h[1] + h[2] + h[3]);
        float vv = 0.f;
#pragma unroll
        for (int m = 0; m < 4; m++) { float d = h[m] - mean; vv += d * d; }
        float rstd = rsqrtf(vv * 0.25f + LNEPS);
#pragma unroll
        for (int m = 0; m < 4; m++) {
            float x = (h[m] - mean) * rstd * ln1g[m] + ln1b[m];
            g_wt[r * 4 + m] = 0.5f * x * (1.f + erff(x * 0.70710678118654752440f));
        }
    }
}

// ================= token kernel: 1 warp per token, 8 ch/thread, no __syncthreads =================
__global__ __launch_bounds__(256) void token_kernel(
    const float* __restrict__ pos, const int* __restrict__ member,
    const float* __restrict__ cmask, const float* __restrict__ lp,
    const int* __restrict__ pe, const float* __restrict__ ng,
    const float* __restrict__ nb, float* __restrict__ out_pos) {
    int tid = threadIdx.x;
    int grp = tid >> 5;          // 0..7: token within block
    int lane = tid & 31;         // owns channels [lane*8, lane*8+8)
    int t = blockIdx.x * 8 + grp;
    int b = t / KEEP;

    __shared__ int    s_mem[8][NBHD];
    __shared__ float4 s_w4[8][NBHD];

    int src = g_idx[t];          // broadcast load, all lanes same address

    if (lane < 2) out_pos[(size_t)t * 2 + lane] = pos[((size_t)b * NN + src) * 2 + lane];

    for (int j = lane; j < NBHD; j += 32) {
        size_t eoff = ((size_t)b * NN + src) * NBHD + j;
        int mm = member[eoff];
        int pp = pe[eoff];
        float sc = lp[(size_t)b * NN + mm] * cmask[eoff];
        s_mem[grp][j] = mm;
        float4 w;
        w.x = g_wt[pp * 4 + 0] * sc;
        w.y = g_wt[pp * 4 + 1] * sc;
        w.z = g_wt[pp * 4 + 2] * sc;
        w.w = g_wt[pp * 4 + 3] * sc;
        s_w4[grp][j] = w;
    }
    __syncwarp();

    const uint4* fb4 = (const uint4*)(g_feat16 + (size_t)b * NN * DIM);
    float a[4][8];
#pragma unroll
    for (int m = 0; m < 4; m++)
#pragma unroll
        for (int c = 0; c < 8; c++) a[m][c] = 0.f;

#pragma unroll 4
    for (int j = 0; j < NBHD; j++) {
        int mm = s_mem[grp][j];
        float4 w = s_w4[grp][j];
        uint4 fv = fb4[(size_t)mm * 32 + lane];   // 16B = 8 halves of this token row
        float2 f01 = __half22float2(*(__half2*)&fv.x);
        float2 f23 = __half22float2(*(__half2*)&fv.y);
        float2 f45 = __half22float2(*(__half2*)&fv.z);
        float2 f67 = __half22float2(*(__half2*)&fv.w);
        float f[8] = {f01.x, f01.y, f23.x, f23.y, f45.x, f45.y, f67.x, f67.y};
        float wm[4] = {w.x, w.y, w.z, w.w};
#pragma unroll
        for (int m = 0; m < 4; m++)
#pragma unroll
            for (int c = 0; c < 8; c++) a[m][c] += wm[m] * f[c];
    }

    // LayerNorm over 1024 values: 32 per thread, warp-only butterfly reduction
    float s = 0.f;
#pragma unroll
    for (int m = 0; m < 4; m++)
#pragma unroll
        for (int c = 0; c < 8; c++) s += a[m][c];
#pragma unroll
    for (int o = 16; o > 0; o >>= 1) s += __shfl_xor_sync(0xffffffffu, s, o);
    float mean = s * (1.f / 1024.f);

    float vs = 0.f;
#pragma unroll
    for (int m = 0; m < 4; m++)
#pragma unroll
        for (int c = 0; c < 8; c++) { float d = a[m][c] - mean; vs += d * d; }
#pragma unroll
    for (int o = 16; o > 0; o >>= 1) vs += __shfl_xor_sync(0xffffffffu, vs, o);
    float rstd = rsqrtf(vs * (1.f / 1024.f) + LNEPS);

    __half* X = g_X16 + (size_t)t * KDIM;
#pragma unroll
    for (int m = 0; m < 4; m++) {
        int idx = m * 256 + lane * 8;
        float4 g0 = *(const float4*)(ng + idx);
        float4 g1 = *(const float4*)(ng + idx + 4);
        float4 b0 = *(const float4*)(nb + idx);
        float4 b1v = *(const float4*)(nb + idx + 4);
        float v0 = (a[m][0] - mean) * rstd * g0.x + b0.x;
        float v1 = (a[m][1] - mean) * rstd * g0.y + b0.y;
        float v2 = (a[m][2] - mean) * rstd * g0.z + b0.z;
        float v3 = (a[m][3] - mean) * rstd * g0.w + b0.w;
        float v4 = (a[m][4] - mean) * rstd * g1.x + b1v.x;
        float v5 = (a[m][5] - mean) * rstd * g1.y + b1v.y;
        float v6 = (a[m][6] - mean) * rstd * g1.z + b1v.z;
        float v7 = (a[m][7] - mean) * rstd * g1.w + b1v.w;
        __half2 h0 = __floats2half2_rn(v0, v1);
        __half2 h1 = __floats2half2_rn(v2, v3);
        __half2 h2 = __floats2half2_rn(v4, v5);
        __half2 h3 = __floats2half2_rn(v6, v7);
        uint4 o;
        o.x = *(uint32_t*)&h0;
        o.y = *(uint32_t*)&h1;
        o.z = *(uint32_t*)&h2;
        o.w = *(uint32_t*)&h3;
        *(uint4*)(X + idx) = o;
    }
}

// ================= GEMM: 4-stage cp.async fp16 mma.sync, 1 sync/iter =================
#define BM 128
#define BN 128
#define BKK 32
#define NT (KDIM / BKK)   // 32
#define ASTR 40           // fp16 elems; 80B row stride
#define ARR_BYTES 10240
#define STAGE_BYTES (2 * ARR_BYTES)
#define NSTAGE 4
#define GSMEM (NSTAGE * STAGE_BYTES)   // 81920

#define CP16(d, s) asm volatile("cp.async.cg.shared.global [%0], [%1], 16;" :: "r"(d), "l"(__cvta_generic_to_global(s)))
#define CP_COMMIT() asm volatile("cp.async.commit_group;" ::: "memory")
#define CP_WAIT2() asm volatile("cp.async.wait_group 2;" ::: "memory")
#define CP_WAIT1() asm volatile("cp.async.wait_group 1;" ::: "memory")
#define CP_WAIT0() asm volatile("cp.async.wait_group 0;" ::: "memory")

#define LDMX4(r0, r1, r2, r3, a) \
    asm volatile("ldmatrix.sync.aligned.m8n8.x4.shared.b16 {%0,%1,%2,%3}, [%4];" \
                 : "=r"(r0), "=r"(r1), "=r"(r2), "=r"(r3) : "r"(a))
#define MMAF16(c, a, b) \
    asm volatile("mma.sync.aligned.m16n8k16.row.col.f32.f16.f16.f32 " \
                 "{%0,%1,%2,%3}, {%4,%5,%6,%7}, {%8,%9}, {%0,%1,%2,%3};" \
                 : "+f"((c)[0]), "+f"((c)[1]), "+f"((c)[2]), "+f"((c)[3]) \
                 : "r"((a)[0]), "r"((a)[1]), "r"((a)[2]), "r"((a)[3]), "r"((b)[0]), "r"((b)[1]))

__device__ __forceinline__ void gemm_load(uint32_t sbase, int m0, int n0, int kt, int tid) {
    int k0 = kt * BKK;
#pragma unroll
    for (int it = 0; it < 2; it++) {
        int id = tid + it * 256;          // 0..511
        int r = id >> 2, c = id & 3;
        uint32_t doff = (uint32_t)(r * 80 + c * 16);
        CP16(sbase + 0 * ARR_BYTES + doff, g_X16  + (size_t)(m0 + r) * KDIM + k0 + c * 8);
        CP16(sbase + 1 * ARR_BYTES + doff, g_Wh16 + (size_t)(n0 + r) * KDIM + k0 + c * 8);
    }
}

__global__ __launch_bounds__(256) void gemm_mma_kernel(const float* __restrict__ bias,
                                                       float* __restrict__ out) {
    uint32_t sb = smem_u32(dynsm);
    int tid = threadIdx.x;
    int wid = tid >> 5, lane = tid & 31;
    int wm = wid >> 2, wn = wid & 3;
    int n0 = blockIdx.x * BN;
    int m0 = blockIdx.y * BM;

    float acc[4][4][4];
#pragma unroll
    for (int i = 0; i < 4; i++)
#pragma unroll
        for (int j = 0; j < 4; j++)
#pragma unroll
            for (int q = 0; q < 4; q++) acc[i][j][q] = 0.f;

    gemm_load(sb + 0 * STAGE_BYTES, m0, n0, 0, tid);
    CP_COMMIT();
    gemm_load(sb + 1 * STAGE_BYTES, m0, n0, 1, tid);
    CP_COMMIT();
    gemm_load(sb + 2 * STAGE_BYTES, m0, n0, 2, tid);
    CP_COMMIT();

    int slot = 0;
    for (int kt = 0; kt < NT; kt++) {
        if (kt + 2 < NT) { CP_WAIT2(); }
        else if (kt + 1 < NT) { CP_WAIT1(); }
        else { CP_WAIT0(); }
        __syncthreads();

        uint32_t base = sb + slot * STAGE_BYTES;
        uint32_t uA = base;
        uint32_t uB = base + ARR_BYTES;

#pragma unroll
        for (int s = 0; s < 2; s++) {
            int kk = s * 16;
            uint32_t a[4][4], bf[4][2];
            int arow = wm * 64 + (lane & 15);
            int acol = kk + (lane >> 4) * 8;
#pragma unroll
            for (int i = 0; i < 4; i++) {
                uint32_t off = (uint32_t)((arow + i * 16) * ASTR + acol) * 2;
                LDMX4(a[i][0], a[i][1], a[i][2], a[i][3], uA + off);
            }
            {
                int q = lane >> 3;
                int brow_base = wn * 32 + (lane & 7);
#pragma unroll
                for (int jj = 0; jj < 2; jj++) {
                    int row = brow_base + jj * 16 + (q >> 1) * 8;
                    int col = kk + (q & 1) * 8;
                    uint32_t off = (uint32_t)(row * ASTR + col) * 2;
                    LDMX4(bf[jj * 2][0], bf[jj * 2][1], bf[jj * 2 + 1][0], bf[jj * 2 + 1][1], uB + off);
                }
            }
#pragma unroll
            for (int i = 0; i < 4; i++)
#pragma unroll
                for (int j = 0; j < 4; j++)
                    MMAF16(acc[i][j], a[i], bf[j]);
        }

        if (kt + 3 < NT) {
            gemm_load(sb + ((slot + 3) % NSTAGE) * STAGE_BYTES, m0, n0, kt + 3, tid);
            CP_COMMIT();
        }
        slot = (slot + 1) % NSTAGE;
    }

    int er = lane >> 2;
    int ec = (lane & 3) * 2;
#pragma unroll
    for (int i = 0; i < 4; i++) {
#pragma unroll
        for (int j = 0; j < 4; j++) {
            int m = m0 + wm * 64 + i * 16 + er;
            int n = n0 + wn * 32 + j * 8 + ec;
            float b0 = bias[n], b1 = bias[n + 1];
            float2 r0 = make_float2(acc[i][j][0] + b0, acc[i][j][1] + b1);
            float2 r1 = make_float2(acc[i][j][2] + b0, acc[i][j][3] + b1);
            *(float2*)(out + (size_t)m * OUTD + n) = r0;
            *(float2*)(out + (size_t)(m + 8) * OUTD + n) = r1;
        }
    }
}

// ---------------- launch ----------------
extern "C" void kernel_launch(void* const* d_in, const int* in_sizes, int n_in,
                              void* d_out, int out_size) {
    const float* pos    = (const float*)d_in[0];
    const float* feat   = (const float*)d_in[1];
    const int*   member = (const int*)d_in[2];
    const float* cmask  = (const float*)d_in[3];
    const float* lp     = (const float*)d_in[4];

    int pi = 5;
    if (pi < n_in && in_sizes[pi] == 1) pi++;
    const int* pe = (const int*)d_in[pi];

    int pt = pi + 1;
    while (pt < n_in && in_sizes[pt] != TABLE * 5) pt++;
    const float* pre    = (const float*)d_in[pt];
    const float* w1     = (const float*)d_in[pt + 1];
    const float* b1     = (const float*)d_in[pt + 2];
    const float* ln1_g  = (const float*)d_in[pt + 3];
    const float* ln1_b  = (const float*)d_in[pt + 4];
    const float* norm_g = (const float*)d_in[pt + 5];
    const float* norm_b = (const float*)d_in[pt + 6];
    const float* lin_w  = (const float*)d_in[pt + 7];
    const float* lin_b  = (const float*)d_in[pt + 8];

    float* out_pos = (float*)d_out;
    float* out_res = (float*)d_out + (size_t)BB * KEEP * 2;

    cudaFuncSetAttribute(prep_kernel, cudaFuncAttributeMaxDynamicSharedMemorySize, PREP_SMEM);
    cudaFuncSetAttribute(gemm_mma_kernel, cudaFuncAttributeMaxDynamicSharedMemorySize, GSMEM);

    prep_kernel<<<PREP_GRID, 1024, PREP_SMEM>>>(pos, lp, pre, w1, b1, ln1_g, ln1_b, lin_w, feat);
    token_kernel<<<MTOT / 8, 256>>>(pos, member, cmask, lp, pe, norm_g, norm_b, out_pos);
    dim3 ggrid(OUTD / BN, MTOT / BM);
    gemm_mma_kernel<<<ggrid, 256, GSMEM>>>(lin_b, out_res);
}